// round 1
// baseline (speedup 1.0000x reference)
#include <cuda_runtime.h>

#define NTHREADS 256

__device__ __forceinline__ float lrelu(float v) { return fmaxf(v, 0.01f * v); }

// ---- shared memory layout (float offsets) ----
#define OFF_XS    0        // 128   : input image 121
#define OFF_W1    128      // 576   : conv1 weights
#define OFF_WOT   704      // 2048  : wo transposed [i][c] (i<32, c<64)
#define OFF_A1    2752     // 5184  : conv1 out / nlb out [64][81]
#define OFF_TH    7936     // 2673  : theta [81][33] ; later a3 [32][49]
#define OFF_PH    10609    // 2592  : phi [32][81]  ; later flat [200]
#define OFF_G     13201    // 2673  : g [81][33]
#define OFF_ATTN  15874    // 648   : per-warp attn row [8][81]
#define OFF_YS    16522    // 256   : per-warp y scratch [8][32]
#define OFF_FC    16778    // 128   : fc activations
#define SMEM_FLOATS 16906
#define SMEM_BYTES  (SMEM_FLOATS * 4)

__global__ void __launch_bounds__(NTHREADS, 3) braggnn_kernel(
    const float* __restrict__ x,
    const float* __restrict__ w1, const float* __restrict__ b1,
    const float* __restrict__ wt, const float* __restrict__ bt,
    const float* __restrict__ wp, const float* __restrict__ bp,
    const float* __restrict__ wg, const float* __restrict__ bg,
    const float* __restrict__ wo, const float* __restrict__ bo,
    const float* __restrict__ w2, const float* __restrict__ b2,
    const float* __restrict__ w3, const float* __restrict__ b3,
    const float* __restrict__ fw1, const float* __restrict__ fb1,
    const float* __restrict__ fw2, const float* __restrict__ fb2,
    const float* __restrict__ fw3, const float* __restrict__ fb3,
    const float* __restrict__ fw4, const float* __restrict__ fb4,
    const float* __restrict__ fwo, const float* __restrict__ fbo,
    float* __restrict__ out)
{
    extern __shared__ float sm[];
    const int b    = blockIdx.x;
    const int tid  = threadIdx.x;
    const int w    = tid >> 5;
    const int lane = tid & 31;

    // ---- preload image + small weights into smem ----
    for (int i = tid; i < 121;  i += NTHREADS) sm[OFF_XS + i] = x[b * 121 + i];
    for (int i = tid; i < 576;  i += NTHREADS) sm[OFF_W1 + i] = w1[i];
    for (int i = tid; i < 2048; i += NTHREADS) {
        int ii = i >> 6, cc = i & 63;           // woT[i][c] = wo[c][i]
        sm[OFF_WOT + i] = wo[cc * 32 + ii];
    }
    __syncthreads();

    // ---- phase 1: conv1  [1,11,11] -> [64,9,9] ----
    for (int idx = tid; idx < 64 * 81; idx += NTHREADS) {
        int c = idx / 81, s = idx - c * 81;
        int oy = s / 9, ox = s - oy * 9;
        const float* wp1 = &sm[OFF_W1 + c * 9];
        const float* xp  = &sm[OFF_XS + oy * 11 + ox];
        float acc = b1[c];
        #pragma unroll
        for (int ky = 0; ky < 3; ky++)
            #pragma unroll
            for (int kx = 0; kx < 3; kx++)
                acc += wp1[ky * 3 + kx] * xp[ky * 11 + kx];
        sm[OFF_A1 + idx] = acc;                 // a1[c][s]
    }
    __syncthreads();

    // ---- phase 2: theta/phi/g  (1x1 convs over channels) ----
    // warp w handles output channels o = 4w..4w+3; lanes cover s = lane, lane+32, lane+64
    {
        const int s0 = lane, s1 = lane + 32;
        const int s2v = lane < 17;
        const int s2 = s2v ? lane + 64 : 80;
        for (int oi = 0; oi < 4; oi++) {
            int o = w * 4 + oi;
            float btv = bt[o], bpv = bp[o], bgv = bg[o];
            float at0 = btv, at1 = btv, at2 = btv;
            float ap0 = bpv, ap1 = bpv, ap2 = bpv;
            float ag0 = bgv, ag1 = bgv, ag2 = bgv;
            const float* wtr = &wt[o * 64];
            const float* wpr = &wp[o * 64];
            const float* wgr = &wg[o * 64];
            for (int c = 0; c < 64; c++) {
                float wtv = wtr[c], wpv = wpr[c], wgv = wgr[c];   // uniform LDG (L1-hot)
                const float* ar = &sm[OFF_A1 + c * 81];
                float x0 = ar[s0], x1 = ar[s1], x2 = ar[s2];
                at0 += wtv * x0; at1 += wtv * x1; at2 += wtv * x2;
                ap0 += wpv * x0; ap1 += wpv * x1; ap2 += wpv * x2;
                ag0 += wgv * x0; ag1 += wgv * x1; ag2 += wgv * x2;
            }
            sm[OFF_TH + s0 * 33 + o] = at0;
            sm[OFF_TH + s1 * 33 + o] = at1;
            sm[OFF_PH + o * 81 + s0] = ap0;
            sm[OFF_PH + o * 81 + s1] = ap1;
            sm[OFF_G  + s0 * 33 + o] = ag0;
            sm[OFF_G  + s1 * 33 + o] = ag1;
            if (s2v) {
                sm[OFF_TH + s2 * 33 + o] = at2;
                sm[OFF_PH + o * 81 + s2] = ap2;
                sm[OFF_G  + s2 * 33 + o] = ag2;
            }
        }
    }
    __syncthreads();

    // ---- phase 3: attention rows (row s per warp), fused y + wo + residual + lrelu ----
    for (int s = w; s < 81; s += 8) {
        const float* ths = &sm[OFF_TH + s * 33];
        const int t0 = lane, t1 = lane + 32, t2 = lane + 64;
        const int t2ok = t2 < 81;
        float l0 = 0.f, l1 = 0.f, l2 = 0.f;
        for (int i = 0; i < 32; i++) {
            float tv = ths[i];                         // smem broadcast
            const float* pr = &sm[OFF_PH + i * 81];
            l0 += tv * pr[t0];
            l1 += tv * pr[t1];
            l2 += tv * pr[t2ok ? t2 : 0];
        }
        if (!t2ok) l2 = -1e30f;
        float m = fmaxf(fmaxf(l0, l1), l2);
        #pragma unroll
        for (int d = 16; d > 0; d >>= 1) m = fmaxf(m, __shfl_xor_sync(0xffffffffu, m, d));
        float e0 = __expf(l0 - m), e1 = __expf(l1 - m);
        float e2 = t2ok ? __expf(l2 - m) : 0.f;
        float ssum = e0 + e1 + e2;
        #pragma unroll
        for (int d = 16; d > 0; d >>= 1) ssum += __shfl_xor_sync(0xffffffffu, ssum, d);
        float inv = 1.0f / ssum;

        float* arow = &sm[OFF_ATTN + w * 81];
        arow[t0] = e0 * inv;
        arow[t1] = e1 * inv;
        if (t2ok) arow[t2] = e2 * inv;
        __syncwarp();

        // y[s][i], i = lane
        float acc = 0.f;
        for (int t = 0; t < 81; t++)
            acc += arow[t] * sm[OFF_G + t * 33 + lane];
        sm[OFF_YS + w * 32 + lane] = acc;
        __syncwarp();

        // out[c][s] = wo @ y + bo + a1, then lrelu; c = lane, lane+32
        const float* ysw = &sm[OFF_YS + w * 32];
        #pragma unroll
        for (int h = 0; h < 2; h++) {
            int cc = lane + h * 32;
            float acc2 = bo[cc] + sm[OFF_A1 + cc * 81 + s];
            for (int i = 0; i < 32; i++)
                acc2 += sm[OFF_WOT + i * 64 + cc] * ysw[i];
            sm[OFF_A1 + cc * 81 + s] = lrelu(acc2);
        }
        __syncwarp();
    }
    __syncthreads();

    // ---- phase 4: conv2  [64,9,9] -> [32,7,7] ----
    // warp w: channels o = 4w..4w+3; lanes: p = lane, lane+32
    {
        const int p0 = lane;
        const int p1 = lane + 32;
        const int v1 = p1 < 49;
        const int i90 = (p0 / 7) * 9 + (p0 % 7);
        const int i91 = v1 ? (p1 / 7) * 9 + (p1 % 7) : 0;
        for (int oi = 0; oi < 4; oi++) {
            int o = w * 4 + oi;
            float acc0 = b2[o], acc1 = acc0;
            const float* wr = &w2[o * 576];
            for (int c = 0; c < 64; c++) {
                const float* ar = &sm[OFF_A1 + c * 81];
                const float* wc = &wr[c * 9];
                #pragma unroll
                for (int k = 0; k < 9; k++) {
                    float wv = wc[k];                   // uniform LDG
                    int off = (k / 3) * 9 + (k % 3);
                    acc0 += wv * ar[i90 + off];
                    acc1 += wv * ar[i91 + off];
                }
            }
            sm[OFF_TH + o * 49 + p0] = lrelu(acc0);     // a3[o][p]
            if (v1) sm[OFF_TH + o * 49 + p1] = lrelu(acc1);
        }
    }
    __syncthreads();

    // ---- phase 5: conv3  [32,7,7] -> [8,5,5] ; warp w = output channel ----
    if (lane < 25) {
        int o = w;
        int i7 = (lane / 5) * 7 + (lane % 5);
        float acc = b3[o];
        const float* wr = &w3[o * 288];
        for (int c = 0; c < 32; c++) {
            const float* ar = &sm[OFF_TH + c * 49];
            const float* wc = &wr[c * 9];
            #pragma unroll
            for (int k = 0; k < 9; k++)
                acc += wc[k] * ar[i7 + (k / 3) * 7 + (k % 3)];
        }
        sm[OFF_PH + o * 25 + lane] = lrelu(acc);        // flat[o*25+p]
    }
    __syncthreads();

    // ---- phase 6: MLP 200->64->32->16->8->2 ----
    float* flat = &sm[OFF_PH];
    float* f1 = &sm[OFF_FC];
    float* f2 = &sm[OFF_FC + 64];
    float* f3 = &sm[OFF_FC + 96];
    float* f4 = &sm[OFF_FC + 112];

    {   // fc1: 200 -> 64, 4 threads per output
        int j = tid >> 2, q = tid & 3;
        float acc = 0.f;
        const float* wr = &fw1[j * 200 + q * 50];
        const float* fr = &flat[q * 50];
        for (int k = 0; k < 50; k++) acc += wr[k] * fr[k];
        acc += __shfl_xor_sync(0xffffffffu, acc, 1);
        acc += __shfl_xor_sync(0xffffffffu, acc, 2);
        if (q == 0) f1[j] = lrelu(acc + fb1[j]);
    }
    __syncthreads();
    if (tid < 128) {  // fc2: 64 -> 32
        int j = tid >> 2, q = tid & 3;
        float acc = 0.f;
        const float* wr = &fw2[j * 64 + q * 16];
        for (int k = 0; k < 16; k++) acc += wr[k] * f1[q * 16 + k];
        acc += __shfl_xor_sync(0xffffffffu, acc, 1);
        acc += __shfl_xor_sync(0xffffffffu, acc, 2);
        if (q == 0) f2[j] = lrelu(acc + fb2[j]);
    }
    __syncthreads();
    if (tid < 64) {   // fc3: 32 -> 16
        int j = tid >> 2, q = tid & 3;
        float acc = 0.f;
        const float* wr = &fw3[j * 32 + q * 8];
        for (int k = 0; k < 8; k++) acc += wr[k] * f2[q * 8 + k];
        acc += __shfl_xor_sync(0xffffffffu, acc, 1);
        acc += __shfl_xor_sync(0xffffffffu, acc, 2);
        if (q == 0) f3[j] = lrelu(acc + fb3[j]);
    }
    __syncthreads();
    if (tid < 32) {   // fc4: 16 -> 8
        int j = tid >> 2, q = tid & 3;
        float acc = 0.f;
        const float* wr = &fw4[j * 16 + q * 4];
        for (int k = 0; k < 4; k++) acc += wr[k] * f3[q * 4 + k];
        acc += __shfl_xor_sync(0xffffffffu, acc, 1);
        acc += __shfl_xor_sync(0xffffffffu, acc, 2);
        if (q == 0) f4[j] = lrelu(acc + fb4[j]);
    }
    __syncthreads();
    if (tid < 2) {    // fco: 8 -> 2 (no lrelu)
        float acc = fbo[tid];
        const float* wr = &fwo[tid * 8];
        #pragma unroll
        for (int k = 0; k < 8; k++) acc += wr[k] * f4[k];
        out[b * 2 + tid] = acc;
    }
}

extern "C" void kernel_launch(void* const* d_in, const int* in_sizes, int n_in,
                              void* d_out, int out_size) {
    const float* x   = (const float*)d_in[0];
    const float* w1  = (const float*)d_in[1];
    const float* b1  = (const float*)d_in[2];
    const float* wt  = (const float*)d_in[3];
    const float* bt  = (const float*)d_in[4];
    const float* wp  = (const float*)d_in[5];
    const float* bp  = (const float*)d_in[6];
    const float* wg  = (const float*)d_in[7];
    const float* bg  = (const float*)d_in[8];
    const float* wo  = (const float*)d_in[9];
    const float* bo  = (const float*)d_in[10];
    const float* w2  = (const float*)d_in[11];
    const float* b2  = (const float*)d_in[12];
    const float* w3  = (const float*)d_in[13];
    const float* b3  = (const float*)d_in[14];
    const float* fw1 = (const float*)d_in[15];
    const float* fb1 = (const float*)d_in[16];
    const float* fw2 = (const float*)d_in[17];
    const float* fb2 = (const float*)d_in[18];
    const float* fw3 = (const float*)d_in[19];
    const float* fb3 = (const float*)d_in[20];
    const float* fw4 = (const float*)d_in[21];
    const float* fb4 = (const float*)d_in[22];
    const float* fwo = (const float*)d_in[23];
    const float* fbo = (const float*)d_in[24];
    float* out = (float*)d_out;

    int B = in_sizes[0] / 121;

    cudaFuncSetAttribute(braggnn_kernel,
                         cudaFuncAttributeMaxDynamicSharedMemorySize, SMEM_BYTES);
    braggnn_kernel<<<B, NTHREADS, SMEM_BYTES>>>(
        x, w1, b1, wt, bt, wp, bp, wg, bg, wo, bo, w2, b2, w3, b3,
        fw1, fb1, fw2, fb2, fw3, fb3, fw4, fb4, fwo, fbo, out);
}

// round 2
// speedup vs baseline: 1.9543x; 1.9543x over previous
#include <cuda_runtime.h>

#define NTHREADS 256

__device__ __forceinline__ float lrelu(float v) { return fmaxf(v, 0.01f * v); }

// ---- shared memory layout (float offsets) ----
#define OFF_XS    0        // 128   : input image 121
#define OFF_W1    128      // 576   : conv1 weights
#define OFF_WOT   704      // 2080  : wo transposed [i][c], stride 65
#define OFF_A1    2784     // 5184  : conv1 out / nlb out [64][81]
#define OFF_TH    7968     // 2673  : theta [81][33] ; later a3 [32][49]
#define OFF_PH    10641    // 2592  : phi [32][81]  ; later flat [200]
#define OFF_G     13233    // 2673  : g [81][33]
#define OFF_ATTN  15906    // 1944  : per-warp attn rows [8][3][81] ; later fc partial scratch
#define OFF_YS    17850    // 768   : per-warp y scratch [8][3][32]
#define OFF_FC    18618    // 128   : fc activations
#define SMEM_FLOATS 18746
#define SMEM_BYTES  (SMEM_FLOATS * 4)

// ---- prepacked weights in device scratch (filled by prep kernel each launch) ----
__device__ __align__(16) float g_w2p[32 * 64 * 12];   // [o][c][12] (9 taps + pad)
__device__ __align__(16) float g_w3p[8 * 32 * 12];    // [o][c][12]
__device__ __align__(16) float g_fw1T[200 * 64];      // [k][j]
__device__ __align__(16) float g_fw2T[64 * 32];       // [k][j]

#define N_W2P (32 * 64 * 12)
#define N_W3P (8 * 32 * 12)
#define N_F1T (200 * 64)
#define N_F2T (64 * 32)
#define PREP_TOTAL (N_W2P + N_W3P + N_F1T + N_F2T)

__global__ void prep_kernel(const float* __restrict__ w2, const float* __restrict__ w3,
                            const float* __restrict__ fw1, const float* __restrict__ fw2) {
    int i = blockIdx.x * blockDim.x + threadIdx.x;
    if (i < N_W2P) {
        int k = i % 12, oc = i / 12;
        g_w2p[i] = (k < 9) ? w2[oc * 9 + k] : 0.f;
        return;
    }
    i -= N_W2P;
    if (i < N_W3P) {
        int k = i % 12, oc = i / 12;
        g_w3p[i] = (k < 9) ? w3[oc * 9 + k] : 0.f;
        return;
    }
    i -= N_W3P;
    if (i < N_F1T) {
        int kk = i / 64, jj = i % 64;
        g_fw1T[i] = fw1[jj * 200 + kk];
        return;
    }
    i -= N_F1T;
    if (i < N_F2T) {
        int kk = i / 32, jj = i % 32;
        g_fw2T[i] = fw2[jj * 64 + kk];
    }
}

__global__ void __launch_bounds__(NTHREADS, 3) braggnn_kernel(
    const float* __restrict__ x,
    const float* __restrict__ w1, const float* __restrict__ b1,
    const float* __restrict__ wt, const float* __restrict__ bt,
    const float* __restrict__ wp, const float* __restrict__ bp,
    const float* __restrict__ wg, const float* __restrict__ bg,
    const float* __restrict__ wo, const float* __restrict__ bo,
    const float* __restrict__ b2, const float* __restrict__ b3,
    const float* __restrict__ fb1, const float* __restrict__ fb2,
    const float* __restrict__ fw3, const float* __restrict__ fb3,
    const float* __restrict__ fw4, const float* __restrict__ fb4,
    const float* __restrict__ fwo, const float* __restrict__ fbo,
    float* __restrict__ out)
{
    extern __shared__ float sm[];
    const int b    = blockIdx.x;
    const int tid  = threadIdx.x;
    const int w    = tid >> 5;
    const int lane = tid & 31;

    // ---- preload image + small weights into smem ----
    for (int i = tid; i < 121;  i += NTHREADS) sm[OFF_XS + i] = x[b * 121 + i];
    for (int i = tid; i < 576;  i += NTHREADS) sm[OFF_W1 + i] = w1[i];
    for (int i = tid; i < 2048; i += NTHREADS) {
        int ii = i & 31, cc = i >> 5;                 // coalesced read, conflict-free store
        sm[OFF_WOT + ii * 65 + cc] = wo[cc * 32 + ii];
    }
    __syncthreads();

    // ---- phase 1: conv1  [1,11,11] -> [64,9,9] ----
    for (int idx = tid; idx < 64 * 81; idx += NTHREADS) {
        int c = idx / 81, s = idx - c * 81;
        int oy = s / 9, ox = s - oy * 9;
        const float* wr1 = &sm[OFF_W1 + c * 9];
        const float* xp  = &sm[OFF_XS + oy * 11 + ox];
        float acc = b1[c];
        #pragma unroll
        for (int ky = 0; ky < 3; ky++)
            #pragma unroll
            for (int kx = 0; kx < 3; kx++)
                acc += wr1[ky * 3 + kx] * xp[ky * 11 + kx];
        sm[OFF_A1 + idx] = acc;                 // a1[c][s]
    }
    __syncthreads();

    // ---- phase 2: theta/phi/g (1x1 convs), c-chunked with float4 uniform weights ----
    {
        const int s0 = lane, s1 = lane + 32;
        const bool s2ok = lane < 17;
        const int s2 = s2ok ? lane + 64 : 80;
        const int o0 = w * 4;

        // pass A: theta + phi
        {
            float at[4][3], ap[4][3];
            #pragma unroll
            for (int oi = 0; oi < 4; oi++) {
                float bv = bt[o0 + oi]; at[oi][0] = bv; at[oi][1] = bv; at[oi][2] = bv;
                float pv = bp[o0 + oi]; ap[oi][0] = pv; ap[oi][1] = pv; ap[oi][2] = pv;
            }
            for (int c4 = 0; c4 < 64; c4 += 4) {
                float xv[4][3];
                #pragma unroll
                for (int cc = 0; cc < 4; cc++) {
                    const float* ar = &sm[OFF_A1 + (c4 + cc) * 81];
                    xv[cc][0] = ar[s0]; xv[cc][1] = ar[s1]; xv[cc][2] = ar[s2];
                }
                #pragma unroll
                for (int oi = 0; oi < 4; oi++) {
                    float4 wtq = *(const float4*)&wt[(o0 + oi) * 64 + c4];
                    float4 wpq = *(const float4*)&wp[(o0 + oi) * 64 + c4];
                    #pragma unroll
                    for (int p = 0; p < 3; p++) {
                        at[oi][p] += wtq.x * xv[0][p] + wtq.y * xv[1][p]
                                   + wtq.z * xv[2][p] + wtq.w * xv[3][p];
                        ap[oi][p] += wpq.x * xv[0][p] + wpq.y * xv[1][p]
                                   + wpq.z * xv[2][p] + wpq.w * xv[3][p];
                    }
                }
            }
            #pragma unroll
            for (int oi = 0; oi < 4; oi++) {
                int o = o0 + oi;
                sm[OFF_TH + s0 * 33 + o] = at[oi][0];
                sm[OFF_TH + s1 * 33 + o] = at[oi][1];
                sm[OFF_PH + o * 81 + s0] = ap[oi][0];
                sm[OFF_PH + o * 81 + s1] = ap[oi][1];
                if (s2ok) {
                    sm[OFF_TH + s2 * 33 + o] = at[oi][2];
                    sm[OFF_PH + o * 81 + s2] = ap[oi][2];
                }
            }
        }
        // pass B: g
        {
            float ag[4][3];
            #pragma unroll
            for (int oi = 0; oi < 4; oi++) {
                float gv = bg[o0 + oi]; ag[oi][0] = gv; ag[oi][1] = gv; ag[oi][2] = gv;
            }
            for (int c4 = 0; c4 < 64; c4 += 4) {
                float xv[4][3];
                #pragma unroll
                for (int cc = 0; cc < 4; cc++) {
                    const float* ar = &sm[OFF_A1 + (c4 + cc) * 81];
                    xv[cc][0] = ar[s0]; xv[cc][1] = ar[s1]; xv[cc][2] = ar[s2];
                }
                #pragma unroll
                for (int oi = 0; oi < 4; oi++) {
                    float4 wgq = *(const float4*)&wg[(o0 + oi) * 64 + c4];
                    #pragma unroll
                    for (int p = 0; p < 3; p++)
                        ag[oi][p] += wgq.x * xv[0][p] + wgq.y * xv[1][p]
                                   + wgq.z * xv[2][p] + wgq.w * xv[3][p];
                }
            }
            #pragma unroll
            for (int oi = 0; oi < 4; oi++) {
                int o = o0 + oi;
                sm[OFF_G + s0 * 33 + o] = ag[oi][0];
                sm[OFF_G + s1 * 33 + o] = ag[oi][1];
                if (s2ok) sm[OFF_G + s2 * 33 + o] = ag[oi][2];
            }
        }
    }
    __syncthreads();

    // ---- phase 3: attention, 3 rows per warp per group ----
    {
        const float bo0 = bo[lane], bo1 = bo[lane + 32];
        float* ATT = &sm[OFF_ATTN + w * 243];
        float* YSW = &sm[OFF_YS + w * 96];
        const int t0 = lane, t1 = lane + 32;
        const bool t2ok = lane < 17;
        const int t2 = t2ok ? lane + 64 : 80;

        for (int base = 0; base < 81; base += 24) {
            const int r0 = base + w * 3;
            if (r0 > 80) continue;                       // uniform per warp
            const int ra = r0;
            const int rb = (r0 + 1 < 81) ? r0 + 1 : 80;
            const int rc = (r0 + 2 < 81) ? r0 + 2 : 80;
            const bool vb = r0 + 1 < 81, vc = r0 + 2 < 81;

            float l[3][3] = {{0,0,0},{0,0,0},{0,0,0}};
            for (int i = 0; i < 32; i++) {
                float p0v = sm[OFF_PH + i * 81 + t0];
                float p1v = sm[OFF_PH + i * 81 + t1];
                float p2v = sm[OFF_PH + i * 81 + t2];
                float tha = sm[OFF_TH + ra * 33 + i];
                float thb = sm[OFF_TH + rb * 33 + i];
                float thc = sm[OFF_TH + rc * 33 + i];
                l[0][0] += tha * p0v; l[0][1] += tha * p1v; l[0][2] += tha * p2v;
                l[1][0] += thb * p0v; l[1][1] += thb * p1v; l[1][2] += thb * p2v;
                l[2][0] += thc * p0v; l[2][1] += thc * p1v; l[2][2] += thc * p2v;
            }
            #pragma unroll
            for (int j = 0; j < 3; j++) {
                float l2v = t2ok ? l[j][2] : -1e30f;
                float m = fmaxf(fmaxf(l[j][0], l[j][1]), l2v);
                #pragma unroll
                for (int d = 16; d > 0; d >>= 1) m = fmaxf(m, __shfl_xor_sync(0xffffffffu, m, d));
                float e0 = __expf(l[j][0] - m), e1 = __expf(l[j][1] - m);
                float e2 = t2ok ? __expf(l[j][2] - m) : 0.f;
                float ssum = e0 + e1 + e2;
                #pragma unroll
                for (int d = 16; d > 0; d >>= 1) ssum += __shfl_xor_sync(0xffffffffu, ssum, d);
                float inv = 1.0f / ssum;
                ATT[j * 81 + t0] = e0 * inv;
                ATT[j * 81 + t1] = e1 * inv;
                if (t2ok) ATT[j * 81 + t2] = e2 * inv;
            }
            __syncwarp();

            // y[j][i], i = lane
            float y0 = 0.f, y1 = 0.f, y2 = 0.f;
            for (int t = 0; t < 81; t++) {
                float gv = sm[OFF_G + t * 33 + lane];
                y0 += ATT[t]       * gv;
                y1 += ATT[81 + t]  * gv;
                y2 += ATT[162 + t] * gv;
            }
            YSW[lane] = y0; YSW[32 + lane] = y1; YSW[64 + lane] = y2;
            __syncwarp();

            // out[c][r] = wo @ y + bo + a1, lrelu ; c = lane, lane+32
            float a0a = bo0 + sm[OFF_A1 + lane * 81 + ra];
            float a0b = bo0 + sm[OFF_A1 + lane * 81 + rb];
            float a0c = bo0 + sm[OFF_A1 + lane * 81 + rc];
            float a1a = bo1 + sm[OFF_A1 + (lane + 32) * 81 + ra];
            float a1b = bo1 + sm[OFF_A1 + (lane + 32) * 81 + rb];
            float a1c = bo1 + sm[OFF_A1 + (lane + 32) * 81 + rc];
            for (int i = 0; i < 32; i++) {
                float w0v = sm[OFF_WOT + i * 65 + lane];
                float w1v = sm[OFF_WOT + i * 65 + lane + 32];
                float ya = YSW[i], yb = YSW[32 + i], yc = YSW[64 + i];
                a0a += w0v * ya; a0b += w0v * yb; a0c += w0v * yc;
                a1a += w1v * ya; a1b += w1v * yb; a1c += w1v * yc;
            }
            sm[OFF_A1 + lane * 81 + ra]        = lrelu(a0a);
            sm[OFF_A1 + (lane + 32) * 81 + ra] = lrelu(a1a);
            if (vb) { sm[OFF_A1 + lane * 81 + rb] = lrelu(a0b);
                      sm[OFF_A1 + (lane + 32) * 81 + rb] = lrelu(a1b); }
            if (vc) { sm[OFF_A1 + lane * 81 + rc] = lrelu(a0c);
                      sm[OFF_A1 + (lane + 32) * 81 + rc] = lrelu(a1c); }
            __syncwarp();
        }
    }
    __syncthreads();

    // ---- phase 4: conv2  [64,9,9] -> [32,7,7], c-outer, register windows ----
    {
        const int p0 = lane;
        const int p1raw = lane + 32;
        const bool v1 = p1raw < 49;
        const int p1 = v1 ? p1raw : 48;
        const int i90 = (p0 / 7) * 9 + (p0 % 7);
        const int i91 = (p1 / 7) * 9 + (p1 % 7);
        const int o0 = w * 4;
        float acc0[4], acc1[4];
        #pragma unroll
        for (int oi = 0; oi < 4; oi++) { float bv = b2[o0 + oi]; acc0[oi] = bv; acc1[oi] = bv; }

        for (int c = 0; c < 64; c++) {
            const float* ar = &sm[OFF_A1 + c * 81];
            float a0[9], a1v[9];
            #pragma unroll
            for (int ky = 0; ky < 3; ky++)
                #pragma unroll
                for (int kx = 0; kx < 3; kx++) {
                    a0[ky * 3 + kx]  = ar[i90 + ky * 9 + kx];
                    a1v[ky * 3 + kx] = ar[i91 + ky * 9 + kx];
                }
            #pragma unroll
            for (int oi = 0; oi < 4; oi++) {
                const float* wr = &g_w2p[(((o0 + oi) << 6) + c) * 12];
                float4 wa = *(const float4*)wr;
                float4 wb = *(const float4*)(wr + 4);
                float w8 = wr[8];
                acc0[oi] += wa.x * a0[0] + wa.y * a0[1] + wa.z * a0[2] + wa.w * a0[3]
                          + wb.x * a0[4] + wb.y * a0[5] + wb.z * a0[6] + wb.w * a0[7]
                          + w8 * a0[8];
                acc1[oi] += wa.x * a1v[0] + wa.y * a1v[1] + wa.z * a1v[2] + wa.w * a1v[3]
                          + wb.x * a1v[4] + wb.y * a1v[5] + wb.z * a1v[6] + wb.w * a1v[7]
                          + w8 * a1v[8];
            }
        }
        #pragma unroll
        for (int oi = 0; oi < 4; oi++) {
            sm[OFF_TH + (o0 + oi) * 49 + p0] = lrelu(acc0[oi]);
            if (v1) sm[OFF_TH + (o0 + oi) * 49 + p1] = lrelu(acc1[oi]);
        }
    }
    __syncthreads();

    // ---- phase 5: conv3  [32,7,7] -> [8,5,5] ; warp w = output channel ----
    if (lane < 25) {
        int o = w;
        int i7 = (lane / 5) * 7 + (lane % 5);
        float acc = b3[o];
        for (int c = 0; c < 32; c++) {
            const float* ar = &sm[OFF_TH + c * 49 + i7];
            const float* wr = &g_w3p[((o << 5) + c) * 12];
            float4 wa = *(const float4*)wr;
            float4 wb = *(const float4*)(wr + 4);
            float w8 = wr[8];
            acc += wa.x * ar[0]  + wa.y * ar[1]  + wa.z * ar[2]
                 + wa.w * ar[7]  + wb.x * ar[8]  + wb.y * ar[9]
                 + wb.z * ar[14] + wb.w * ar[15] + w8 * ar[16];
        }
        sm[OFF_PH + o * 25 + lane] = lrelu(acc);        // flat[o*25+p]
    }
    __syncthreads();

    // ---- phase 6: MLP 200->64->32->16->8->2 ----
    float* flat = &sm[OFF_PH];
    float* scr  = &sm[OFF_ATTN];          // partial-sum scratch (phase 3 done)
    float* f1 = &sm[OFF_FC];
    float* f2 = &sm[OFF_FC + 64];
    float* f3 = &sm[OFF_FC + 96];
    float* f4 = &sm[OFF_FC + 112];

    {   // fc1: 200 -> 64 ; thread = (q, j), coalesced transposed weights
        int q = tid >> 6, j = tid & 63;
        float acc = 0.f;
        int k0 = q * 50;
        for (int k = 0; k < 50; k++)
            acc += g_fw1T[(k0 + k) * 64 + j] * flat[k0 + k];
        scr[q * 64 + j] = acc;
    }
    __syncthreads();
    if (tid < 64)
        f1[tid] = lrelu(scr[tid] + scr[64 + tid] + scr[128 + tid] + scr[192 + tid] + fb1[tid]);
    __syncthreads();
    if (tid < 128) {  // fc2: 64 -> 32
        int q = tid >> 5, j = tid & 31;
        float acc = 0.f;
        int k0 = q * 16;
        for (int k = 0; k < 16; k++)
            acc += g_fw2T[(k0 + k) * 32 + j] * f1[k0 + k];
        scr[256 + q * 32 + j] = acc;
    }
    __syncthreads();
    if (tid < 32)
        f2[tid] = lrelu(scr[256 + tid] + scr[288 + tid] + scr[320 + tid] + scr[352 + tid] + fb2[tid]);
    __syncthreads();
    if (tid < 64) {   // fc3: 32 -> 16
        int j = tid >> 2, q = tid & 3;
        float acc = 0.f;
        const float* wr = &fw3[j * 32 + q * 8];
        for (int k = 0; k < 8; k++) acc += wr[k] * f2[q * 8 + k];
        acc += __shfl_xor_sync(0xffffffffu, acc, 1);
        acc += __shfl_xor_sync(0xffffffffu, acc, 2);
        if (q == 0) f3[j] = lrelu(acc + fb3[j]);
    }
    __syncthreads();
    if (tid < 32) {   // fc4: 16 -> 8
        int j = tid >> 2, q = tid & 3;
        float acc = 0.f;
        const float* wr = &fw4[j * 16 + q * 4];
        for (int k = 0; k < 4; k++) acc += wr[k] * f3[q * 4 + k];
        acc += __shfl_xor_sync(0xffffffffu, acc, 1);
        acc += __shfl_xor_sync(0xffffffffu, acc, 2);
        if (q == 0) f4[j] = lrelu(acc + fb4[j]);
    }
    __syncthreads();
    if (tid < 2) {    // fco: 8 -> 2 (no lrelu)
        float acc = fbo[tid];
        const float* wr = &fwo[tid * 8];
        #pragma unroll
        for (int k = 0; k < 8; k++) acc += wr[k] * f4[k];
        out[b * 2 + tid] = acc;
    }
}

extern "C" void kernel_launch(void* const* d_in, const int* in_sizes, int n_in,
                              void* d_out, int out_size) {
    const float* x   = (const float*)d_in[0];
    const float* w1  = (const float*)d_in[1];
    const float* b1  = (const float*)d_in[2];
    const float* wt  = (const float*)d_in[3];
    const float* bt  = (const float*)d_in[4];
    const float* wp  = (const float*)d_in[5];
    const float* bp  = (const float*)d_in[6];
    const float* wg  = (const float*)d_in[7];
    const float* bg  = (const float*)d_in[8];
    const float* wo  = (const float*)d_in[9];
    const float* bo  = (const float*)d_in[10];
    const float* w2  = (const float*)d_in[11];
    const float* b2  = (const float*)d_in[12];
    const float* w3  = (const float*)d_in[13];
    const float* b3  = (const float*)d_in[14];
    const float* fw1 = (const float*)d_in[15];
    const float* fb1 = (const float*)d_in[16];
    const float* fw2 = (const float*)d_in[17];
    const float* fb2 = (const float*)d_in[18];
    const float* fw3 = (const float*)d_in[19];
    const float* fb3 = (const float*)d_in[20];
    const float* fw4 = (const float*)d_in[21];
    const float* fb4 = (const float*)d_in[22];
    const float* fwo = (const float*)d_in[23];
    const float* fbo = (const float*)d_in[24];
    float* out = (float*)d_out;

    int B = in_sizes[0] / 121;

    prep_kernel<<<(PREP_TOTAL + 255) / 256, 256>>>(w2, w3, fw1, fw2);

    cudaFuncSetAttribute(braggnn_kernel,
                         cudaFuncAttributeMaxDynamicSharedMemorySize, SMEM_BYTES);
    braggnn_kernel<<<B, NTHREADS, SMEM_BYTES>>>(
        x, w1, b1, wt, bt, wp, bp, wg, bg, wo, bo, b2, b3,
        fb1, fb2, fw3, fb3, fw4, fb4, fwo, fbo, out);
}

// round 3
// speedup vs baseline: 2.1303x; 1.0900x over previous
#include <cuda_runtime.h>

#define NTHREADS 256

__device__ __forceinline__ float lrelu(float v) { return fmaxf(v, 0.01f * v); }

// ---- shared memory layout (float offsets) ----
#define OFF_XS    0        // 128   : input image 121
#define OFF_W1    128      // 576   : conv1 weights
#define OFF_WOT   704      // 2176  : wo transposed [i][c], stride 68 (float4-aligned)
#define OFF_A1    2880     // 5188  : conv1 out / nlb out [64][81] (+pad)
#define OFF_TH    8068     // 2997  : theta [81][36] -> y [81][37] -> a3 [32][49]
#define OFF_PH    11068    // 2592  : phi [32][81] -> flat [200]
#define OFF_G     13660    // 2916  : g [81][36]
#define OFF_ATT   16576    // 6885  : attn [81][85] -> fc scratch
#define OFF_FC    23464    // 128   : fc activations
#define SMEM_FLOATS 23592
#define SMEM_BYTES  (SMEM_FLOATS * 4)

// ---- prepacked weights in device scratch ----
__device__ __align__(16) float g_w2p[32 * 64 * 12];   // [o][c][12] (9 taps + pad)
__device__ __align__(16) float g_w3p[8 * 32 * 12];    // [o][c][12]
__device__ __align__(16) float g_fw1T[200 * 64];      // [k][j]
__device__ __align__(16) float g_fw2T[64 * 32];       // [k][j]

#define N_W2P (32 * 64 * 12)
#define N_W3P (8 * 32 * 12)
#define N_F1T (200 * 64)
#define N_F2T (64 * 32)
#define PREP_TOTAL (N_W2P + N_W3P + N_F1T + N_F2T)

__global__ void prep_kernel(const float* __restrict__ w2, const float* __restrict__ w3,
                            const float* __restrict__ fw1, const float* __restrict__ fw2) {
    int i = blockIdx.x * blockDim.x + threadIdx.x;
    if (i < N_W2P) {
        int k = i % 12, oc = i / 12;
        g_w2p[i] = (k < 9) ? w2[oc * 9 + k] : 0.f;
        return;
    }
    i -= N_W2P;
    if (i < N_W3P) {
        int k = i % 12, oc = i / 12;
        g_w3p[i] = (k < 9) ? w3[oc * 9 + k] : 0.f;
        return;
    }
    i -= N_W3P;
    if (i < N_F1T) {
        int kk = i / 64, jj = i % 64;
        g_fw1T[i] = fw1[jj * 200 + kk];
        return;
    }
    i -= N_F1T;
    if (i < N_F2T) {
        int kk = i / 32, jj = i % 32;
        g_fw2T[i] = fw2[jj * 64 + kk];
    }
}

__global__ void __launch_bounds__(NTHREADS, 2) braggnn_kernel(
    const float* __restrict__ x,
    const float* __restrict__ w1, const float* __restrict__ b1,
    const float* __restrict__ wt, const float* __restrict__ bt,
    const float* __restrict__ wp, const float* __restrict__ bp,
    const float* __restrict__ wg, const float* __restrict__ bg,
    const float* __restrict__ wo, const float* __restrict__ bo,
    const float* __restrict__ b2, const float* __restrict__ b3,
    const float* __restrict__ fb1, const float* __restrict__ fb2,
    const float* __restrict__ fw3, const float* __restrict__ fb3,
    const float* __restrict__ fw4, const float* __restrict__ fb4,
    const float* __restrict__ fwo, const float* __restrict__ fbo,
    float* __restrict__ out)
{
    extern __shared__ float sm[];
    const int b    = blockIdx.x;
    const int tid  = threadIdx.x;
    const int w    = tid >> 5;
    const int lane = tid & 31;

    // ---- preload image + small weights ----
    for (int i = tid; i < 121;  i += NTHREADS) sm[OFF_XS + i] = x[b * 121 + i];
    for (int i = tid; i < 576;  i += NTHREADS) sm[OFF_W1 + i] = w1[i];
    for (int i = tid; i < 2048; i += NTHREADS) {
        int ii = i & 31, cc = i >> 5;
        sm[OFF_WOT + ii * 68 + cc] = wo[cc * 32 + ii];
    }
    __syncthreads();

    // ---- phase 1: conv1  [1,11,11] -> [64,9,9] ----
    for (int idx = tid; idx < 64 * 81; idx += NTHREADS) {
        int c = idx / 81, s = idx - c * 81;
        int oy = s / 9, ox = s - oy * 9;
        const float* wr1 = &sm[OFF_W1 + c * 9];
        const float* xp  = &sm[OFF_XS + oy * 11 + ox];
        float acc = b1[c];
        #pragma unroll
        for (int ky = 0; ky < 3; ky++)
            #pragma unroll
            for (int kx = 0; kx < 3; kx++)
                acc += wr1[ky * 3 + kx] * xp[ky * 11 + kx];
        sm[OFF_A1 + idx] = acc;
    }
    __syncthreads();

    // ---- phase 2: theta/phi/g in ONE pass ----
    {
        const int s0 = lane, s1 = lane + 32;
        const bool s2ok = lane < 17;
        const int s2 = s2ok ? lane + 64 : 80;
        const int o0 = w * 4;

        float at[4][3], ap[4][3], ag[4][3];
        #pragma unroll
        for (int oi = 0; oi < 4; oi++) {
            float bv = bt[o0 + oi]; at[oi][0] = bv; at[oi][1] = bv; at[oi][2] = bv;
            float pv = bp[o0 + oi]; ap[oi][0] = pv; ap[oi][1] = pv; ap[oi][2] = pv;
            float gv = bg[o0 + oi]; ag[oi][0] = gv; ag[oi][1] = gv; ag[oi][2] = gv;
        }
        for (int c4 = 0; c4 < 64; c4 += 4) {
            float xv[4][3];
            #pragma unroll
            for (int cc = 0; cc < 4; cc++) {
                const float* ar = &sm[OFF_A1 + (c4 + cc) * 81];
                xv[cc][0] = ar[s0]; xv[cc][1] = ar[s1]; xv[cc][2] = ar[s2];
            }
            #pragma unroll
            for (int oi = 0; oi < 4; oi++) {
                float4 wtq = *(const float4*)&wt[(o0 + oi) * 64 + c4];
                float4 wpq = *(const float4*)&wp[(o0 + oi) * 64 + c4];
                float4 wgq = *(const float4*)&wg[(o0 + oi) * 64 + c4];
                #pragma unroll
                for (int p = 0; p < 3; p++) {
                    at[oi][p] += wtq.x * xv[0][p] + wtq.y * xv[1][p]
                               + wtq.z * xv[2][p] + wtq.w * xv[3][p];
                    ap[oi][p] += wpq.x * xv[0][p] + wpq.y * xv[1][p]
                               + wpq.z * xv[2][p] + wpq.w * xv[3][p];
                    ag[oi][p] += wgq.x * xv[0][p] + wgq.y * xv[1][p]
                               + wgq.z * xv[2][p] + wgq.w * xv[3][p];
                }
            }
        }
        #pragma unroll
        for (int oi = 0; oi < 4; oi++) {
            int o = o0 + oi;
            sm[OFF_TH + s0 * 36 + o] = at[oi][0];
            sm[OFF_TH + s1 * 36 + o] = at[oi][1];
            sm[OFF_PH + o * 81 + s0] = ap[oi][0];
            sm[OFF_PH + o * 81 + s1] = ap[oi][1];
            sm[OFF_G  + s0 * 36 + o] = ag[oi][0];
            sm[OFF_G  + s1 * 36 + o] = ag[oi][1];
            if (s2ok) {
                sm[OFF_TH + s2 * 36 + o] = at[oi][2];
                sm[OFF_PH + o * 81 + s2] = ap[oi][2];
                sm[OFF_G  + s2 * 36 + o] = ag[oi][2];
            }
        }
    }
    __syncthreads();

    // ---- phase 3a: logits + softmax -> full attn [81][85] ----
    {
        const int t0 = lane, t1 = lane + 32;
        const bool t2ok = lane < 17;
        const int t2 = t2ok ? lane + 64 : 80;

        for (int base = 0; base < 81; base += 24) {
            const int r0 = base + w * 3;
            if (r0 > 80) continue;
            const int ra = r0;
            const int rb = (r0 + 1 < 81) ? r0 + 1 : 80;
            const int rc = (r0 + 2 < 81) ? r0 + 2 : 80;
            const bool vb = r0 + 1 < 81, vc = r0 + 2 < 81;

            float l[3][3] = {{0,0,0},{0,0,0},{0,0,0}};
            for (int i4 = 0; i4 < 32; i4 += 4) {
                float4 tha = *(const float4*)&sm[OFF_TH + ra * 36 + i4];
                float4 thb = *(const float4*)&sm[OFF_TH + rb * 36 + i4];
                float4 thc = *(const float4*)&sm[OFF_TH + rc * 36 + i4];
                const float ta[4] = {tha.x, tha.y, tha.z, tha.w};
                const float tb[4] = {thb.x, thb.y, thb.z, thb.w};
                const float tc[4] = {thc.x, thc.y, thc.z, thc.w};
                #pragma unroll
                for (int u = 0; u < 4; u++) {
                    int i = i4 + u;
                    float p0v = sm[OFF_PH + i * 81 + t0];
                    float p1v = sm[OFF_PH + i * 81 + t1];
                    float p2v = sm[OFF_PH + i * 81 + t2];
                    l[0][0] += ta[u] * p0v; l[0][1] += ta[u] * p1v; l[0][2] += ta[u] * p2v;
                    l[1][0] += tb[u] * p0v; l[1][1] += tb[u] * p1v; l[1][2] += tb[u] * p2v;
                    l[2][0] += tc[u] * p0v; l[2][1] += tc[u] * p1v; l[2][2] += tc[u] * p2v;
                }
            }
            const int rr[3] = {ra, rb, rc};
            const bool vv[3] = {true, vb, vc};
            #pragma unroll
            for (int j = 0; j < 3; j++) {
                float l2v = t2ok ? l[j][2] : -1e30f;
                float m = fmaxf(fmaxf(l[j][0], l[j][1]), l2v);
                #pragma unroll
                for (int d = 16; d > 0; d >>= 1) m = fmaxf(m, __shfl_xor_sync(0xffffffffu, m, d));
                float e0 = __expf(l[j][0] - m), e1 = __expf(l[j][1] - m);
                float e2 = t2ok ? __expf(l[j][2] - m) : 0.f;
                float ssum = e0 + e1 + e2;
                #pragma unroll
                for (int d = 16; d > 0; d >>= 1) ssum += __shfl_xor_sync(0xffffffffu, ssum, d);
                float inv = 1.0f / ssum;
                if (vv[j]) {
                    float* arow = &sm[OFF_ATT + rr[j] * 85];
                    arow[t0] = e0 * inv;
                    arow[t1] = e1 * inv;
                    if (t2ok) arow[t2] = e2 * inv;
                }
            }
        }
    }
    __syncthreads();

    // ---- phase 3b: y = attn @ g, full-CTA. warp: 4 i-cols, lanes: s-rows ----
    {
        const int i0 = w * 4;
        const int s0 = lane, s1 = lane + 32;
        const bool s2ok = lane < 17;
        const int s2 = s2ok ? lane + 64 : 80;
        float acc[3][4] = {{0,0,0,0},{0,0,0,0},{0,0,0,0}};
        for (int t = 0; t < 81; t++) {
            float4 gv = *(const float4*)&sm[OFF_G + t * 36 + i0];   // broadcast
            float a0 = sm[OFF_ATT + s0 * 85 + t];
            float a1v = sm[OFF_ATT + s1 * 85 + t];
            float a2 = sm[OFF_ATT + s2 * 85 + t];
            acc[0][0] += a0 * gv.x;  acc[0][1] += a0 * gv.y;
            acc[0][2] += a0 * gv.z;  acc[0][3] += a0 * gv.w;
            acc[1][0] += a1v * gv.x; acc[1][1] += a1v * gv.y;
            acc[1][2] += a1v * gv.z; acc[1][3] += a1v * gv.w;
            acc[2][0] += a2 * gv.x;  acc[2][1] += a2 * gv.y;
            acc[2][2] += a2 * gv.z;  acc[2][3] += a2 * gv.w;
        }
        #pragma unroll
        for (int j = 0; j < 4; j++) {
            sm[OFF_TH + s0 * 37 + i0 + j] = acc[0][j];   // y overwrites theta
            sm[OFF_TH + s1 * 37 + i0 + j] = acc[1][j];
            if (s2ok) sm[OFF_TH + s2 * 37 + i0 + j] = acc[2][j];
        }
    }
    __syncthreads();

    // ---- phase 3c: out = wo @ y + bo + a1, lrelu. warp: 8 c, lanes: s ----
    {
        const int c0 = w * 8;
        const int s0 = lane, s1 = lane + 32;
        const bool s2ok = lane < 17;
        const int s2 = s2ok ? lane + 64 : 80;
        float acc[3][8];
        #pragma unroll
        for (int j = 0; j < 8; j++) { acc[0][j] = 0.f; acc[1][j] = 0.f; acc[2][j] = 0.f; }
        for (int i = 0; i < 32; i++) {
            float4 wv0 = *(const float4*)&sm[OFF_WOT + i * 68 + c0];
            float4 wv1 = *(const float4*)&sm[OFF_WOT + i * 68 + c0 + 4];
            float y0 = sm[OFF_TH + s0 * 37 + i];
            float y1 = sm[OFF_TH + s1 * 37 + i];
            float y2 = sm[OFF_TH + s2 * 37 + i];
            const float wvv[8] = {wv0.x, wv0.y, wv0.z, wv0.w, wv1.x, wv1.y, wv1.z, wv1.w};
            #pragma unroll
            for (int j = 0; j < 8; j++) {
                acc[0][j] += wvv[j] * y0;
                acc[1][j] += wvv[j] * y1;
                acc[2][j] += wvv[j] * y2;
            }
        }
        #pragma unroll
        for (int j = 0; j < 8; j++) {
            int c = c0 + j;
            float bv = bo[c];
            float v0 = acc[0][j] + bv + sm[OFF_A1 + c * 81 + s0];
            float v1 = acc[1][j] + bv + sm[OFF_A1 + c * 81 + s1];
            sm[OFF_A1 + c * 81 + s0] = lrelu(v0);
            sm[OFF_A1 + c * 81 + s1] = lrelu(v1);
            if (s2ok) {
                float v2 = acc[2][j] + bv + sm[OFF_A1 + c * 81 + s2];
                sm[OFF_A1 + c * 81 + s2] = lrelu(v2);
            }
        }
    }
    __syncthreads();

    // ---- phase 4: conv2 [64,9,9] -> [32,7,7], adjacent-pair windows ----
    {
        const bool act = lane < 28;
        const int row = lane >> 2, cp = lane & 3;
        const int p0 = row * 7 + cp * 2;
        const bool hasp1 = (cp < 3);
        const int i9 = row * 9 + cp * 2;
        const int o0 = w * 4;
        float acc0[4], acc1[4];
        #pragma unroll
        for (int oi = 0; oi < 4; oi++) { float bv = b2[o0 + oi]; acc0[oi] = bv; acc1[oi] = bv; }

        if (act) {
            for (int c = 0; c < 64; c++) {
                const float* ar = &sm[OFF_A1 + c * 81 + i9];
                float win[3][4];
                #pragma unroll
                for (int r = 0; r < 3; r++) {
                    win[r][0] = ar[r * 9 + 0];
                    win[r][1] = ar[r * 9 + 1];
                    win[r][2] = ar[r * 9 + 2];
                    win[r][3] = ar[r * 9 + 3];
                }
                #pragma unroll
                for (int oi = 0; oi < 4; oi++) {
                    const float* wr = &g_w2p[(((o0 + oi) << 6) + c) * 12];
                    float4 wa = *(const float4*)wr;
                    float4 wb = *(const float4*)(wr + 4);
                    float w8 = wr[8];
                    acc0[oi] += wa.x * win[0][0] + wa.y * win[0][1] + wa.z * win[0][2]
                              + wa.w * win[1][0] + wb.x * win[1][1] + wb.y * win[1][2]
                              + wb.z * win[2][0] + wb.w * win[2][1] + w8 * win[2][2];
                    acc1[oi] += wa.x * win[0][1] + wa.y * win[0][2] + wa.z * win[0][3]
                              + wa.w * win[1][1] + wb.x * win[1][2] + wb.y * win[1][3]
                              + wb.z * win[2][1] + wb.w * win[2][2] + w8 * win[2][3];
                }
            }
        }
        __syncthreads();   // A1 reads done before TH overwrite (TH held y, now a3)
        if (act) {
            #pragma unroll
            for (int oi = 0; oi < 4; oi++) {
                sm[OFF_TH + (o0 + oi) * 49 + p0] = lrelu(acc0[oi]);
                if (hasp1) sm[OFF_TH + (o0 + oi) * 49 + p0 + 1] = lrelu(acc1[oi]);
            }
        }
    }
    __syncthreads();

    // ---- phase 5: conv3 [32,7,7] -> [8,5,5]; warp = output channel ----
    if (lane < 25) {
        int o = w;
        int i7 = (lane / 5) * 7 + (lane % 5);
        float acc = b3[o];
        for (int c = 0; c < 32; c++) {
            const float* ar = &sm[OFF_TH + c * 49 + i7];
            const float* wr = &g_w3p[((o << 5) + c) * 12];
            float4 wa = *(const float4*)wr;
            float4 wb = *(const float4*)(wr + 4);
            float w8 = wr[8];
            acc += wa.x * ar[0]  + wa.y * ar[1]  + wa.z * ar[2]
                 + wa.w * ar[7]  + wb.x * ar[8]  + wb.y * ar[9]
                 + wb.z * ar[14] + wb.w * ar[15] + w8 * ar[16];
        }
        sm[OFF_PH + o * 25 + lane] = lrelu(acc);        // flat
    }
    __syncthreads();

    // ---- phase 6: MLP 200->64->32->16->8->2 ----
    float* flat = &sm[OFF_PH];
    float* scr  = &sm[OFF_ATT];
    float* f1 = &sm[OFF_FC];
    float* f2 = &sm[OFF_FC + 64];
    float* f3 = &sm[OFF_FC + 96];
    float* f4 = &sm[OFF_FC + 112];

    {   // fc1: 200 -> 64
        int q = tid >> 6, j = tid & 63;
        float acc = 0.f;
        int k0 = q * 50;
        for (int k = 0; k < 50; k++)
            acc += g_fw1T[(k0 + k) * 64 + j] * flat[k0 + k];
        scr[q * 64 + j] = acc;
    }
    __syncthreads();
    if (tid < 64)
        f1[tid] = lrelu(scr[tid] + scr[64 + tid] + scr[128 + tid] + scr[192 + tid] + fb1[tid]);
    __syncthreads();
    if (tid < 128) {  // fc2: 64 -> 32
        int q = tid >> 5, j = tid & 31;
        float acc = 0.f;
        int k0 = q * 16;
        for (int k = 0; k < 16; k++)
            acc += g_fw2T[(k0 + k) * 32 + j] * f1[k0 + k];
        scr[256 + q * 32 + j] = acc;
    }
    __syncthreads();
    if (tid < 32)
        f2[tid] = lrelu(scr[256 + tid] + scr[288 + tid] + scr[320 + tid] + scr[352 + tid] + fb2[tid]);
    __syncthreads();
    if (tid < 64) {   // fc3: 32 -> 16
        int j = tid >> 2, q = tid & 3;
        float acc = 0.f;
        const float* wr = &fw3[j * 32 + q * 8];
        for (int k = 0; k < 8; k++) acc += wr[k] * f2[q * 8 + k];
        acc += __shfl_xor_sync(0xffffffffu, acc, 1);
        acc += __shfl_xor_sync(0xffffffffu, acc, 2);
        if (q == 0) f3[j] = lrelu(acc + fb3[j]);
    }
    __syncthreads();
    if (tid < 32) {   // fc4: 16 -> 8
        int j = tid >> 2, q = tid & 3;
        float acc = 0.f;
        const float* wr = &fw4[j * 16 + q * 4];
        for (int k = 0; k < 4; k++) acc += wr[k] * f3[q * 4 + k];
        acc += __shfl_xor_sync(0xffffffffu, acc, 1);
        acc += __shfl_xor_sync(0xffffffffu, acc, 2);
        if (q == 0) f4[j] = lrelu(acc + fb4[j]);
    }
    __syncthreads();
    if (tid < 2) {    // fco: 8 -> 2
        float acc = fbo[tid];
        const float* wr = &fwo[tid * 8];
        #pragma unroll
        for (int k = 0; k < 8; k++) acc += wr[k] * f4[k];
        out[b * 2 + tid] = acc;
    }
}

extern "C" void kernel_launch(void* const* d_in, const int* in_sizes, int n_in,
                              void* d_out, int out_size) {
    const float* x   = (const float*)d_in[0];
    const float* w1  = (const float*)d_in[1];
    const float* b1  = (const float*)d_in[2];
    const float* wt  = (const float*)d_in[3];
    const float* bt  = (const float*)d_in[4];
    const float* wp  = (const float*)d_in[5];
    const float* bp  = (const float*)d_in[6];
    const float* wg  = (const float*)d_in[7];
    const float* bg  = (const float*)d_in[8];
    const float* wo  = (const float*)d_in[9];
    const float* bo  = (const float*)d_in[10];
    const float* w2  = (const float*)d_in[11];
    const float* b2  = (const float*)d_in[12];
    const float* w3  = (const float*)d_in[13];
    const float* b3  = (const float*)d_in[14];
    const float* fw1 = (const float*)d_in[15];
    const float* fb1 = (const float*)d_in[16];
    const float* fw2 = (const float*)d_in[17];
    const float* fb2 = (const float*)d_in[18];
    const float* fw3 = (const float*)d_in[19];
    const float* fb3 = (const float*)d_in[20];
    const float* fw4 = (const float*)d_in[21];
    const float* fb4 = (const float*)d_in[22];
    const float* fwo = (const float*)d_in[23];
    const float* fbo = (const float*)d_in[24];
    float* out = (float*)d_out;

    int B = in_sizes[0] / 121;

    prep_kernel<<<(PREP_TOTAL + 255) / 256, 256>>>(w2, w3, fw1, fw2);

    cudaFuncSetAttribute(braggnn_kernel,
                         cudaFuncAttributeMaxDynamicSharedMemorySize, SMEM_BYTES);
    braggnn_kernel<<<B, NTHREADS, SMEM_BYTES>>>(
        x, w1, b1, wt, bt, wp, bp, wg, bg, wo, bo, b2, b3,
        fb1, fb2, fw3, fb3, fw4, fb4, fwo, fbo, out);
}

// round 4
// speedup vs baseline: 2.1312x; 1.0004x over previous
#include <cuda_runtime.h>

#define NTHREADS 256

__device__ __forceinline__ float lrelu(float v) { return fmaxf(v, 0.01f * v); }

// ---- shared memory layout (float offsets) ----
#define OFF_XS    0        // 128   : input image 121
#define OFF_W1    128      // 576   : conv1 weights
#define OFF_WOT   704      // 2176  : wo transposed [i][c], stride 68 (float4-aligned)
#define OFF_A1    2880     // 5188  : conv1 out / nlb out [64][81] (+pad)
#define OFF_TH    8068     // 2997  : theta [81][36] -> y [81][37] -> a3 [32][49]
#define OFF_PH    11068    // 2592  : phi [32][81] -> flat [200]
#define OFF_G     13660    // 2916  : g [81][36]
#define OFF_ATT   16576    // 6885  : attn [81][85] -> fc scratch
#define OFF_FC    23464    // 128   : fc activations
#define SMEM_FLOATS 23592
#define SMEM_BYTES  (SMEM_FLOATS * 4)

// ---- prepacked weights in device scratch ----
__device__ __align__(16) float g_w2p[32 * 64 * 12];   // [o][c][12] (9 taps + pad)
__device__ __align__(16) float g_w3p[8 * 32 * 12];    // [o][c][12]
__device__ __align__(16) float g_fw1T[200 * 64];      // [k][j]
__device__ __align__(16) float g_fw2T[64 * 32];       // [k][j]

#define N_W2P (32 * 64 * 12)
#define N_W3P (8 * 32 * 12)
#define N_F1T (200 * 64)
#define N_F2T (64 * 32)
#define PREP_TOTAL (N_W2P + N_W3P + N_F1T + N_F2T)

__global__ void prep_kernel(const float* __restrict__ w2, const float* __restrict__ w3,
                            const float* __restrict__ fw1, const float* __restrict__ fw2) {
    int i = blockIdx.x * blockDim.x + threadIdx.x;
    if (i < N_W2P) {
        int k = i % 12, oc = i / 12;
        g_w2p[i] = (k < 9) ? w2[oc * 9 + k] : 0.f;
        return;
    }
    i -= N_W2P;
    if (i < N_W3P) {
        int k = i % 12, oc = i / 12;
        g_w3p[i] = (k < 9) ? w3[oc * 9 + k] : 0.f;
        return;
    }
    i -= N_W3P;
    if (i < N_F1T) {
        int kk = i / 64, jj = i % 64;
        g_fw1T[i] = fw1[jj * 200 + kk];
        return;
    }
    i -= N_F1T;
    if (i < N_F2T) {
        int kk = i / 32, jj = i % 32;
        g_fw2T[i] = fw2[jj * 64 + kk];
    }
}

__global__ void __launch_bounds__(NTHREADS, 2) braggnn_kernel(
    const float* __restrict__ x,
    const float* __restrict__ w1, const float* __restrict__ b1,
    const float* __restrict__ wt, const float* __restrict__ bt,
    const float* __restrict__ wp, const float* __restrict__ bp,
    const float* __restrict__ wg, const float* __restrict__ bg,
    const float* __restrict__ wo, const float* __restrict__ bo,
    const float* __restrict__ b2, const float* __restrict__ b3,
    const float* __restrict__ fb1, const float* __restrict__ fb2,
    const float* __restrict__ fw3, const float* __restrict__ fb3,
    const float* __restrict__ fw4, const float* __restrict__ fb4,
    const float* __restrict__ fwo, const float* __restrict__ fbo,
    float* __restrict__ out)
{
    extern __shared__ float sm[];
    const int b    = blockIdx.x;
    const int tid  = threadIdx.x;
    const int w    = tid >> 5;
    const int lane = tid & 31;

    // ---- preload image + small weights ----
    for (int i = tid; i < 121;  i += NTHREADS) sm[OFF_XS + i] = x[b * 121 + i];
    for (int i = tid; i < 576;  i += NTHREADS) sm[OFF_W1 + i] = w1[i];
    for (int i = tid; i < 2048; i += NTHREADS) {
        int ii = i & 31, cc = i >> 5;
        sm[OFF_WOT + ii * 68 + cc] = wo[cc * 32 + ii];
    }
    __syncthreads();

    // ---- phase 1: conv1  [1,11,11] -> [64,9,9] ----
    for (int idx = tid; idx < 64 * 81; idx += NTHREADS) {
        int c = idx / 81, s = idx - c * 81;
        int oy = s / 9, ox = s - oy * 9;
        const float* wr1 = &sm[OFF_W1 + c * 9];
        const float* xp  = &sm[OFF_XS + oy * 11 + ox];
        float acc = b1[c];
        #pragma unroll
        for (int ky = 0; ky < 3; ky++)
            #pragma unroll
            for (int kx = 0; kx < 3; kx++)
                acc += wr1[ky * 3 + kx] * xp[ky * 11 + kx];
        sm[OFF_A1 + idx] = acc;
    }
    __syncthreads();

    // ---- phase 2: theta/phi/g in ONE pass ----
    {
        const int s0 = lane, s1 = lane + 32;
        const bool s2ok = lane < 17;
        const int s2 = s2ok ? lane + 64 : 80;
        const int o0 = w * 4;

        float at[4][3], ap[4][3], ag[4][3];
        #pragma unroll
        for (int oi = 0; oi < 4; oi++) {
            float bv = bt[o0 + oi]; at[oi][0] = bv; at[oi][1] = bv; at[oi][2] = bv;
            float pv = bp[o0 + oi]; ap[oi][0] = pv; ap[oi][1] = pv; ap[oi][2] = pv;
            float gv = bg[o0 + oi]; ag[oi][0] = gv; ag[oi][1] = gv; ag[oi][2] = gv;
        }
        for (int c4 = 0; c4 < 64; c4 += 4) {
            float xv[4][3];
            #pragma unroll
            for (int cc = 0; cc < 4; cc++) {
                const float* ar = &sm[OFF_A1 + (c4 + cc) * 81];
                xv[cc][0] = ar[s0]; xv[cc][1] = ar[s1]; xv[cc][2] = ar[s2];
            }
            #pragma unroll
            for (int oi = 0; oi < 4; oi++) {
                float4 wtq = *(const float4*)&wt[(o0 + oi) * 64 + c4];
                float4 wpq = *(const float4*)&wp[(o0 + oi) * 64 + c4];
                float4 wgq = *(const float4*)&wg[(o0 + oi) * 64 + c4];
                #pragma unroll
                for (int p = 0; p < 3; p++) {
                    at[oi][p] += wtq.x * xv[0][p] + wtq.y * xv[1][p]
                               + wtq.z * xv[2][p] + wtq.w * xv[3][p];
                    ap[oi][p] += wpq.x * xv[0][p] + wpq.y * xv[1][p]
                               + wpq.z * xv[2][p] + wpq.w * xv[3][p];
                    ag[oi][p] += wgq.x * xv[0][p] + wgq.y * xv[1][p]
                               + wgq.z * xv[2][p] + wgq.w * xv[3][p];
                }
            }
        }
        #pragma unroll
        for (int oi = 0; oi < 4; oi++) {
            int o = o0 + oi;
            sm[OFF_TH + s0 * 36 + o] = at[oi][0];
            sm[OFF_TH + s1 * 36 + o] = at[oi][1];
            sm[OFF_PH + o * 81 + s0] = ap[oi][0];
            sm[OFF_PH + o * 81 + s1] = ap[oi][1];
            sm[OFF_G  + s0 * 36 + o] = ag[oi][0];
            sm[OFF_G  + s1 * 36 + o] = ag[oi][1];
            if (s2ok) {
                sm[OFF_TH + s2 * 36 + o] = at[oi][2];
                sm[OFF_PH + o * 81 + s2] = ap[oi][2];
                sm[OFF_G  + s2 * 36 + o] = ag[oi][2];
            }
        }
    }
    __syncthreads();

    // ---- phase 3a: logits + softmax -> full attn [81][85] ----
    {
        const int t0 = lane, t1 = lane + 32;
        const bool t2ok = lane < 17;
        const int t2 = t2ok ? lane + 64 : 80;

        for (int base = 0; base < 81; base += 24) {
            const int r0 = base + w * 3;
            if (r0 > 80) continue;
            const int ra = r0;
            const int rb = (r0 + 1 < 81) ? r0 + 1 : 80;
            const int rc = (r0 + 2 < 81) ? r0 + 2 : 80;
            const bool vb = r0 + 1 < 81, vc = r0 + 2 < 81;

            float l[3][3] = {{0,0,0},{0,0,0},{0,0,0}};
            for (int i4 = 0; i4 < 32; i4 += 4) {
                float4 tha = *(const float4*)&sm[OFF_TH + ra * 36 + i4];
                float4 thb = *(const float4*)&sm[OFF_TH + rb * 36 + i4];
                float4 thc = *(const float4*)&sm[OFF_TH + rc * 36 + i4];
                const float ta[4] = {tha.x, tha.y, tha.z, tha.w};
                const float tb[4] = {thb.x, thb.y, thb.z, thb.w};
                const float tc[4] = {thc.x, thc.y, thc.z, thc.w};
                #pragma unroll
                for (int u = 0; u < 4; u++) {
                    int i = i4 + u;
                    float p0v = sm[OFF_PH + i * 81 + t0];
                    float p1v = sm[OFF_PH + i * 81 + t1];
                    float p2v = sm[OFF_PH + i * 81 + t2];
                    l[0][0] += ta[u] * p0v; l[0][1] += ta[u] * p1v; l[0][2] += ta[u] * p2v;
                    l[1][0] += tb[u] * p0v; l[1][1] += tb[u] * p1v; l[1][2] += tb[u] * p2v;
                    l[2][0] += tc[u] * p0v; l[2][1] += tc[u] * p1v; l[2][2] += tc[u] * p2v;
                }
            }
            const int rr[3] = {ra, rb, rc};
            const bool vv[3] = {true, vb, vc};
            #pragma unroll
            for (int j = 0; j < 3; j++) {
                float l2v = t2ok ? l[j][2] : -1e30f;
                float m = fmaxf(fmaxf(l[j][0], l[j][1]), l2v);
                #pragma unroll
                for (int d = 16; d > 0; d >>= 1) m = fmaxf(m, __shfl_xor_sync(0xffffffffu, m, d));
                float e0 = __expf(l[j][0] - m), e1 = __expf(l[j][1] - m);
                float e2 = t2ok ? __expf(l[j][2] - m) : 0.f;
                float ssum = e0 + e1 + e2;
                #pragma unroll
                for (int d = 16; d > 0; d >>= 1) ssum += __shfl_xor_sync(0xffffffffu, ssum, d);
                float inv = 1.0f / ssum;
                if (vv[j]) {
                    float* arow = &sm[OFF_ATT + rr[j] * 85];
                    arow[t0] = e0 * inv;
                    arow[t1] = e1 * inv;
                    if (t2ok) arow[t2] = e2 * inv;
                }
            }
        }
    }
    __syncthreads();

    // ---- phase 3b: y = attn @ g, full-CTA. warp: 4 i-cols, lanes: s-rows ----
    {
        const int i0 = w * 4;
        const int s0 = lane, s1 = lane + 32;
        const bool s2ok = lane < 17;
        const int s2 = s2ok ? lane + 64 : 80;
        float acc[3][4] = {{0,0,0,0},{0,0,0,0},{0,0,0,0}};
        for (int t = 0; t < 81; t++) {
            float4 gv = *(const float4*)&sm[OFF_G + t * 36 + i0];   // broadcast
            float a0 = sm[OFF_ATT + s0 * 85 + t];
            float a1v = sm[OFF_ATT + s1 * 85 + t];
            float a2 = sm[OFF_ATT + s2 * 85 + t];
            acc[0][0] += a0 * gv.x;  acc[0][1] += a0 * gv.y;
            acc[0][2] += a0 * gv.z;  acc[0][3] += a0 * gv.w;
            acc[1][0] += a1v * gv.x; acc[1][1] += a1v * gv.y;
            acc[1][2] += a1v * gv.z; acc[1][3] += a1v * gv.w;
            acc[2][0] += a2 * gv.x;  acc[2][1] += a2 * gv.y;
            acc[2][2] += a2 * gv.z;  acc[2][3] += a2 * gv.w;
        }
        #pragma unroll
        for (int j = 0; j < 4; j++) {
            sm[OFF_TH + s0 * 37 + i0 + j] = acc[0][j];   // y overwrites theta
            sm[OFF_TH + s1 * 37 + i0 + j] = acc[1][j];
            if (s2ok) sm[OFF_TH + s2 * 37 + i0 + j] = acc[2][j];
        }
    }
    __syncthreads();

    // ---- phase 3c: out = wo @ y + bo + a1, lrelu. warp: 8 c, lanes: s ----
    {
        const int c0 = w * 8;
        const int s0 = lane, s1 = lane + 32;
        const bool s2ok = lane < 17;
        const int s2 = s2ok ? lane + 64 : 80;
        float acc[3][8];
        #pragma unroll
        for (int j = 0; j < 8; j++) { acc[0][j] = 0.f; acc[1][j] = 0.f; acc[2][j] = 0.f; }
        for (int i = 0; i < 32; i++) {
            float4 wv0 = *(const float4*)&sm[OFF_WOT + i * 68 + c0];
            float4 wv1 = *(const float4*)&sm[OFF_WOT + i * 68 + c0 + 4];
            float y0 = sm[OFF_TH + s0 * 37 + i];
            float y1 = sm[OFF_TH + s1 * 37 + i];
            float y2 = sm[OFF_TH + s2 * 37 + i];
            const float wvv[8] = {wv0.x, wv0.y, wv0.z, wv0.w, wv1.x, wv1.y, wv1.z, wv1.w};
            #pragma unroll
            for (int j = 0; j < 8; j++) {
                acc[0][j] += wvv[j] * y0;
                acc[1][j] += wvv[j] * y1;
                acc[2][j] += wvv[j] * y2;
            }
        }
        #pragma unroll
        for (int j = 0; j < 8; j++) {
            int c = c0 + j;
            float bv = bo[c];
            float v0 = acc[0][j] + bv + sm[OFF_A1 + c * 81 + s0];
            float v1 = acc[1][j] + bv + sm[OFF_A1 + c * 81 + s1];
            sm[OFF_A1 + c * 81 + s0] = lrelu(v0);
            sm[OFF_A1 + c * 81 + s1] = lrelu(v1);
            if (s2ok) {
                float v2 = acc[2][j] + bv + sm[OFF_A1 + c * 81 + s2];
                sm[OFF_A1 + c * 81 + s2] = lrelu(v2);
            }
        }
    }
    __syncthreads();

    // ---- phase 4: conv2 [64,9,9] -> [32,7,7], adjacent-pair windows ----
    {
        const bool act = lane < 28;
        const int row = lane >> 2, cp = lane & 3;
        const int p0 = row * 7 + cp * 2;
        const bool hasp1 = (cp < 3);
        const int i9 = row * 9 + cp * 2;
        const int o0 = w * 4;
        float acc0[4], acc1[4];
        #pragma unroll
        for (int oi = 0; oi < 4; oi++) { float bv = b2[o0 + oi]; acc0[oi] = bv; acc1[oi] = bv; }

        if (act) {
            for (int c = 0; c < 64; c++) {
                const float* ar = &sm[OFF_A1 + c * 81 + i9];
                float win[3][4];
                #pragma unroll
                for (int r = 0; r < 3; r++) {
                    win[r][0] = ar[r * 9 + 0];
                    win[r][1] = ar[r * 9 + 1];
                    win[r][2] = ar[r * 9 + 2];
                    win[r][3] = ar[r * 9 + 3];
                }
                #pragma unroll
                for (int oi = 0; oi < 4; oi++) {
                    const float* wr = &g_w2p[(((o0 + oi) << 6) + c) * 12];
                    float4 wa = *(const float4*)wr;
                    float4 wb = *(const float4*)(wr + 4);
                    float w8 = wr[8];
                    acc0[oi] += wa.x * win[0][0] + wa.y * win[0][1] + wa.z * win[0][2]
                              + wa.w * win[1][0] + wb.x * win[1][1] + wb.y * win[1][2]
                              + wb.z * win[2][0] + wb.w * win[2][1] + w8 * win[2][2];
                    acc1[oi] += wa.x * win[0][1] + wa.y * win[0][2] + wa.z * win[0][3]
                              + wa.w * win[1][1] + wb.x * win[1][2] + wb.y * win[1][3]
                              + wb.z * win[2][1] + wb.w * win[2][2] + w8 * win[2][3];
                }
            }
        }
        __syncthreads();   // A1 reads done before TH overwrite (TH held y, now a3)
        if (act) {
            #pragma unroll
            for (int oi = 0; oi < 4; oi++) {
                sm[OFF_TH + (o0 + oi) * 49 + p0] = lrelu(acc0[oi]);
                if (hasp1) sm[OFF_TH + (o0 + oi) * 49 + p0 + 1] = lrelu(acc1[oi]);
            }
        }
    }
    __syncthreads();

    // ---- phase 5: conv3 [32,7,7] -> [8,5,5]; warp = output channel ----
    if (lane < 25) {
        int o = w;
        int i7 = (lane / 5) * 7 + (lane % 5);
        float acc = b3[o];
        for (int c = 0; c < 32; c++) {
            const float* ar = &sm[OFF_TH + c * 49 + i7];
            const float* wr = &g_w3p[((o << 5) + c) * 12];
            float4 wa = *(const float4*)wr;
            float4 wb = *(const float4*)(wr + 4);
            float w8 = wr[8];
            acc += wa.x * ar[0]  + wa.y * ar[1]  + wa.z * ar[2]
                 + wa.w * ar[7]  + wb.x * ar[8]  + wb.y * ar[9]
                 + wb.z * ar[14] + wb.w * ar[15] + w8 * ar[16];
        }
        sm[OFF_PH + o * 25 + lane] = lrelu(acc);        // flat
    }
    __syncthreads();

    // ---- phase 6: MLP 200->64->32->16->8->2 ----
    float* flat = &sm[OFF_PH];
    float* scr  = &sm[OFF_ATT];
    float* f1 = &sm[OFF_FC];
    float* f2 = &sm[OFF_FC + 64];
    float* f3 = &sm[OFF_FC + 96];
    float* f4 = &sm[OFF_FC + 112];

    {   // fc1: 200 -> 64
        int q = tid >> 6, j = tid & 63;
        float acc = 0.f;
        int k0 = q * 50;
        for (int k = 0; k < 50; k++)
            acc += g_fw1T[(k0 + k) * 64 + j] * flat[k0 + k];
        scr[q * 64 + j] = acc;
    }
    __syncthreads();
    if (tid < 64)
        f1[tid] = lrelu(scr[tid] + scr[64 + tid] + scr[128 + tid] + scr[192 + tid] + fb1[tid]);
    __syncthreads();
    if (tid < 128) {  // fc2: 64 -> 32
        int q = tid >> 5, j = tid & 31;
        float acc = 0.f;
        int k0 = q * 16;
        for (int k = 0; k < 16; k++)
            acc += g_fw2T[(k0 + k) * 32 + j] * f1[k0 + k];
        scr[256 + q * 32 + j] = acc;
    }
    __syncthreads();
    if (tid < 32)
        f2[tid] = lrelu(scr[256 + tid] + scr[288 + tid] + scr[320 + tid] + scr[352 + tid] + fb2[tid]);
    __syncthreads();
    if (tid < 64) {   // fc3: 32 -> 16
        int j = tid >> 2, q = tid & 3;
        float acc = 0.f;
        const float* wr = &fw3[j * 32 + q * 8];
        for (int k = 0; k < 8; k++) acc += wr[k] * f2[q * 8 + k];
        acc += __shfl_xor_sync(0xffffffffu, acc, 1);
        acc += __shfl_xor_sync(0xffffffffu, acc, 2);
        if (q == 0) f3[j] = lrelu(acc + fb3[j]);
    }
    __syncthreads();
    if (tid < 32) {   // fc4: 16 -> 8
        int j = tid >> 2, q = tid & 3;
        float acc = 0.f;
        const float* wr = &fw4[j * 16 + q * 4];
        for (int k = 0; k < 4; k++) acc += wr[k] * f3[q * 4 + k];
        acc += __shfl_xor_sync(0xffffffffu, acc, 1);
        acc += __shfl_xor_sync(0xffffffffu, acc, 2);
        if (q == 0) f4[j] = lrelu(acc + fb4[j]);
    }
    __syncthreads();
    if (tid < 2) {    // fco: 8 -> 2
        float acc = fbo[tid];
        const float* wr = &fwo[tid * 8];
        #pragma unroll
        for (int k = 0; k < 8; k++) acc += wr[k] * f4[k];
        out[b * 2 + tid] = acc;
    }
}

extern "C" void kernel_launch(void* const* d_in, const int* in_sizes, int n_in,
                              void* d_out, int out_size) {
    const float* x   = (const float*)d_in[0];
    const float* w1  = (const float*)d_in[1];
    const float* b1  = (const float*)d_in[2];
    const float* wt  = (const float*)d_in[3];
    const float* bt  = (const float*)d_in[4];
    const float* wp  = (const float*)d_in[5];
    const float* bp  = (const float*)d_in[6];
    const float* wg  = (const float*)d_in[7];
    const float* bg  = (const float*)d_in[8];
    const float* wo  = (const float*)d_in[9];
    const float* bo  = (const float*)d_in[10];
    const float* w2  = (const float*)d_in[11];
    const float* b2  = (const float*)d_in[12];
    const float* w3  = (const float*)d_in[13];
    const float* b3  = (const float*)d_in[14];
    const float* fw1 = (const float*)d_in[15];
    const float* fb1 = (const float*)d_in[16];
    const float* fw2 = (const float*)d_in[17];
    const float* fb2 = (const float*)d_in[18];
    const float* fw3 = (const float*)d_in[19];
    const float* fb3 = (const float*)d_in[20];
    const float* fw4 = (const float*)d_in[21];
    const float* fb4 = (const float*)d_in[22];
    const float* fwo = (const float*)d_in[23];
    const float* fbo = (const float*)d_in[24];
    float* out = (float*)d_out;

    int B = in_sizes[0] / 121;

    prep_kernel<<<(PREP_TOTAL + 255) / 256, 256>>>(w2, w3, fw1, fw2);

    cudaFuncSetAttribute(braggnn_kernel,
                         cudaFuncAttributeMaxDynamicSharedMemorySize, SMEM_BYTES);
    braggnn_kernel<<<B, NTHREADS, SMEM_BYTES>>>(
        x, w1, b1, wt, bt, wp, bp, wg, bg, wo, bo, b2, b3,
        fb1, fb2, fw3, fb3, fw4, fb4, fwo, fbo, out);
}

// round 5
// speedup vs baseline: 4.1236x; 1.9349x over previous
#include <cuda_runtime.h>
#include <cstdint>

#define NTHREADS 256

__device__ __forceinline__ float lrelu(float v) { return fmaxf(v, 0.01f * v); }

__device__ __forceinline__ uint32_t f2tf(float f) {
    uint32_t r;
    asm("cvt.rna.tf32.f32 %0, %1;" : "=r"(r) : "f"(f));
    return r;
}
__device__ __forceinline__ float tfr(float f) {      // round-to-tf32, keep as float
    return __uint_as_float(f2tf(f));
}
__device__ __forceinline__ uint32_t ldu(const float* p) { return __float_as_uint(*p); }

__device__ __forceinline__ void mma_tf32(float* d,
                                         uint32_t a0, uint32_t a1, uint32_t a2, uint32_t a3,
                                         uint32_t b0, uint32_t b1) {
    asm volatile("mma.sync.aligned.m16n8k8.row.col.f32.tf32.tf32.f32 "
                 "{%0,%1,%2,%3},{%4,%5,%6,%7},{%8,%9},{%0,%1,%2,%3};"
                 : "+f"(d[0]), "+f"(d[1]), "+f"(d[2]), "+f"(d[3])
                 : "r"(a0), "r"(a1), "r"(a2), "r"(a3), "r"(b0), "r"(b1));
}

// ---- shared memory layout (float offsets) ----
#define OFF_XS    0        // 121 image (dead after conv1) ; then a3 [32][49]
#define OFF_W1    128      // 576 conv1 w (dead after conv1)
#define OFF_A3    0        // 1568
#define OFF_FLAT  1600     // 200
#define OFF_FCS   1800     // 256 fc1 scratch
#define OFF_F1    2056     // 64
#define OFF_F2    2120     // 32
#define OFF_F3    2152     // 16
#define OFF_F4    2168     // 8
#define OFF_FC2S  2200     // 128 fc2 scratch
#define OFF_A1    2880     // 5184  a1 [64][81]
#define OFF_TH    8068     // 2916  theta [81][36] -> Y [81][36]
#define OFF_PH    10984    // 2592  phi [i][81] -> staged wo [64][36]
#define OFF_G     13576    // 3168  g [88][36], rows 81..87 zero
#define OFF_ATT   16744    // 6808  staged W96 [96][68] (6528) -> attn [81][84] + pad4
#define OFF_RED   8068     // conv2 reduction: 8 x 1824 = 14592 (over TH/PH/G/ATT, all dead)
#define SMEM_FLOATS 23552
#define SMEM_BYTES  (SMEM_FLOATS * 4)

// ---- prepacked weights (device scratch, filled by prep kernel) ----
__device__ __align__(16) float g_w2f[9 * 8 * 8 * 32];  // conv2 frag-order, tf32-rounded
__device__ __align__(16) float g_w3p[8 * 32 * 12];     // conv3 [o][c][12]
__device__ __align__(16) float g_fw1T[200 * 64];       // [k][j]
__device__ __align__(16) float g_fw2T[64 * 32];        // [k][j]

#define N_W2F (9 * 8 * 8 * 32)
#define N_W3P (8 * 32 * 12)
#define N_F1T (200 * 64)
#define N_F2T (64 * 32)
#define PREP_TOTAL (N_W2F + N_W3P + N_F1T + N_F2T)

__global__ void prep_kernel(const float* __restrict__ w2, const float* __restrict__ w3,
                            const float* __restrict__ fw1, const float* __restrict__ fw2) {
    int i = blockIdx.x * blockDim.x + threadIdx.x;
    if (i < N_W2F) {
        // layout: (((tap*8 + wblk)*8 + r)*32 + lane), r = mt*4 + ai
        int lane = i & 31;
        int r    = (i >> 5) & 7;
        int wblk = (i >> 8) & 7;
        int tap  = i >> 11;
        int g  = lane >> 2, tg = lane & 3;
        int mt = r >> 2,    ai = r & 3;
        int o = mt * 16 + g + 8 * (ai & 1);
        int c = wblk * 8 + tg + 4 * (ai >> 1);
        g_w2f[i] = tfr(w2[o * 576 + c * 9 + tap]);
        return;
    }
    i -= N_W2F;
    if (i < N_W3P) {
        int k = i % 12, oc = i / 12;
        g_w3p[i] = (k < 9) ? w3[oc * 9 + k] : 0.f;
        return;
    }
    i -= N_W3P;
    if (i < N_F1T) {
        int kk = i / 64, jj = i % 64;
        g_fw1T[i] = fw1[jj * 200 + kk];
        return;
    }
    i -= N_F1T;
    if (i < N_F2T) {
        int kk = i / 32, jj = i % 32;
        g_fw2T[i] = fw2[jj * 64 + kk];
    }
}

__global__ void __launch_bounds__(NTHREADS, 2) braggnn_kernel(
    const float* __restrict__ x,
    const float* __restrict__ w1, const float* __restrict__ b1,
    const float* __restrict__ wt, const float* __restrict__ bt,
    const float* __restrict__ wp, const float* __restrict__ bp,
    const float* __restrict__ wg, const float* __restrict__ bg,
    const float* __restrict__ wo, const float* __restrict__ bo,
    const float* __restrict__ b2, const float* __restrict__ b3,
    const float* __restrict__ fb1, const float* __restrict__ fb2,
    const float* __restrict__ fw3, const float* __restrict__ fb3,
    const float* __restrict__ fw4, const float* __restrict__ fb4,
    const float* __restrict__ fwo, const float* __restrict__ fbo,
    float* __restrict__ out)
{
    extern __shared__ float sm[];
    const int b    = blockIdx.x;
    const int tid  = threadIdx.x;
    const int w    = tid >> 5;
    const int lane = tid & 31;
    const int g    = lane >> 2;   // mma groupID
    const int tg   = lane & 3;    // mma threadID-in-group

    // ---- preload / staging / zero-fill ----
    for (int i = tid; i < 121; i += NTHREADS) sm[OFF_XS + i] = x[b * 121 + i];
    for (int i = tid; i < 576; i += NTHREADS) sm[OFF_W1 + i] = w1[i];
    for (int i = tid; i < 6144; i += NTHREADS) {       // W96 [96][68] into ATT region
        int r = i >> 6, c = i & 63;
        const float* src = (r < 32) ? wt : ((r < 64) ? wp : wg);
        sm[OFF_ATT + r * 68 + c] = tfr(src[(r & 31) * 64 + c]);
    }
    for (int i = tid; i < 7 * 36; i += NTHREADS) sm[OFF_G + 81 * 36 + i] = 0.f;
    if (tid < 4) sm[OFF_ATT + 81 * 84 + tid] = 0.f;    // attn tail pad
    __syncthreads();

    // ---- phase 1: conv1 [1,11,11] -> [64,9,9] (scalar), store tf32-rounded ----
    for (int idx = tid; idx < 64 * 81; idx += NTHREADS) {
        int c = idx / 81, s = idx - c * 81;
        int oy = s / 9, ox = s - oy * 9;
        const float* wr1 = &sm[OFF_W1 + c * 9];
        const float* xp  = &sm[OFF_XS + oy * 11 + ox];
        float acc = b1[c];
        #pragma unroll
        for (int ky = 0; ky < 3; ky++)
            #pragma unroll
            for (int kx = 0; kx < 3; kx++)
                acc += wr1[ky * 3 + kx] * xp[ky * 11 + kx];
        sm[OFF_A1 + idx] = tfr(acc);
    }
    __syncthreads();

    // ---- phase 2 (mma): P[96][81] = W96[96][64] @ A1[64][81] ----
    if (w < 6) {
        const int m0 = w * 16;
        float D[11][4];
        #pragma unroll
        for (int nt = 0; nt < 11; nt++) { D[nt][0]=0.f; D[nt][1]=0.f; D[nt][2]=0.f; D[nt][3]=0.f; }
        for (int k0 = 0; k0 < 64; k0 += 8) {
            uint32_t a0 = ldu(&sm[OFF_ATT + (m0 + g)     * 68 + k0 + tg]);
            uint32_t a1 = ldu(&sm[OFF_ATT + (m0 + g + 8) * 68 + k0 + tg]);
            uint32_t a2 = ldu(&sm[OFF_ATT + (m0 + g)     * 68 + k0 + tg + 4]);
            uint32_t a3 = ldu(&sm[OFF_ATT + (m0 + g + 8) * 68 + k0 + tg + 4]);
            #pragma unroll
            for (int nt = 0; nt < 11; nt++) {
                uint32_t b0 = ldu(&sm[OFF_A1 + (k0 + tg)     * 81 + nt * 8 + g]);
                uint32_t b1 = ldu(&sm[OFF_A1 + (k0 + tg + 4) * 81 + nt * 8 + g]);
                mma_tf32(D[nt], a0, a1, a2, a3, b0, b1);
            }
        }
        const int mat = w >> 1;                      // 0=theta 1=phi 2=g
        const float* bias = (mat == 0) ? bt : ((mat == 1) ? bp : bg);
        const int ch0 = (w & 1) * 16 + g, ch1 = ch0 + 8;
        const float bv0 = bias[ch0], bv1 = bias[ch1];
        #pragma unroll
        for (int nt = 0; nt < 11; nt++)
            #pragma unroll
            for (int dd = 0; dd < 2; dd++) {
                int s = nt * 8 + 2 * tg + dd;
                if (s < 81) {
                    float v0 = tfr(D[nt][dd] + bv0);
                    float v1 = tfr(D[nt][2 + dd] + bv1);
                    if (mat == 0)      { sm[OFF_TH + s * 36 + ch0] = v0; sm[OFF_TH + s * 36 + ch1] = v1; }
                    else if (mat == 1) { sm[OFF_PH + ch0 * 81 + s] = v0; sm[OFF_PH + ch1 * 81 + s] = v1; }
                    else               { sm[OFF_G  + s * 36 + ch0] = v0; sm[OFF_G  + s * 36 + ch1] = v1; }
                }
            }
    }
    __syncthreads();

    // ---- phase 3a (mma): logits = theta @ phi, register softmax -> attn[81][84] ----
    if (w < 6) {
        const int m0 = w * 16;
        const int r0 = min(m0 + g, 80), r1 = min(m0 + g + 8, 80);
        float D[11][4];
        #pragma unroll
        for (int nt = 0; nt < 11; nt++) { D[nt][0]=0.f; D[nt][1]=0.f; D[nt][2]=0.f; D[nt][3]=0.f; }
        for (int k0 = 0; k0 < 32; k0 += 8) {
            uint32_t a0 = ldu(&sm[OFF_TH + r0 * 36 + k0 + tg]);
            uint32_t a1 = ldu(&sm[OFF_TH + r1 * 36 + k0 + tg]);
            uint32_t a2 = ldu(&sm[OFF_TH + r0 * 36 + k0 + tg + 4]);
            uint32_t a3 = ldu(&sm[OFF_TH + r1 * 36 + k0 + tg + 4]);
            #pragma unroll
            for (int nt = 0; nt < 11; nt++) {
                uint32_t b0 = ldu(&sm[OFF_PH + (k0 + tg)     * 81 + nt * 8 + g]);
                uint32_t b1 = ldu(&sm[OFF_PH + (k0 + tg + 4) * 81 + nt * 8 + g]);
                mma_tf32(D[nt], a0, a1, a2, a3, b0, b1);
            }
        }
        float mx0 = -1e30f, mx1 = -1e30f;
        #pragma unroll
        for (int nt = 0; nt < 11; nt++)
            #pragma unroll
            for (int dd = 0; dd < 2; dd++) {
                int t = nt * 8 + 2 * tg + dd;
                if (t < 81) { mx0 = fmaxf(mx0, D[nt][dd]); mx1 = fmaxf(mx1, D[nt][2 + dd]); }
            }
        mx0 = fmaxf(mx0, __shfl_xor_sync(0xffffffffu, mx0, 1));
        mx0 = fmaxf(mx0, __shfl_xor_sync(0xffffffffu, mx0, 2));
        mx1 = fmaxf(mx1, __shfl_xor_sync(0xffffffffu, mx1, 1));
        mx1 = fmaxf(mx1, __shfl_xor_sync(0xffffffffu, mx1, 2));
        float s0 = 0.f, s1 = 0.f;
        #pragma unroll
        for (int nt = 0; nt < 11; nt++)
            #pragma unroll
            for (int dd = 0; dd < 2; dd++) {
                int t = nt * 8 + 2 * tg + dd;
                float e0 = (t < 81) ? __expf(D[nt][dd]     - mx0) : 0.f;
                float e1 = (t < 81) ? __expf(D[nt][2 + dd] - mx1) : 0.f;
                D[nt][dd] = e0; D[nt][2 + dd] = e1;
                s0 += e0; s1 += e1;
            }
        s0 += __shfl_xor_sync(0xffffffffu, s0, 1);
        s0 += __shfl_xor_sync(0xffffffffu, s0, 2);
        s1 += __shfl_xor_sync(0xffffffffu, s1, 1);
        s1 += __shfl_xor_sync(0xffffffffu, s1, 2);
        const float inv0 = 1.0f / s0, inv1 = 1.0f / s1;
        const int sr0 = m0 + g, sr1 = m0 + g + 8;
        #pragma unroll
        for (int nt = 0; nt < 11; nt++)
            #pragma unroll
            for (int dd = 0; dd < 2; dd++) {
                int t = nt * 8 + 2 * tg + dd;
                if (t < 84) {
                    if (sr0 < 81) sm[OFF_ATT + sr0 * 84 + t] = (t < 81) ? tfr(D[nt][dd]     * inv0) : 0.f;
                    if (sr1 < 81) sm[OFF_ATT + sr1 * 84 + t] = (t < 81) ? tfr(D[nt][2 + dd] * inv1) : 0.f;
                }
            }
    }
    __syncthreads();

    // ---- phase 3b (mma): Y[81][32] = attn[81][88] @ g[88][32] ; warps 6,7 stage wo ----
    if (w < 6) {
        const int m0 = w * 16;
        const int r0 = min(m0 + g, 80), r1 = min(m0 + g + 8, 80);
        float D[4][4];
        #pragma unroll
        for (int nt = 0; nt < 4; nt++) { D[nt][0]=0.f; D[nt][1]=0.f; D[nt][2]=0.f; D[nt][3]=0.f; }
        for (int k0 = 0; k0 < 88; k0 += 8) {
            uint32_t a0 = ldu(&sm[OFF_ATT + r0 * 84 + k0 + tg]);
            uint32_t a1 = ldu(&sm[OFF_ATT + r1 * 84 + k0 + tg]);
            uint32_t a2 = ldu(&sm[OFF_ATT + r0 * 84 + k0 + tg + 4]);
            uint32_t a3 = ldu(&sm[OFF_ATT + r1 * 84 + k0 + tg + 4]);
            #pragma unroll
            for (int nt = 0; nt < 4; nt++) {
                uint32_t b0 = ldu(&sm[OFF_G + (k0 + tg)     * 36 + nt * 8 + g]);
                uint32_t b1 = ldu(&sm[OFF_G + (k0 + tg + 4) * 36 + nt * 8 + g]);
                mma_tf32(D[nt], a0, a1, a2, a3, b0, b1);
            }
        }
        const int sr0 = m0 + g, sr1 = m0 + g + 8;
        #pragma unroll
        for (int nt = 0; nt < 4; nt++)
            #pragma unroll
            for (int dd = 0; dd < 2; dd++) {
                int i = nt * 8 + 2 * tg + dd;
                if (sr0 < 81) sm[OFF_TH + sr0 * 36 + i] = tfr(D[nt][dd]);
                if (sr1 < 81) sm[OFF_TH + sr1 * 36 + i] = tfr(D[nt][2 + dd]);
            }
    } else {
        for (int i = tid - 192; i < 2048; i += 64) {   // wo[64][32] -> PH, stride 36
            int r = i >> 5, c = i & 31;
            sm[OFF_PH + r * 36 + c] = tfr(wo[i]);
        }
    }
    __syncthreads();

    // ---- phase 3c (mma): Z[64][81] = wo @ Y^T, + bo + residual + lrelu -> A1 ----
    {
        const int mt = w >> 1, m0 = mt * 16;
        const int nbeg = (w & 1) ? 6 : 0, nend = (w & 1) ? 11 : 6;
        float D[6][4];
        #pragma unroll
        for (int j = 0; j < 6; j++) { D[j][0]=0.f; D[j][1]=0.f; D[j][2]=0.f; D[j][3]=0.f; }
        for (int k0 = 0; k0 < 32; k0 += 8) {
            uint32_t a0 = ldu(&sm[OFF_PH + (m0 + g)     * 36 + k0 + tg]);
            uint32_t a1 = ldu(&sm[OFF_PH + (m0 + g + 8) * 36 + k0 + tg]);
            uint32_t a2 = ldu(&sm[OFF_PH + (m0 + g)     * 36 + k0 + tg + 4]);
            uint32_t a3 = ldu(&sm[OFF_PH + (m0 + g + 8) * 36 + k0 + tg + 4]);
            int j = 0;
            for (int nt = nbeg; nt < nend; nt++, j++) {
                uint32_t b0 = ldu(&sm[OFF_TH + (nt * 8 + g) * 36 + k0 + tg]);
                uint32_t b1 = ldu(&sm[OFF_TH + (nt * 8 + g) * 36 + k0 + tg + 4]);
                mma_tf32(D[j], a0, a1, a2, a3, b0, b1);
            }
        }
        const int c0 = m0 + g, c1 = m0 + g + 8;
        const float bo0 = bo[c0], bo1 = bo[c1];
        int j = 0;
        for (int nt = nbeg; nt < nend; nt++, j++)
            #pragma unroll
            for (int dd = 0; dd < 2; dd++) {
                int s = nt * 8 + 2 * tg + dd;
                if (s < 81) {
                    sm[OFF_A1 + c0 * 81 + s] = tfr(lrelu(D[j][dd]     + bo0 + sm[OFF_A1 + c0 * 81 + s]));
                    sm[OFF_A1 + c1 * 81 + s] = tfr(lrelu(D[j][2 + dd] + bo1 + sm[OFF_A1 + c1 * 81 + s]));
                }
            }
    }
    __syncthreads();

    // ---- phase 4 (mma): conv2 = 9 shifted GEMMs, K split by channel across warps ----
    {
        const int c0 = w * 8;
        int rmv[7];
        #pragma unroll
        for (int nt = 0; nt < 7; nt++) {
            int p = nt * 8 + g;
            rmv[nt] = (p < 49) ? (p / 7) * 9 + (p % 7) : 0;
        }
        float D[14][4];
        #pragma unroll
        for (int j = 0; j < 14; j++) { D[j][0]=0.f; D[j][1]=0.f; D[j][2]=0.f; D[j][3]=0.f; }
        for (int tap = 0; tap < 9; tap++) {
            const int off = (tap / 3) * 9 + (tap % 3);
            const float* af = &g_w2f[(tap * 8 + w) * 256];
            uint32_t A[8];
            #pragma unroll
            for (int r = 0; r < 8; r++) A[r] = __float_as_uint(af[r * 32 + lane]);
            #pragma unroll
            for (int nt = 0; nt < 7; nt++) {
                uint32_t b0 = ldu(&sm[OFF_A1 + (c0 + tg)     * 81 + rmv[nt] + off]);
                uint32_t b1 = ldu(&sm[OFF_A1 + (c0 + tg + 4) * 81 + rmv[nt] + off]);
                mma_tf32(D[nt],     A[0], A[1], A[2], A[3], b0, b1);
                mma_tf32(D[7 + nt], A[4], A[5], A[6], A[7], b0, b1);
            }
        }
        __syncthreads();                 // A1 reads done before RED overwrites nothing of A1 (disjoint), but TH/ATT now dead
        float* buf = &sm[OFF_RED + w * 1824];
        #pragma unroll
        for (int mt = 0; mt < 2; mt++)
            #pragma unroll
            for (int nt = 0; nt < 7; nt++)
                #pragma unroll
                for (int dd = 0; dd < 2; dd++) {
                    int o0 = mt * 16 + g, p = nt * 8 + 2 * tg + dd;
                    buf[o0 * 57 + p]       = D[mt * 7 + nt][dd];
                    buf[(o0 + 8) * 57 + p] = D[mt * 7 + nt][2 + dd];
                }
    }
    __syncthreads();
    for (int e = tid; e < 1568; e += NTHREADS) {     // reduce 8 warps + bias + lrelu -> a3
        int o = e / 49, p = e % 49;
        float s = b2[o];
        #pragma unroll
        for (int ww = 0; ww < 8; ww++) s += sm[OFF_RED + ww * 1824 + o * 57 + p];
        sm[OFF_A3 + e] = lrelu(s);
    }
    __syncthreads();

    // ---- phase 5: conv3 [32,7,7] -> [8,5,5] (scalar) ----
    if (lane < 25) {
        const int o = w;
        const int i7 = (lane / 5) * 7 + (lane % 5);
        float acc = b3[o];
        for (int c = 0; c < 32; c++) {
            const float* ar = &sm[OFF_A3 + c * 49 + i7];
            const float* wr = &g_w3p[((o << 5) + c) * 12];
            float4 wa = *(const float4*)wr;
            float4 wb = *(const float4*)(wr + 4);
            float w8 = wr[8];
            acc += wa.x * ar[0]  + wa.y * ar[1]  + wa.z * ar[2]
                 + wa.w * ar[7]  + wb.x * ar[8]  + wb.y * ar[9]
                 + wb.z * ar[14] + wb.w * ar[15] + w8 * ar[16];
        }
        sm[OFF_FLAT + o * 25 + lane] = lrelu(acc);
    }
    __syncthreads();

    // ---- phase 6: MLP 200->64->32->16->8->2 ----
    float* flat = &sm[OFF_FLAT];
    float* scr  = &sm[OFF_FCS];
    float* sc2  = &sm[OFF_FC2S];
    float* f1 = &sm[OFF_F1];
    float* f2 = &sm[OFF_F2];
    float* f3 = &sm[OFF_F3];
    float* f4 = &sm[OFF_F4];

    {   // fc1: 200 -> 64
        int q = tid >> 6, j = tid & 63;
        float acc = 0.f;
        int k0 = q * 50;
        for (int k = 0; k < 50; k++)
            acc += g_fw1T[(k0 + k) * 64 + j] * flat[k0 + k];
        scr[q * 64 + j] = acc;
    }
    __syncthreads();
    if (tid < 64)
        f1[tid] = lrelu(scr[tid] + scr[64 + tid] + scr[128 + tid] + scr[192 + tid] + fb1[tid]);
    __syncthreads();
    if (tid < 128) {  // fc2: 64 -> 32
        int q = tid >> 5, j = tid & 31;
        float acc = 0.f;
        int k0 = q * 16;
        for (int k = 0; k < 16; k++)
            acc += g_fw2T[(k0 + k) * 32 + j] * f1[k0 + k];
        sc2[q * 32 + j] = acc;
    }
    __syncthreads();
    if (tid < 32)
        f2[tid] = lrelu(sc2[tid] + sc2[32 + tid] + sc2[64 + tid] + sc2[96 + tid] + fb2[tid]);
    __syncthreads();
    if (tid < 64) {   // fc3: 32 -> 16
        int j = tid >> 2, q = tid & 3;
        float acc = 0.f;
        const float* wr = &fw3[j * 32 + q * 8];
        for (int k = 0; k < 8; k++) acc += wr[k] * f2[q * 8 + k];
        acc += __shfl_xor_sync(0xffffffffu, acc, 1);
        acc += __shfl_xor_sync(0xffffffffu, acc, 2);
        if (q == 0) f3[j] = lrelu(acc + fb3[j]);
    }
    __syncthreads();
    if (tid < 32) {   // fc4: 16 -> 8
        int j = tid >> 2, q = tid & 3;
        float acc = 0.f;
        const float* wr = &fw4[j * 16 + q * 4];
        for (int k = 0; k < 4; k++) acc += wr[k] * f3[q * 4 + k];
        acc += __shfl_xor_sync(0xffffffffu, acc, 1);
        acc += __shfl_xor_sync(0xffffffffu, acc, 2);
        if (q == 0) f4[j] = lrelu(acc + fb4[j]);
    }
    __syncthreads();
    if (tid < 2) {    // fco: 8 -> 2
        float acc = fbo[tid];
        const float* wr = &fwo[tid * 8];
        #pragma unroll
        for (int k = 0; k < 8; k++) acc += wr[k] * f4[k];
        out[b * 2 + tid] = acc;
    }
}

extern "C" void kernel_launch(void* const* d_in, const int* in_sizes, int n_in,
                              void* d_out, int out_size) {
    const float* x   = (const float*)d_in[0];
    const float* w1  = (const float*)d_in[1];
    const float* b1  = (const float*)d_in[2];
    const float* wt  = (const float*)d_in[3];
    const float* bt  = (const float*)d_in[4];
    const float* wp  = (const float*)d_in[5];
    const float* bp  = (const float*)d_in[6];
    const float* wg  = (const float*)d_in[7];
    const float* bg  = (const float*)d_in[8];
    const float* wo  = (const float*)d_in[9];
    const float* bo  = (const float*)d_in[10];
    const float* w2  = (const float*)d_in[11];
    const float* b2  = (const float*)d_in[12];
    const float* w3  = (const float*)d_in[13];
    const float* b3  = (const float*)d_in[14];
    const float* fw1 = (const float*)d_in[15];
    const float* fb1 = (const float*)d_in[16];
    const float* fw2 = (const float*)d_in[17];
    const float* fb2 = (const float*)d_in[18];
    const float* fw3 = (const float*)d_in[19];
    const float* fb3 = (const float*)d_in[20];
    const float* fw4 = (const float*)d_in[21];
    const float* fb4 = (const float*)d_in[22];
    const float* fwo = (const float*)d_in[23];
    const float* fbo = (const float*)d_in[24];
    float* out = (float*)d_out;

    int B = in_sizes[0] / 121;

    prep_kernel<<<(PREP_TOTAL + 255) / 256, 256>>>(w2, w3, fw1, fw2);

    cudaFuncSetAttribute(braggnn_kernel,
                         cudaFuncAttributeMaxDynamicSharedMemorySize, SMEM_BYTES);
    braggnn_kernel<<<B, NTHREADS, SMEM_BYTES>>>(
        x, w1, b1, wt, bt, wp, bp, wg, bg, wo, bo, b2, b3,
        fb1, fb2, fw3, fb3, fw4, fb4, fwo, fbo, out);
}

// round 7
// speedup vs baseline: 5.2236x; 1.2668x over previous
#include <cuda_runtime.h>
#include <cstdint>

#define NTHREADS 256

__device__ __forceinline__ float lrelu(float v) { return fmaxf(v, 0.01f * v); }

__device__ __forceinline__ uint32_t f2tf(float f) {
    uint32_t r;
    asm("cvt.rna.tf32.f32 %0, %1;" : "=r"(r) : "f"(f));
    return r;
}
__device__ __forceinline__ float tfr(float f) {      // round-to-tf32, keep as float
    return __uint_as_float(f2tf(f));
}
__device__ __forceinline__ uint32_t ldu(const float* p) { return __float_as_uint(*p); }

__device__ __forceinline__ void mma_tf32(float* d,
                                         uint32_t a0, uint32_t a1, uint32_t a2, uint32_t a3,
                                         uint32_t b0, uint32_t b1) {
    asm volatile("mma.sync.aligned.m16n8k8.row.col.f32.tf32.tf32.f32 "
                 "{%0,%1,%2,%3},{%4,%5,%6,%7},{%8,%9},{%0,%1,%2,%3};"
                 : "+f"(d[0]), "+f"(d[1]), "+f"(d[2]), "+f"(d[3])
                 : "r"(a0), "r"(a1), "r"(a2), "r"(a3), "r"(b0), "r"(b1));
}

// ---- shared memory layout (float offsets) ----
// low region (reused over time):
#define OFF_XS    0        // 121 image (phase 1 only)
#define OFF_P     128      // 16*88 = 1408 im2col patches (phase 1 only)
#define OFF_W1S   1536     // 64*20 = 1280 staged conv1 weights (phase 1 only)
#define OFF_A3    0        // 32*56 = 1792 conv2 out (from conv2-reduce on)
#define OFF_FLAT  1792     // 200
#define OFF_FCS   1992     // 256 fc1 scratch
#define OFF_F1    2248     // 64
#define OFF_F2    2312     // 32
#define OFF_F3    2344     // 16
#define OFF_F4    2360     // 8
#define OFF_FC2S  2368     // 128 fc2 scratch
// high region:
#define OFF_A1    2880     // 5184  a1 [64][81]
#define OFF_TH    8068     // 2916  theta [81][36] -> Y [81][36]
#define OFF_PH    10984    // 2592  phi [i][81] -> staged wo [64][36]
#define OFF_G     13576    // 3168  g [88][36], rows 81..87 zero
#define OFF_ATT   16744    // 6808  staged W96 [96][68] -> attn [81][84] + pad4
#define OFF_RED   8068     // conv2 reduction: 8 x 1824 (TH..ATT dead)
#define OFF_RED3  8068     // conv3 reduction: 8 x 264 (dead again)
#define SMEM_FLOATS 23552
#define SMEM_BYTES  (SMEM_FLOATS * 4)

// ---- prepacked weights (device scratch, filled by prep kernel) ----
__device__ __align__(16) float g_w2f[9 * 8 * 8 * 32];  // conv2 frag-order, tf32
__device__ __align__(16) float g_w3f[9 * 4 * 2 * 32];  // conv3 frag-order, tf32
__device__ __align__(16) float g_fw1T[200 * 64];       // [k][j]
__device__ __align__(16) float g_fw2T[64 * 32];        // [k][j]

#define N_W2F (9 * 8 * 8 * 32)
#define N_W3F (9 * 4 * 2 * 32)
#define N_F1T (200 * 64)
#define N_F2T (64 * 32)
#define PREP_TOTAL (N_W2F + N_W3F + N_F1T + N_F2T)

__global__ void prep_kernel(const float* __restrict__ w2, const float* __restrict__ w3,
                            const float* __restrict__ fw1, const float* __restrict__ fw2) {
    int i = blockIdx.x * blockDim.x + threadIdx.x;
    if (i < N_W2F) {
        // layout: (((tap*8 + wblk)*8 + r)*32 + lane), r = mt*4 + ai
        int lane = i & 31;
        int r    = (i >> 5) & 7;
        int wblk = (i >> 8) & 7;
        int tap  = i >> 11;
        int g  = lane >> 2, tg = lane & 3;
        int mt = r >> 2,    ai = r & 3;
        int o = mt * 16 + g + 8 * (ai & 1);
        int c = wblk * 8 + tg + 4 * (ai >> 1);
        g_w2f[i] = tfr(w2[o * 576 + c * 9 + tap]);
        return;
    }
    i -= N_W2F;
    if (i < N_W3F) {
        // layout: (((tap*4 + kc)*2 + ai)*32 + lane); row o = lane>>2, k = kc*8 + (lane&3) + 4*ai
        int lane = i & 31;
        int ai   = (i >> 5) & 1;
        int kc   = (i >> 6) & 3;
        int tap  = i >> 8;
        int o = lane >> 2, tg = lane & 3;
        int c = kc * 8 + tg + 4 * ai;
        g_w3f[i] = tfr(w3[o * 288 + c * 9 + tap]);
        return;
    }
    i -= N_W3F;
    if (i < N_F1T) {
        int kk = i / 64, jj = i % 64;
        g_fw1T[i] = fw1[jj * 200 + kk];
        return;
    }
    i -= N_F1T;
    if (i < N_F2T) {
        int kk = i / 32, jj = i % 32;
        g_fw2T[i] = fw2[jj * 64 + kk];
    }
}

__global__ void __launch_bounds__(NTHREADS, 2) braggnn_kernel(
    const float* __restrict__ x,
    const float* __restrict__ w1, const float* __restrict__ b1,
    const float* __restrict__ wt, const float* __restrict__ bt,
    const float* __restrict__ wp, const float* __restrict__ bp,
    const float* __restrict__ wg, const float* __restrict__ bg,
    const float* __restrict__ wo, const float* __restrict__ bo,
    const float* __restrict__ b2, const float* __restrict__ b3,
    const float* __restrict__ fb1, const float* __restrict__ fb2,
    const float* __restrict__ fw3, const float* __restrict__ fb3,
    const float* __restrict__ fw4, const float* __restrict__ fb4,
    const float* __restrict__ fwo, const float* __restrict__ fbo,
    float* __restrict__ out)
{
    extern __shared__ float sm[];
    const int b    = blockIdx.x;
    const int tid  = threadIdx.x;
    const int w    = tid >> 5;
    const int lane = tid & 31;
    const int g    = lane >> 2;   // mma groupID
    const int tg   = lane & 3;    // mma threadID-in-group

    // ---- preload / staging / zero-fill ----
    for (int i = tid; i < 121; i += NTHREADS) sm[OFF_XS + i] = x[b * 121 + i];
    for (int i = tid; i < 6144; i += NTHREADS) {       // W96 [96][68] into ATT region
        int r = i >> 6, c = i & 63;
        const float* src = (r < 32) ? wt : ((r < 64) ? wp : wg);
        sm[OFF_ATT + r * 68 + c] = tfr(src[(r & 31) * 64 + c]);
    }
    for (int i = tid; i < 1280; i += NTHREADS) {       // W1 staged [64][20]
        int o = i / 20, k = i % 20;
        sm[OFF_W1S + i] = (k < 9) ? tfr(w1[o * 9 + k]) : 0.f;
    }
    for (int i = tid; i < 1408; i += NTHREADS) sm[OFF_P + i] = 0.f;   // patches zero
    for (int i = tid; i < 7 * 36; i += NTHREADS) sm[OFF_G + 81 * 36 + i] = 0.f;
    if (tid < 4) sm[OFF_ATT + 81 * 84 + tid] = 0.f;    // attn tail pad
    __syncthreads();

    // ---- im2col patches P[16][88]: rows = taps, cols = output pos ----
    for (int i = tid; i < 729; i += NTHREADS) {
        int tap = i / 81, s = i - tap * 81;
        int iy = s / 9 + tap / 3, ix = s % 9 + tap % 3;
        sm[OFF_P + tap * 88 + s] = tfr(sm[OFF_XS + iy * 11 + ix]);
    }
    __syncthreads();

    // ---- phase 1 (mma): A1[64][81] = W1[64][16] @ P[16][81] ----
    {
        const int m0 = (w >> 1) * 16;
        const int nbeg = (w & 1) ? 6 : 0, nend = (w & 1) ? 11 : 6;
        float D[6][4];
        #pragma unroll
        for (int j = 0; j < 6; j++) { D[j][0]=0.f; D[j][1]=0.f; D[j][2]=0.f; D[j][3]=0.f; }
        #pragma unroll
        for (int kc = 0; kc < 2; kc++) {
            const int k0 = kc * 8;
            uint32_t a0 = ldu(&sm[OFF_W1S + (m0 + g)     * 20 + k0 + tg]);
            uint32_t a1 = ldu(&sm[OFF_W1S + (m0 + g + 8) * 20 + k0 + tg]);
            uint32_t a2 = ldu(&sm[OFF_W1S + (m0 + g)     * 20 + k0 + tg + 4]);
            uint32_t a3 = ldu(&sm[OFF_W1S + (m0 + g + 8) * 20 + k0 + tg + 4]);
            int j = 0;
            for (int nt = nbeg; nt < nend; nt++, j++) {
                uint32_t b0 = ldu(&sm[OFF_P + (k0 + tg)     * 88 + nt * 8 + g]);
                uint32_t b1 = ldu(&sm[OFF_P + (k0 + tg + 4) * 88 + nt * 8 + g]);
                mma_tf32(D[j], a0, a1, a2, a3, b0, b1);
            }
        }
        const int c0 = m0 + g, c1 = m0 + g + 8;
        const float bia0 = b1[c0], bia1 = b1[c1];
        int j = 0;
        for (int nt = nbeg; nt < nend; nt++, j++)
            #pragma unroll
            for (int dd = 0; dd < 2; dd++) {
                int s = nt * 8 + 2 * tg + dd;
                if (s < 81) {
                    sm[OFF_A1 + c0 * 81 + s] = tfr(D[j][dd]     + bia0);
                    sm[OFF_A1 + c1 * 81 + s] = tfr(D[j][2 + dd] + bia1);
                }
            }
    }
    __syncthreads();

    // ---- phase 2 (mma): P96[96][81] = W96[96][64] @ A1[64][81] ----
    if (w < 6) {
        const int m0 = w * 16;
        float D[11][4];
        #pragma unroll
        for (int nt = 0; nt < 11; nt++) { D[nt][0]=0.f; D[nt][1]=0.f; D[nt][2]=0.f; D[nt][3]=0.f; }
        for (int k0 = 0; k0 < 64; k0 += 8) {
            uint32_t a0 = ldu(&sm[OFF_ATT + (m0 + g)     * 68 + k0 + tg]);
            uint32_t a1 = ldu(&sm[OFF_ATT + (m0 + g + 8) * 68 + k0 + tg]);
            uint32_t a2 = ldu(&sm[OFF_ATT + (m0 + g)     * 68 + k0 + tg + 4]);
            uint32_t a3 = ldu(&sm[OFF_ATT + (m0 + g + 8) * 68 + k0 + tg + 4]);
            #pragma unroll
            for (int nt = 0; nt < 11; nt++) {
                uint32_t b0 = ldu(&sm[OFF_A1 + (k0 + tg)     * 81 + nt * 8 + g]);
                uint32_t b1 = ldu(&sm[OFF_A1 + (k0 + tg + 4) * 81 + nt * 8 + g]);
                mma_tf32(D[nt], a0, a1, a2, a3, b0, b1);
            }
        }
        const int mat = w >> 1;                      // 0=theta 1=phi 2=g
        const float* bias = (mat == 0) ? bt : ((mat == 1) ? bp : bg);
        const int ch0 = (w & 1) * 16 + g, ch1 = ch0 + 8;
        const float bv0 = bias[ch0], bv1 = bias[ch1];
        #pragma unroll
        for (int nt = 0; nt < 11; nt++)
            #pragma unroll
            for (int dd = 0; dd < 2; dd++) {
                int s = nt * 8 + 2 * tg + dd;
                if (s < 81) {
                    float v0 = tfr(D[nt][dd] + bv0);
                    float v1 = tfr(D[nt][2 + dd] + bv1);
                    if (mat == 0)      { sm[OFF_TH + s * 36 + ch0] = v0; sm[OFF_TH + s * 36 + ch1] = v1; }
                    else if (mat == 1) { sm[OFF_PH + ch0 * 81 + s] = v0; sm[OFF_PH + ch1 * 81 + s] = v1; }
                    else               { sm[OFF_G  + s * 36 + ch0] = v0; sm[OFF_G  + s * 36 + ch1] = v1; }
                }
            }
    }
    __syncthreads();

    // ---- phase 3a (mma): logits = theta @ phi, register softmax -> attn[81][84] ----
    if (w < 6) {
        const int m0 = w * 16;
        const int r0 = min(m0 + g, 80), r1 = min(m0 + g + 8, 80);
        float D[11][4];
        #pragma unroll
        for (int nt = 0; nt < 11; nt++) { D[nt][0]=0.f; D[nt][1]=0.f; D[nt][2]=0.f; D[nt][3]=0.f; }
        for (int k0 = 0; k0 < 32; k0 += 8) {
            uint32_t a0 = ldu(&sm[OFF_TH + r0 * 36 + k0 + tg]);
            uint32_t a1 = ldu(&sm[OFF_TH + r1 * 36 + k0 + tg]);
            uint32_t a2 = ldu(&sm[OFF_TH + r0 * 36 + k0 + tg + 4]);
            uint32_t a3 = ldu(&sm[OFF_TH + r1 * 36 + k0 + tg + 4]);
            #pragma unroll
            for (int nt = 0; nt < 11; nt++) {
                uint32_t b0 = ldu(&sm[OFF_PH + (k0 + tg)     * 81 + nt * 8 + g]);
                uint32_t b1 = ldu(&sm[OFF_PH + (k0 + tg + 4) * 81 + nt * 8 + g]);
                mma_tf32(D[nt], a0, a1, a2, a3, b0, b1);
            }
        }
        float mx0 = -1e30f, mx1 = -1e30f;
        #pragma unroll
        for (int nt = 0; nt < 11; nt++)
            #pragma unroll
            for (int dd = 0; dd < 2; dd++) {
                int t = nt * 8 + 2 * tg + dd;
                if (t < 81) { mx0 = fmaxf(mx0, D[nt][dd]); mx1 = fmaxf(mx1, D[nt][2 + dd]); }
            }
        mx0 = fmaxf(mx0, __shfl_xor_sync(0xffffffffu, mx0, 1));
        mx0 = fmaxf(mx0, __shfl_xor_sync(0xffffffffu, mx0, 2));
        mx1 = fmaxf(mx1, __shfl_xor_sync(0xffffffffu, mx1, 1));
        mx1 = fmaxf(mx1, __shfl_xor_sync(0xffffffffu, mx1, 2));
        float s0 = 0.f, s1 = 0.f;
        #pragma unroll
        for (int nt = 0; nt < 11; nt++)
            #pragma unroll
            for (int dd = 0; dd < 2; dd++) {
                int t = nt * 8 + 2 * tg + dd;
                float e0 = (t < 81) ? __expf(D[nt][dd]     - mx0) : 0.f;
                float e1 = (t < 81) ? __expf(D[nt][2 + dd] - mx1) : 0.f;
                D[nt][dd] = e0; D[nt][2 + dd] = e1;
                s0 += e0; s1 += e1;
            }
        s0 += __shfl_xor_sync(0xffffffffu, s0, 1);
        s0 += __shfl_xor_sync(0xffffffffu, s0, 2);
        s1 += __shfl_xor_sync(0xffffffffu, s1, 1);
        s1 += __shfl_xor_sync(0xffffffffu, s1, 2);
        const float inv0 = 1.0f / s0, inv1 = 1.0f / s1;
        const int sr0 = m0 + g, sr1 = m0 + g + 8;
        #pragma unroll
        for (int nt = 0; nt < 11; nt++)
            #pragma unroll
            for (int dd = 0; dd < 2; dd++) {
                int t = nt * 8 + 2 * tg + dd;
                if (t < 84) {
                    if (sr0 < 81) sm[OFF_ATT + sr0 * 84 + t] = (t < 81) ? tfr(D[nt][dd]     * inv0) : 0.f;
                    if (sr1 < 81) sm[OFF_ATT + sr1 * 84 + t] = (t < 81) ? tfr(D[nt][2 + dd] * inv1) : 0.f;
                }
            }
    }
    __syncthreads();

    // ---- phase 3b (mma): Y[81][32] = attn[81][88] @ g[88][32] ; warps 6,7 stage wo ----
    if (w < 6) {
        const int m0 = w * 16;
        const int r0 = min(m0 + g, 80), r1 = min(m0 + g + 8, 80);
        float D[4][4];
        #pragma unroll
        for (int nt = 0; nt < 4; nt++) { D[nt][0]=0.f; D[nt][1]=0.f; D[nt][2]=0.f; D[nt][3]=0.f; }
        for (int k0 = 0; k0 < 88; k0 += 8) {
            uint32_t a0 = ldu(&sm[OFF_ATT + r0 * 84 + k0 + tg]);
            uint32_t a1 = ldu(&sm[OFF_ATT + r1 * 84 + k0 + tg]);
            uint32_t a2 = ldu(&sm[OFF_ATT + r0 * 84 + k0 + tg + 4]);
            uint32_t a3 = ldu(&sm[OFF_ATT + r1 * 84 + k0 + tg + 4]);
            #pragma unroll
            for (int nt = 0; nt < 4; nt++) {
                uint32_t b0 = ldu(&sm[OFF_G + (k0 + tg)     * 36 + nt * 8 + g]);
                uint32_t b1 = ldu(&sm[OFF_G + (k0 + tg + 4) * 36 + nt * 8 + g]);
                mma_tf32(D[nt], a0, a1, a2, a3, b0, b1);
            }
        }
        const int sr0 = m0 + g, sr1 = m0 + g + 8;
        #pragma unroll
        for (int nt = 0; nt < 4; nt++)
            #pragma unroll
            for (int dd = 0; dd < 2; dd++) {
                int i = nt * 8 + 2 * tg + dd;
                if (sr0 < 81) sm[OFF_TH + sr0 * 36 + i] = tfr(D[nt][dd]);
                if (sr1 < 81) sm[OFF_TH + sr1 * 36 + i] = tfr(D[nt][2 + dd]);
            }
    } else {
        for (int i = tid - 192; i < 2048; i += 64) {   // wo[64][32] -> PH, stride 36
            int r = i >> 5, c = i & 31;
            sm[OFF_PH + r * 36 + c] = tfr(wo[i]);
        }
    }
    __syncthreads();

    // ---- phase 3c (mma): Z[64][81] = wo @ Y^T, + bo + residual + lrelu -> A1 ----
    {
        const int mt = w >> 1, m0 = mt * 16;
        const int nbeg = (w & 1) ? 6 : 0, nend = (w & 1) ? 11 : 6;
        float D[6][4];
        #pragma unroll
        for (int j = 0; j < 6; j++) { D[j][0]=0.f; D[j][1]=0.f; D[j][2]=0.f; D[j][3]=0.f; }
        for (int k0 = 0; k0 < 32; k0 += 8) {
            uint32_t a0 = ldu(&sm[OFF_PH + (m0 + g)     * 36 + k0 + tg]);
            uint32_t a1 = ldu(&sm[OFF_PH + (m0 + g + 8) * 36 + k0 + tg]);
            uint32_t a2 = ldu(&sm[OFF_PH + (m0 + g)     * 36 + k0 + tg + 4]);
            uint32_t a3 = ldu(&sm[OFF_PH + (m0 + g + 8) * 36 + k0 + tg + 4]);
            int j = 0;
            for (int nt = nbeg; nt < nend; nt++, j++) {
                uint32_t b0 = ldu(&sm[OFF_TH + (nt * 8 + g) * 36 + k0 + tg]);
                uint32_t b1 = ldu(&sm[OFF_TH + (nt * 8 + g) * 36 + k0 + tg + 4]);
                mma_tf32(D[j], a0, a1, a2, a3, b0, b1);
            }
        }
        const int c0 = m0 + g, c1 = m0 + g + 8;
        const float bo0 = bo[c0], bo1 = bo[c1];
        int j = 0;
        for (int nt = nbeg; nt < nend; nt++, j++)
            #pragma unroll
            for (int dd = 0; dd < 2; dd++) {
                int s = nt * 8 + 2 * tg + dd;
                if (s < 81) {
                    sm[OFF_A1 + c0 * 81 + s] = tfr(lrelu(D[j][dd]     + bo0 + sm[OFF_A1 + c0 * 81 + s]));
                    sm[OFF_A1 + c1 * 81 + s] = tfr(lrelu(D[j][2 + dd] + bo1 + sm[OFF_A1 + c1 * 81 + s]));
                }
            }
    }
    __syncthreads();

    // ---- phase 4 (mma): conv2 = 9 shifted GEMMs, K split by channel across warps ----
    {
        const int c0 = w * 8;
        int rmv[7];
        #pragma unroll
        for (int nt = 0; nt < 7; nt++) {
            int p = nt * 8 + g;
            rmv[nt] = (p < 49) ? (p / 7) * 9 + (p % 7) : 0;
        }
        float D[14][4];
        #pragma unroll
        for (int j = 0; j < 14; j++) { D[j][0]=0.f; D[j][1]=0.f; D[j][2]=0.f; D[j][3]=0.f; }
        for (int tap = 0; tap < 9; tap++) {
            const int off = (tap / 3) * 9 + (tap % 3);
            const float* af = &g_w2f[(tap * 8 + w) * 256];
            uint32_t A[8];
            #pragma unroll
            for (int r = 0; r < 8; r++) A[r] = __float_as_uint(af[r * 32 + lane]);
            #pragma unroll
            for (int nt = 0; nt < 7; nt++) {
                uint32_t b0 = ldu(&sm[OFF_A1 + (c0 + tg)     * 81 + rmv[nt] + off]);
                uint32_t b1 = ldu(&sm[OFF_A1 + (c0 + tg + 4) * 81 + rmv[nt] + off]);
                mma_tf32(D[nt],     A[0], A[1], A[2], A[3], b0, b1);
                mma_tf32(D[7 + nt], A[4], A[5], A[6], A[7], b0, b1);
            }
        }
        __syncthreads();
        float* buf = &sm[OFF_RED + w * 1824];
        #pragma unroll
        for (int mt = 0; mt < 2; mt++)
            #pragma unroll
            for (int nt = 0; nt < 7; nt++)
                #pragma unroll
                for (int dd = 0; dd < 2; dd++) {
                    int o0 = mt * 16 + g, p = nt * 8 + 2 * tg + dd;
                    buf[o0 * 57 + p]       = D[mt * 7 + nt][dd];
                    buf[(o0 + 8) * 57 + p] = D[mt * 7 + nt][2 + dd];
                }
    }
    __syncthreads();
    for (int e = tid; e < 1568; e += NTHREADS) {     // reduce + bias + lrelu -> a3 [32][56]
        int o = e / 49, p = e % 49;
        float s = b2[o];
        #pragma unroll
        for (int ww = 0; ww < 8; ww++) s += sm[OFF_RED + ww * 1824 + o * 57 + p];
        sm[OFF_A3 + o * 56 + p] = lrelu(s);
    }
    __syncthreads();

    // ---- phase 5 (mma): conv3 = 9 shifted GEMMs, taps split across warps ----
    {
        int rmv[4];
        #pragma unroll
        for (int nt = 0; nt < 4; nt++) {
            int n = nt * 8 + g;
            rmv[nt] = (n < 25) ? (n / 5) * 7 + (n % 5) : 0;
        }
        float D[4][4];
        #pragma unroll
        for (int nt = 0; nt < 4; nt++) { D[nt][0]=0.f; D[nt][1]=0.f; D[nt][2]=0.f; D[nt][3]=0.f; }
        for (int t = w; t < 9; t += 8) {
            const int off = (t / 3) * 7 + (t % 3);
            #pragma unroll
            for (int kc = 0; kc < 4; kc++) {
                uint32_t a0 = __float_as_uint(g_w3f[((t * 4 + kc) * 2 + 0) * 32 + lane]);
                uint32_t a2 = __float_as_uint(g_w3f[((t * 4 + kc) * 2 + 1) * 32 + lane]);
                #pragma unroll
                for (int nt = 0; nt < 4; nt++) {
                    uint32_t b0 = ldu(&sm[OFF_A3 + (kc * 8 + tg)     * 56 + rmv[nt] + off]);
                    uint32_t b1 = ldu(&sm[OFF_A3 + (kc * 8 + tg + 4) * 56 + rmv[nt] + off]);
                    mma_tf32(D[nt], a0, 0u, a2, 0u, b0, b1);
                }
            }
        }
        float* buf = &sm[OFF_RED3 + w * 264];
        #pragma unroll
        for (int nt = 0; nt < 4; nt++)
            #pragma unroll
            for (int dd = 0; dd < 2; dd++)
                buf[g * 33 + nt * 8 + 2 * tg + dd] = D[nt][dd];
    }
    __syncthreads();
    if (tid < 200) {     // reduce 8 taps-partials + bias + lrelu -> flat [8][25]
        int o = tid / 25, p = tid % 25;
        float s = b3[o];
        #pragma unroll
        for (int ww = 0; ww < 8; ww++) s += sm[OFF_RED3 + ww * 264 + o * 33 + p];
        sm[OFF_FLAT + o * 25 + p] = lrelu(s);
    }
    __syncthreads();

    // ---- phase 6: MLP 200->64->32->16->8->2 ----
    float* flat = &sm[OFF_FLAT];
    float* scr  = &sm[OFF_FCS];
    float* sc2  = &sm[OFF_FC2S];
    float* f1 = &sm[OFF_F1];
    float* f2 = &sm[OFF_F2];
    float* f3 = &sm[OFF_F3];
    float* f4 = &sm[OFF_F4];

    {   // fc1: 200 -> 64
        int q = tid >> 6, j = tid & 63;
        float acc = 0.f;
        int k0 = q * 50;
        for (int k = 0; k < 50; k++)
            acc += g_fw1T[(k0 + k) * 64 + j] * flat[k0 + k];
        scr[q * 64 + j] = acc;
    }
    __syncthreads();
    if (tid < 64)
        f1[tid] = lrelu(scr[tid] + scr[64 + tid] + scr[128 + tid] + scr[192 + tid] + fb1[tid]);
    __syncthreads();
    if (tid < 128) {  // fc2: 64 -> 32
        int q = tid >> 5, j = tid & 31;
        float acc = 0.f;
        int k0 = q * 16;
        for (int k = 0; k < 16; k++)
            acc += g_fw2T[(k0 + k) * 32 + j] * f1[k0 + k];
        sc2[q * 32 + j] = acc;
    }
    __syncthreads();
    if (tid < 32)
        f2[tid] = lrelu(sc2[tid] + sc2[32 + tid] + sc2[64 + tid] + sc2[96 + tid] + fb2[tid]);
    __syncthreads();
    if (tid < 64) {   // fc3: 32 -> 16
        int j = tid >> 2, q = tid & 3;
        float acc = 0.f;
        const float* wr = &fw3[j * 32 + q * 8];
        for (int k = 0; k < 8; k++) acc += wr[k] * f2[q * 8 + k];
        acc += __shfl_xor_sync(0xffffffffu, acc, 1);
        acc += __shfl_xor_sync(0xffffffffu, acc, 2);
        if (q == 0) f3[j] = lrelu(acc + fb3[j]);
    }
    __syncthreads();
    if (tid < 32) {   // fc4: 16 -> 8
        int j = tid >> 2, q = tid & 3;
        float acc = 0.f;
        const float* wr = &fw4[j * 16 + q * 4];
        for (int k = 0; k < 4; k++) acc += wr[k] * f3[q * 4 + k];
        acc += __shfl_xor_sync(0xffffffffu, acc, 1);
        acc += __shfl_xor_sync(0xffffffffu, acc, 2);
        if (q == 0) f4[j] = lrelu(acc + fb4[j]);
    }
    __syncthreads();
    if (tid < 2) {    // fco: 8 -> 2
        float acc = fbo[tid];
        const float* wr = &fwo[tid * 8];
        #pragma unroll
        for (int k = 0; k < 8; k++) acc += wr[k] * f4[k];
        out[b * 2 + tid] = acc;
    }
}

extern "C" void kernel_launch(void* const* d_in, const int* in_sizes, int n_in,
                              void* d_out, int out_size) {
    const float* x   = (const float*)d_in[0];
    const float* w1  = (const float*)d_in[1];
    const float* b1  = (const float*)d_in[2];
    const float* wt  = (const float*)d_in[3];
    const float* bt  = (const float*)d_in[4];
    const float* wp  = (const float*)d_in[5];
    const float* bp  = (const float*)d_in[6];
    const float* wg  = (const float*)d_in[7];
    const float* bg  = (const float*)d_in[8];
    const float* wo  = (const float*)d_in[9];
    const float* bo  = (const float*)d_in[10];
    const float* w2  = (const float*)d_in[11];
    const float* b2  = (const float*)d_in[12];
    const float* w3  = (const float*)d_in[13];
    const float* b3  = (const float*)d_in[14];
    const float* fw1 = (const float*)d_in[15];
    const float* fb1 = (const float*)d_in[16];
    const float* fw2 = (const float*)d_in[17];
    const float* fb2 = (const float*)d_in[18];
    const float* fw3 = (const float*)d_in[19];
    const float* fb3 = (const float*)d_in[20];
    const float* fw4 = (const float*)d_in[21];
    const float* fb4 = (const float*)d_in[22];
    const float* fwo = (const float*)d_in[23];
    const float* fbo = (const float*)d_in[24];
    float* out = (float*)d_out;

    int B = in_sizes[0] / 121;

    prep_kernel<<<(PREP_TOTAL + 255) / 256, 256>>>(w2, w3, fw1, fw2);

    cudaFuncSetAttribute(braggnn_kernel,
                         cudaFuncAttributeMaxDynamicSharedMemorySize, SMEM_BYTES);
    braggnn_kernel<<<B, NTHREADS, SMEM_BYTES>>>(
        x, w1, b1, wt, bt, wp, bp, wg, bg, wo, bo, b2, b3,
        fb1, fb2, fw3, fb3, fw4, fb4, fwo, fbo, out);
}

// round 8
// speedup vs baseline: 5.5463x; 1.0618x over previous
#include <cuda_runtime.h>
#include <cstdint>

#define NTHREADS 256

__device__ __forceinline__ float lrelu(float v) { return fmaxf(v, 0.01f * v); }

__device__ __forceinline__ uint32_t f2tf(float f) {
    uint32_t r;
    asm("cvt.rna.tf32.f32 %0, %1;" : "=r"(r) : "f"(f));
    return r;
}
__device__ __forceinline__ float tfr(float f) {      // round-to-tf32, keep as float
    return __uint_as_float(f2tf(f));
}
__device__ __forceinline__ uint32_t ldu(const float* p) { return __float_as_uint(*p); }

__device__ __forceinline__ void mma_tf32(float* d,
                                         uint32_t a0, uint32_t a1, uint32_t a2, uint32_t a3,
                                         uint32_t b0, uint32_t b1) {
    asm volatile("mma.sync.aligned.m16n8k8.row.col.f32.tf32.tf32.f32 "
                 "{%0,%1,%2,%3},{%4,%5,%6,%7},{%8,%9},{%0,%1,%2,%3};"
                 : "+f"(d[0]), "+f"(d[1]), "+f"(d[2]), "+f"(d[3])
                 : "r"(a0), "r"(a1), "r"(a2), "r"(a3), "r"(b0), "r"(b1));
}

// ---- shared memory layout (float offsets) ----
// low region (reused over time):
#define OFF_XS    0        // 121 image (phase 1 only)
#define OFF_P     128      // 16*88 = 1408 im2col patches (phase 1 only)
#define OFF_W1S   1536     // 64*20 = 1280 staged conv1 weights (phase 1 only)
#define OFF_A3    0        // 32*56 = 1792 conv2 out (from conv2-reduce on)
#define OFF_FLAT  1792     // 200
#define OFF_FCS   1992     // 256 fc1 scratch
#define OFF_F1    2248     // 64
#define OFF_F2    2312     // 32
#define OFF_F3    2344     // 16
#define OFF_F4    2360     // 8
#define OFF_FC2S  2368     // 128 fc2 scratch
// high region (bank-tiled strides: A1/PH 88, G 40, TH 36, ATT 84):
#define OFF_A1    2880     // 64*88 = 5632 -> ends 8512
#define OFF_TH    8512     // 81*36 = 2916 -> ends 11428 (theta -> Y)
#define OFF_PH    11428    // 32*88 = 2816 -> ends 14244 (phi -> staged wo [64][36])
#define OFF_G     14244    // 88*40 = 3520 -> ends 17764 (rows 81..87 zero)
#define OFF_ATT   17764    // 6808 -> ends 24572 (staged W96 [96][68] -> attn [81][84]+pad)
#define OFF_RED   8512     // conv2 reduction: 8 x 1824 -> ends 23104 (TH..ATT dead)
#define OFF_RED3  8512     // conv3 reduction: 8 x 264
#define SMEM_FLOATS 24572
#define SMEM_BYTES  (SMEM_FLOATS * 4)

// ---- prepacked weights (device scratch, filled by prep kernel) ----
__device__ __align__(16) float g_w2f[9 * 8 * 8 * 32];  // conv2 frag-order, tf32
__device__ __align__(16) float g_w3f[9 * 4 * 2 * 32];  // conv3 frag-order, tf32
__device__ __align__(16) float g_fw1T[200 * 64];       // [k][j]
__device__ __align__(16) float g_fw2T[64 * 32];        // [k][j]

#define N_W2F (9 * 8 * 8 * 32)
#define N_W3F (9 * 4 * 2 * 32)
#define N_F1T (200 * 64)
#define N_F2T (64 * 32)
#define PREP_TOTAL (N_W2F + N_W3F + N_F1T + N_F2T)

__global__ void prep_kernel(const float* __restrict__ w2, const float* __restrict__ w3,
                            const float* __restrict__ fw1, const float* __restrict__ fw2) {
    int i = blockIdx.x * blockDim.x + threadIdx.x;
    if (i < N_W2F) {
        // layout: (((tap*8 + wblk)*8 + r)*32 + lane), r = mt*4 + ai
        int lane = i & 31;
        int r    = (i >> 5) & 7;
        int wblk = (i >> 8) & 7;
        int tap  = i >> 11;
        int g  = lane >> 2, tg = lane & 3;
        int mt = r >> 2,    ai = r & 3;
        int o = mt * 16 + g + 8 * (ai & 1);
        int c = wblk * 8 + tg + 4 * (ai >> 1);
        g_w2f[i] = tfr(w2[o * 576 + c * 9 + tap]);
        return;
    }
    i -= N_W2F;
    if (i < N_W3F) {
        // layout: (((tap*4 + kc)*2 + ai)*32 + lane); row o = lane>>2, k = kc*8 + (lane&3) + 4*ai
        int lane = i & 31;
        int ai   = (i >> 5) & 1;
        int kc   = (i >> 6) & 3;
        int tap  = i >> 8;
        int o = lane >> 2, tg = lane & 3;
        int c = kc * 8 + tg + 4 * ai;
        g_w3f[i] = tfr(w3[o * 288 + c * 9 + tap]);
        return;
    }
    i -= N_W3F;
    if (i < N_F1T) {
        int kk = i / 64, jj = i % 64;
        g_fw1T[i] = fw1[jj * 200 + kk];
        return;
    }
    i -= N_F1T;
    if (i < N_F2T) {
        int kk = i / 32, jj = i % 32;
        g_fw2T[i] = fw2[jj * 64 + kk];
    }
}

__global__ void __launch_bounds__(NTHREADS, 2) braggnn_kernel(
    const float* __restrict__ x,
    const float* __restrict__ w1, const float* __restrict__ b1,
    const float* __restrict__ wt, const float* __restrict__ bt,
    const float* __restrict__ wp, const float* __restrict__ bp,
    const float* __restrict__ wg, const float* __restrict__ bg,
    const float* __restrict__ wo, const float* __restrict__ bo,
    const float* __restrict__ b2, const float* __restrict__ b3,
    const float* __restrict__ fb1, const float* __restrict__ fb2,
    const float* __restrict__ fw3, const float* __restrict__ fb3,
    const float* __restrict__ fw4, const float* __restrict__ fb4,
    const float* __restrict__ fwo, const float* __restrict__ fbo,
    float* __restrict__ out)
{
    extern __shared__ float sm[];
    const int b    = blockIdx.x;
    const int tid  = threadIdx.x;
    const int w    = tid >> 5;
    const int lane = tid & 31;
    const int g    = lane >> 2;   // mma groupID
    const int tg   = lane & 3;    // mma threadID-in-group

    // ---- preload / staging / zero-fill ----
    for (int i = tid; i < 121; i += NTHREADS) sm[OFF_XS + i] = x[b * 121 + i];
    for (int i = tid; i < 6144; i += NTHREADS) {       // W96 [96][68] into ATT region
        int r = i >> 6, c = i & 63;
        const float* src = (r < 32) ? wt : ((r < 64) ? wp : wg);
        sm[OFF_ATT + r * 68 + c] = tfr(src[(r & 31) * 64 + c]);
    }
    for (int i = tid; i < 1280; i += NTHREADS) {       // W1 staged [64][20]
        int o = i / 20, k = i % 20;
        sm[OFF_W1S + i] = (k < 9) ? tfr(w1[o * 9 + k]) : 0.f;
    }
    for (int i = tid; i < 1408; i += NTHREADS) sm[OFF_P + i] = 0.f;   // patches zero
    for (int i = tid; i < 7 * 40; i += NTHREADS) sm[OFF_G + 81 * 40 + i] = 0.f;
    if (tid < 4) sm[OFF_ATT + 81 * 84 + tid] = 0.f;    // attn tail pad
    __syncthreads();

    // ---- im2col patches P[16][88]: rows = taps, cols = output pos ----
    for (int i = tid; i < 729; i += NTHREADS) {
        int tap = i / 81, s = i - tap * 81;
        int iy = s / 9 + tap / 3, ix = s % 9 + tap % 3;
        sm[OFF_P + tap * 88 + s] = tfr(sm[OFF_XS + iy * 11 + ix]);
    }
    __syncthreads();

    // ---- phase 1 (mma): A1[64][81] = W1[64][16] @ P[16][81] ----
    {
        const int m0 = (w >> 1) * 16;
        const int nbeg = (w & 1) ? 6 : 0, nend = (w & 1) ? 11 : 6;
        float D[6][4];
        #pragma unroll
        for (int j = 0; j < 6; j++) { D[j][0]=0.f; D[j][1]=0.f; D[j][2]=0.f; D[j][3]=0.f; }
        #pragma unroll
        for (int kc = 0; kc < 2; kc++) {
            const int k0 = kc * 8;
            uint32_t a0 = ldu(&sm[OFF_W1S + (m0 + g)     * 20 + k0 + tg]);
            uint32_t a1 = ldu(&sm[OFF_W1S + (m0 + g + 8) * 20 + k0 + tg]);
            uint32_t a2 = ldu(&sm[OFF_W1S + (m0 + g)     * 20 + k0 + tg + 4]);
            uint32_t a3 = ldu(&sm[OFF_W1S + (m0 + g + 8) * 20 + k0 + tg + 4]);
            int j = 0;
            for (int nt = nbeg; nt < nend; nt++, j++) {
                uint32_t b0 = ldu(&sm[OFF_P + (k0 + tg)     * 88 + nt * 8 + g]);
                uint32_t b1 = ldu(&sm[OFF_P + (k0 + tg + 4) * 88 + nt * 8 + g]);
                mma_tf32(D[j], a0, a1, a2, a3, b0, b1);
            }
        }
        const int c0 = m0 + g, c1 = m0 + g + 8;
        const float bia0 = b1[c0], bia1 = b1[c1];
        int j = 0;
        for (int nt = nbeg; nt < nend; nt++, j++)
            #pragma unroll
            for (int dd = 0; dd < 2; dd++) {
                int s = nt * 8 + 2 * tg + dd;
                if (s < 81) {
                    sm[OFF_A1 + c0 * 88 + s] = tfr(D[j][dd]     + bia0);
                    sm[OFF_A1 + c1 * 88 + s] = tfr(D[j][2 + dd] + bia1);
                }
            }
    }
    __syncthreads();

    // ---- phase 2 (mma): P96[96][81] = W96[96][64] @ A1[64][81] ----
    if (w < 6) {
        const int m0 = w * 16;
        float D[11][4];
        #pragma unroll
        for (int nt = 0; nt < 11; nt++) { D[nt][0]=0.f; D[nt][1]=0.f; D[nt][2]=0.f; D[nt][3]=0.f; }
        for (int k0 = 0; k0 < 64; k0 += 8) {
            uint32_t a0 = ldu(&sm[OFF_ATT + (m0 + g)     * 68 + k0 + tg]);
            uint32_t a1 = ldu(&sm[OFF_ATT + (m0 + g + 8) * 68 + k0 + tg]);
            uint32_t a2 = ldu(&sm[OFF_ATT + (m0 + g)     * 68 + k0 + tg + 4]);
            uint32_t a3 = ldu(&sm[OFF_ATT + (m0 + g + 8) * 68 + k0 + tg + 4]);
            #pragma unroll
            for (int nt = 0; nt < 11; nt++) {
                uint32_t b0 = ldu(&sm[OFF_A1 + (k0 + tg)     * 88 + nt * 8 + g]);
                uint32_t b1 = ldu(&sm[OFF_A1 + (k0 + tg + 4) * 88 + nt * 8 + g]);
                mma_tf32(D[nt], a0, a1, a2, a3, b0, b1);
            }
        }
        const int mat = w >> 1;                      // 0=theta 1=phi 2=g
        const float* bias = (mat == 0) ? bt : ((mat == 1) ? bp : bg);
        const int ch0 = (w & 1) * 16 + g, ch1 = ch0 + 8;
        const float bv0 = bias[ch0], bv1 = bias[ch1];
        #pragma unroll
        for (int nt = 0; nt < 11; nt++)
            #pragma unroll
            for (int dd = 0; dd < 2; dd++) {
                int s = nt * 8 + 2 * tg + dd;
                if (s < 81) {
                    float v0 = tfr(D[nt][dd] + bv0);
                    float v1 = tfr(D[nt][2 + dd] + bv1);
                    if (mat == 0)      { sm[OFF_TH + s * 36 + ch0] = v0; sm[OFF_TH + s * 36 + ch1] = v1; }
                    else if (mat == 1) { sm[OFF_PH + ch0 * 88 + s] = v0; sm[OFF_PH + ch1 * 88 + s] = v1; }
                    else               { sm[OFF_G  + s * 40 + ch0] = v0; sm[OFF_G  + s * 40 + ch1] = v1; }
                }
            }
    }
    __syncthreads();

    // ---- phase 3a (mma): logits = theta @ phi, register softmax -> attn[81][84] ----
    if (w < 6) {
        const int m0 = w * 16;
        const int r0 = min(m0 + g, 80), r1 = min(m0 + g + 8, 80);
        float D[11][4];
        #pragma unroll
        for (int nt = 0; nt < 11; nt++) { D[nt][0]=0.f; D[nt][1]=0.f; D[nt][2]=0.f; D[nt][3]=0.f; }
        for (int k0 = 0; k0 < 32; k0 += 8) {
            uint32_t a0 = ldu(&sm[OFF_TH + r0 * 36 + k0 + tg]);
            uint32_t a1 = ldu(&sm[OFF_TH + r1 * 36 + k0 + tg]);
            uint32_t a2 = ldu(&sm[OFF_TH + r0 * 36 + k0 + tg + 4]);
            uint32_t a3 = ldu(&sm[OFF_TH + r1 * 36 + k0 + tg + 4]);
            #pragma unroll
            for (int nt = 0; nt < 11; nt++) {
                uint32_t b0 = ldu(&sm[OFF_PH + (k0 + tg)     * 88 + nt * 8 + g]);
                uint32_t b1 = ldu(&sm[OFF_PH + (k0 + tg + 4) * 88 + nt * 8 + g]);
                mma_tf32(D[nt], a0, a1, a2, a3, b0, b1);
            }
        }
        float mx0 = -1e30f, mx1 = -1e30f;
        #pragma unroll
        for (int nt = 0; nt < 11; nt++)
            #pragma unroll
            for (int dd = 0; dd < 2; dd++) {
                int t = nt * 8 + 2 * tg + dd;
                if (t < 81) { mx0 = fmaxf(mx0, D[nt][dd]); mx1 = fmaxf(mx1, D[nt][2 + dd]); }
            }
        mx0 = fmaxf(mx0, __shfl_xor_sync(0xffffffffu, mx0, 1));
        mx0 = fmaxf(mx0, __shfl_xor_sync(0xffffffffu, mx0, 2));
        mx1 = fmaxf(mx1, __shfl_xor_sync(0xffffffffu, mx1, 1));
        mx1 = fmaxf(mx1, __shfl_xor_sync(0xffffffffu, mx1, 2));
        float s0 = 0.f, s1 = 0.f;
        #pragma unroll
        for (int nt = 0; nt < 11; nt++)
            #pragma unroll
            for (int dd = 0; dd < 2; dd++) {
                int t = nt * 8 + 2 * tg + dd;
                float e0 = (t < 81) ? __expf(D[nt][dd]     - mx0) : 0.f;
                float e1 = (t < 81) ? __expf(D[nt][2 + dd] - mx1) : 0.f;
                D[nt][dd] = e0; D[nt][2 + dd] = e1;
                s0 += e0; s1 += e1;
            }
        s0 += __shfl_xor_sync(0xffffffffu, s0, 1);
        s0 += __shfl_xor_sync(0xffffffffu, s0, 2);
        s1 += __shfl_xor_sync(0xffffffffu, s1, 1);
        s1 += __shfl_xor_sync(0xffffffffu, s1, 2);
        const float inv0 = 1.0f / s0, inv1 = 1.0f / s1;
        const int sr0 = m0 + g, sr1 = m0 + g + 8;
        #pragma unroll
        for (int nt = 0; nt < 11; nt++)
            #pragma unroll
            for (int dd = 0; dd < 2; dd++) {
                int t = nt * 8 + 2 * tg + dd;
                if (t < 84) {
                    if (sr0 < 81) sm[OFF_ATT + sr0 * 84 + t] = (t < 81) ? tfr(D[nt][dd]     * inv0) : 0.f;
                    if (sr1 < 81) sm[OFF_ATT + sr1 * 84 + t] = (t < 81) ? tfr(D[nt][2 + dd] * inv1) : 0.f;
                }
            }
    }
    __syncthreads();

    // ---- phase 3b (mma): Y[81][32] = attn[81][88] @ g[88][32] ; warps 6,7 stage wo ----
    if (w < 6) {
        const int m0 = w * 16;
        const int r0 = min(m0 + g, 80), r1 = min(m0 + g + 8, 80);
        float D[4][4];
        #pragma unroll
        for (int nt = 0; nt < 4; nt++) { D[nt][0]=0.f; D[nt][1]=0.f; D[nt][2]=0.f; D[nt][3]=0.f; }
        for (int k0 = 0; k0 < 88; k0 += 8) {
            uint32_t a0 = ldu(&sm[OFF_ATT + r0 * 84 + k0 + tg]);
            uint32_t a1 = ldu(&sm[OFF_ATT + r1 * 84 + k0 + tg]);
            uint32_t a2 = ldu(&sm[OFF_ATT + r0 * 84 + k0 + tg + 4]);
            uint32_t a3 = ldu(&sm[OFF_ATT + r1 * 84 + k0 + tg + 4]);
            #pragma unroll
            for (int nt = 0; nt < 4; nt++) {
                uint32_t b0 = ldu(&sm[OFF_G + (k0 + tg)     * 40 + nt * 8 + g]);
                uint32_t b1 = ldu(&sm[OFF_G + (k0 + tg + 4) * 40 + nt * 8 + g]);
                mma_tf32(D[nt], a0, a1, a2, a3, b0, b1);
            }
        }
        const int sr0 = m0 + g, sr1 = m0 + g + 8;
        #pragma unroll
        for (int nt = 0; nt < 4; nt++)
            #pragma unroll
            for (int dd = 0; dd < 2; dd++) {
                int i = nt * 8 + 2 * tg + dd;
                if (sr0 < 81) sm[OFF_TH + sr0 * 36 + i] = tfr(D[nt][dd]);
                if (sr1 < 81) sm[OFF_TH + sr1 * 36 + i] = tfr(D[nt][2 + dd]);
            }
    } else {
        for (int i = tid - 192; i < 2048; i += 64) {   // wo[64][32] -> PH, stride 36
            int r = i >> 5, c = i & 31;
            sm[OFF_PH + r * 36 + c] = tfr(wo[i]);
        }
    }
    __syncthreads();

    // ---- phase 3c (mma): Z[64][81] = wo @ Y^T, + bo + residual + lrelu -> A1 ----
    {
        const int mt = w >> 1, m0 = mt * 16;
        const int nbeg = (w & 1) ? 6 : 0, nend = (w & 1) ? 11 : 6;
        float D[6][4];
        #pragma unroll
        for (int j = 0; j < 6; j++) { D[j][0]=0.f; D[j][1]=0.f; D[j][2]=0.f; D[j][3]=0.f; }
        for (int k0 = 0; k0 < 32; k0 += 8) {
            uint32_t a0 = ldu(&sm[OFF_PH + (m0 + g)     * 36 + k0 + tg]);
            uint32_t a1 = ldu(&sm[OFF_PH + (m0 + g + 8) * 36 + k0 + tg]);
            uint32_t a2 = ldu(&sm[OFF_PH + (m0 + g)     * 36 + k0 + tg + 4]);
            uint32_t a3 = ldu(&sm[OFF_PH + (m0 + g + 8) * 36 + k0 + tg + 4]);
            int j = 0;
            for (int nt = nbeg; nt < nend; nt++, j++) {
                uint32_t b0 = ldu(&sm[OFF_TH + (nt * 8 + g) * 36 + k0 + tg]);
                uint32_t b1 = ldu(&sm[OFF_TH + (nt * 8 + g) * 36 + k0 + tg + 4]);
                mma_tf32(D[j], a0, a1, a2, a3, b0, b1);
            }
        }
        const int c0 = m0 + g, c1 = m0 + g + 8;
        const float bo0 = bo[c0], bo1 = bo[c1];
        int j = 0;
        for (int nt = nbeg; nt < nend; nt++, j++)
            #pragma unroll
            for (int dd = 0; dd < 2; dd++) {
                int s = nt * 8 + 2 * tg + dd;
                if (s < 81) {
                    sm[OFF_A1 + c0 * 88 + s] = tfr(lrelu(D[j][dd]     + bo0 + sm[OFF_A1 + c0 * 88 + s]));
                    sm[OFF_A1 + c1 * 88 + s] = tfr(lrelu(D[j][2 + dd] + bo1 + sm[OFF_A1 + c1 * 88 + s]));
                }
            }
    }
    __syncthreads();

    // ---- phase 4 (mma): conv2 = 9 shifted GEMMs, K split by channel across warps ----
    {
        const int c0 = w * 8;
        int rmv[7];
        #pragma unroll
        for (int nt = 0; nt < 7; nt++) {
            int p = nt * 8 + g;
            rmv[nt] = (p < 49) ? (p / 7) * 9 + (p % 7) : 0;
        }
        float D[14][4];
        #pragma unroll
        for (int j = 0; j < 14; j++) { D[j][0]=0.f; D[j][1]=0.f; D[j][2]=0.f; D[j][3]=0.f; }
        for (int tap = 0; tap < 9; tap++) {
            const int off = (tap / 3) * 9 + (tap % 3);
            const float* af = &g_w2f[(tap * 8 + w) * 256];
            uint32_t A[8];
            #pragma unroll
            for (int r = 0; r < 8; r++) A[r] = __float_as_uint(af[r * 32 + lane]);
            #pragma unroll
            for (int nt = 0; nt < 7; nt++) {
                uint32_t b0 = ldu(&sm[OFF_A1 + (c0 + tg)     * 88 + rmv[nt] + off]);
                uint32_t b1 = ldu(&sm[OFF_A1 + (c0 + tg + 4) * 88 + rmv[nt] + off]);
                mma_tf32(D[nt],     A[0], A[1], A[2], A[3], b0, b1);
                mma_tf32(D[7 + nt], A[4], A[5], A[6], A[7], b0, b1);
            }
        }
        __syncthreads();
        float* buf = &sm[OFF_RED + w * 1824];
        #pragma unroll
        for (int mt = 0; mt < 2; mt++)
            #pragma unroll
            for (int nt = 0; nt < 7; nt++)
                #pragma unroll
                for (int dd = 0; dd < 2; dd++) {
                    int o0 = mt * 16 + g, p = nt * 8 + 2 * tg + dd;
                    buf[o0 * 57 + p]       = D[mt * 7 + nt][dd];
                    buf[(o0 + 8) * 57 + p] = D[mt * 7 + nt][2 + dd];
                }
    }
    __syncthreads();
    for (int e = tid; e < 1568; e += NTHREADS) {     // reduce + bias + lrelu -> a3 [32][56]
        int o = e / 49, p = e % 49;
        float s = b2[o];
        #pragma unroll
        for (int ww = 0; ww < 8; ww++) s += sm[OFF_RED + ww * 1824 + o * 57 + p];
        sm[OFF_A3 + o * 56 + p] = lrelu(s);
    }
    __syncthreads();

    // ---- phase 5 (mma): conv3 = 9 shifted GEMMs, taps split across warps ----
    {
        int rmv[4];
        #pragma unroll
        for (int nt = 0; nt < 4; nt++) {
            int n = nt * 8 + g;
            rmv[nt] = (n < 25) ? (n / 5) * 7 + (n % 5) : 0;
        }
        float D[4][4];
        #pragma unroll
        for (int nt = 0; nt < 4; nt++) { D[nt][0]=0.f; D[nt][1]=0.f; D[nt][2]=0.f; D[nt][3]=0.f; }
        for (int t = w; t < 9; t += 8) {
            const int off = (t / 3) * 7 + (t % 3);
            #pragma unroll
            for (int kc = 0; kc < 4; kc++) {
                uint32_t a0 = __float_as_uint(g_w3f[((t * 4 + kc) * 2 + 0) * 32 + lane]);
                uint32_t a2 = __float_as_uint(g_w3f[((t * 4 + kc) * 2 + 1) * 32 + lane]);
                #pragma unroll
                for (int nt = 0; nt < 4; nt++) {
                    uint32_t b0 = ldu(&sm[OFF_A3 + (kc * 8 + tg)     * 56 + rmv[nt] + off]);
                    uint32_t b1 = ldu(&sm[OFF_A3 + (kc * 8 + tg + 4) * 56 + rmv[nt] + off]);
                    mma_tf32(D[nt], a0, 0u, a2, 0u, b0, b1);
                }
            }
        }
        float* buf = &sm[OFF_RED3 + w * 264];
        #pragma unroll
        for (int nt = 0; nt < 4; nt++)
            #pragma unroll
            for (int dd = 0; dd < 2; dd++)
                buf[g * 33 + nt * 8 + 2 * tg + dd] = D[nt][dd];
    }
    __syncthreads();
    if (tid < 200) {     // reduce 8 taps-partials + bias + lrelu -> flat [8][25]
        int o = tid / 25, p = tid % 25;
        float s = b3[o];
        #pragma unroll
        for (int ww = 0; ww < 8; ww++) s += sm[OFF_RED3 + ww * 264 + o * 33 + p];
        sm[OFF_FLAT + o * 25 + p] = lrelu(s);
    }
    __syncthreads();

    // ---- phase 6: MLP 200->64->32->16->8->2 ----
    float* flat = &sm[OFF_FLAT];
    float* scr  = &sm[OFF_FCS];
    float* sc2  = &sm[OFF_FC2S];
    float* f1 = &sm[OFF_F1];
    float* f2 = &sm[OFF_F2];
    float* f3 = &sm[OFF_F3];
    float* f4 = &sm[OFF_F4];

    {   // fc1: 200 -> 64
        int q = tid >> 6, j = tid & 63;
        float acc = 0.f;
        int k0 = q * 50;
        for (int k = 0; k < 50; k++)
            acc += g_fw1T[(k0 + k) * 64 + j] * flat[k0 + k];
        scr[q * 64 + j] = acc;
    }
    __syncthreads();
    if (tid < 64)
        f1[tid] = lrelu(scr[tid] + scr[64 + tid] + scr[128 + tid] + scr[192 + tid] + fb1[tid]);
    __syncthreads();
    if (tid < 128) {  // fc2: 64 -> 32
        int q = tid >> 5, j = tid & 31;
        float acc = 0.f;
        int k0 = q * 16;
        for (int k = 0; k < 16; k++)
            acc += g_fw2T[(k0 + k) * 32 + j] * f1[k0 + k];
        sc2[q * 32 + j] = acc;
    }
    __syncthreads();
    if (tid < 32)
        f2[tid] = lrelu(sc2[tid] + sc2[32 + tid] + sc2[64 + tid] + sc2[96 + tid] + fb2[tid]);
    __syncthreads();
    if (tid < 64) {   // fc3: 32 -> 16
        int j = tid >> 2, q = tid & 3;
        float acc = 0.f;
        const float* wr = &fw3[j * 32 + q * 8];
        for (int k = 0; k < 8; k++) acc += wr[k] * f2[q * 8 + k];
        acc += __shfl_xor_sync(0xffffffffu, acc, 1);
        acc += __shfl_xor_sync(0xffffffffu, acc, 2);
        if (q == 0) f3[j] = lrelu(acc + fb3[j]);
    }
    __syncthreads();
    if (tid < 32) {   // fc4: 16 -> 8
        int j = tid >> 2, q = tid & 3;
        float acc = 0.f;
        const float* wr = &fw4[j * 16 + q * 4];
        for (int k = 0; k < 4; k++) acc += wr[k] * f3[q * 4 + k];
        acc += __shfl_xor_sync(0xffffffffu, acc, 1);
        acc += __shfl_xor_sync(0xffffffffu, acc, 2);
        if (q == 0) f4[j] = lrelu(acc + fb4[j]);
    }
    __syncthreads();
    if (tid < 2) {    // fco: 8 -> 2
        float acc = fbo[tid];
        const float* wr = &fwo[tid * 8];
        #pragma unroll
        for (int k = 0; k < 8; k++) acc += wr[k] * f4[k];
        out[b * 2 + tid] = acc;
    }
}

extern "C" void kernel_launch(void* const* d_in, const int* in_sizes, int n_in,
                              void* d_out, int out_size) {
    const float* x   = (const float*)d_in[0];
    const float* w1  = (const float*)d_in[1];
    const float* b1  = (const float*)d_in[2];
    const float* wt  = (const float*)d_in[3];
    const float* bt  = (const float*)d_in[4];
    const float* wp  = (const float*)d_in[5];
    const float* bp  = (const float*)d_in[6];
    const float* wg  = (const float*)d_in[7];
    const float* bg  = (const float*)d_in[8];
    const float* wo  = (const float*)d_in[9];
    const float* bo  = (const float*)d_in[10];
    const float* w2  = (const float*)d_in[11];
    const float* b2  = (const float*)d_in[12];
    const float* w3  = (const float*)d_in[13];
    const float* b3  = (const float*)d_in[14];
    const float* fw1 = (const float*)d_in[15];
    const float* fb1 = (const float*)d_in[16];
    const float* fw2 = (const float*)d_in[17];
    const float* fb2 = (const float*)d_in[18];
    const float* fw3 = (const float*)d_in[19];
    const float* fb3 = (const float*)d_in[20];
    const float* fw4 = (const float*)d_in[21];
    const float* fb4 = (const float*)d_in[22];
    const float* fwo = (const float*)d_in[23];
    const float* fbo = (const float*)d_in[24];
    float* out = (float*)d_out;

    int B = in_sizes[0] / 121;

    prep_kernel<<<(PREP_TOTAL + 255) / 256, 256>>>(w2, w3, fw1, fw2);

    cudaFuncSetAttribute(braggnn_kernel,
                         cudaFuncAttributeMaxDynamicSharedMemorySize, SMEM_BYTES);
    braggnn_kernel<<<B, NTHREADS, SMEM_BYTES>>>(
        x, w1, b1, wt, bt, wp, bp, wg, bg, wo, bo, b2, b3,
        fb1, fb2, fw3, fb3, fw4, fb4, fwo, fbo, out);
}

// round 9
// speedup vs baseline: 6.3248x; 1.1404x over previous
#include <cuda_runtime.h>
#include <cstdint>

#define NTHREADS 256

__device__ __forceinline__ float lrelu(float v) { return fmaxf(v, 0.01f * v); }

__device__ __forceinline__ uint32_t f2tf(float f) {
    uint32_t r;
    asm("cvt.rna.tf32.f32 %0, %1;" : "=r"(r) : "f"(f));
    return r;
}
__device__ __forceinline__ float tfr(float f) {
    return __uint_as_float(f2tf(f));
}
__device__ __forceinline__ uint32_t ldu(const float* p) { return __float_as_uint(*p); }

__device__ __forceinline__ void mma_tf32(float* d,
                                         uint32_t a0, uint32_t a1, uint32_t a2, uint32_t a3,
                                         uint32_t b0, uint32_t b1) {
    asm volatile("mma.sync.aligned.m16n8k8.row.col.f32.tf32.tf32.f32 "
                 "{%0,%1,%2,%3},{%4,%5,%6,%7},{%8,%9},{%0,%1,%2,%3};"
                 : "+f"(d[0]), "+f"(d[1]), "+f"(d[2]), "+f"(d[3])
                 : "r"(a0), "r"(a1), "r"(a2), "r"(a3), "r"(b0), "r"(b1));
}

// ---- shared memory layout (float offsets) ----
// region0 (reused): phase-1 scratch -> A3/FLAT/FC
#define OFF_XS    0        // 121
#define OFF_P     128      // 16*88 = 1408
#define OFF_W1S   1536     // 64*20 = 1280 -> 2816
#define OFF_A3    0        // 32*56 = 1792
#define OFF_FLAT  1792     // 200
#define OFF_FCS   1992     // 256
#define OFF_F1    2248
#define OFF_F2    2312
#define OFF_F3    2344
#define OFF_F4    2360
#define OFF_FC2S  2368     // -> 2496
// high region:
#define OFF_A1    2880     // [64][88] = 5632 -> 8512
#define OFF_TH    8512     // [81][36] = 2916 -> 11428 (theta -> Y)
#define OFF_PH    11428    // [32][88] = 2816 -> 14244 (phi)
#define OFF_G     14244    // [88][40] = 3520 -> 17764 (rows 81..87 zero)
#define OFF_RED   8512     // conv2: 4 bufs x 1824 = 7296 (TH..G dead)
#define OFF_RED3  8512     // conv3: 8 x 264
#define SMEM_FLOATS 17764
#define SMEM_BYTES  (SMEM_FLOATS * 4)

// ---- prepacked weights (device scratch) ----
__device__ __align__(16) float g_w2f[9 * 8 * 8 * 32];   // conv2 frag-order
__device__ __align__(16) float g_w3f[9 * 4 * 2 * 32];   // conv3 frag-order
__device__ __align__(16) float g_fw1T[200 * 64];
__device__ __align__(16) float g_fw2T[64 * 32];
__device__ __align__(16) float g_w96f[6 * 8 * 4 * 32];  // phase-2 A frags (wt|wp|wg)
__device__ __align__(16) float g_wof[4 * 4 * 4 * 32];   // phase-3c A frags (wo)

#define N_W2F  (9 * 8 * 8 * 32)
#define N_W3F  (9 * 4 * 2 * 32)
#define N_F1T  (200 * 64)
#define N_F2T  (64 * 32)
#define N_W96F (6 * 8 * 4 * 32)
#define N_WOF  (4 * 4 * 4 * 32)
#define PREP_TOTAL (N_W2F + N_W3F + N_F1T + N_F2T + N_W96F + N_WOF)

__global__ void prep_kernel(const float* __restrict__ w2, const float* __restrict__ w3,
                            const float* __restrict__ fw1, const float* __restrict__ fw2,
                            const float* __restrict__ wt, const float* __restrict__ wp,
                            const float* __restrict__ wg, const float* __restrict__ wo) {
    int i = blockIdx.x * blockDim.x + threadIdx.x;
    if (i < N_W2F) {
        int lane = i & 31;
        int r    = (i >> 5) & 7;
        int wblk = (i >> 8) & 7;
        int tap  = i >> 11;
        int g  = lane >> 2, tg = lane & 3;
        int mt = r >> 2,    ai = r & 3;
        int o = mt * 16 + g + 8 * (ai & 1);
        int c = wblk * 8 + tg + 4 * (ai >> 1);
        g_w2f[i] = tfr(w2[o * 576 + c * 9 + tap]);
        return;
    }
    i -= N_W2F;
    if (i < N_W3F) {
        int lane = i & 31;
        int ai   = (i >> 5) & 1;
        int kc   = (i >> 6) & 3;
        int tap  = i >> 8;
        int o = lane >> 2, tg = lane & 3;
        int c = kc * 8 + tg + 4 * ai;
        g_w3f[i] = tfr(w3[o * 288 + c * 9 + tap]);
        return;
    }
    i -= N_W3F;
    if (i < N_F1T) {
        int kk = i / 64, jj = i % 64;
        g_fw1T[i] = fw1[jj * 200 + kk];
        return;
    }
    i -= N_F1T;
    if (i < N_F2T) {
        int kk = i / 32, jj = i % 32;
        g_fw2T[i] = fw2[jj * 64 + kk];
        return;
    }
    i -= N_F2T;
    if (i < N_W96F) {
        int lane = i & 31;
        int ai   = (i >> 5) & 3;
        int kc   = (i >> 7) & 7;
        int wm   = i >> 10;                 // 0..5
        int g = lane >> 2, tg = lane & 3;
        int row = wm * 16 + g + 8 * (ai & 1);   // 0..95
        int col = kc * 8 + tg + 4 * (ai >> 1);  // 0..63
        const float* src = (row < 32) ? wt : ((row < 64) ? wp : wg);
        g_w96f[i] = tfr(src[(row & 31) * 64 + col]);
        return;
    }
    i -= N_W96F;
    if (i < N_WOF) {
        int lane = i & 31;
        int ai   = (i >> 5) & 3;
        int kc   = (i >> 7) & 3;
        int mt   = i >> 9;                  // 0..3
        int g = lane >> 2, tg = lane & 3;
        int row = mt * 16 + g + 8 * (ai & 1);   // 0..63
        int col = kc * 8 + tg + 4 * (ai >> 1);  // 0..31
        g_wof[i] = tfr(wo[row * 32 + col]);
    }
}

__global__ void __launch_bounds__(NTHREADS, 3) braggnn_kernel(
    const float* __restrict__ x,
    const float* __restrict__ w1, const float* __restrict__ b1,
    const float* __restrict__ bt, const float* __restrict__ bp,
    const float* __restrict__ bg, const float* __restrict__ bo,
    const float* __restrict__ b2, const float* __restrict__ b3,
    const float* __restrict__ fb1, const float* __restrict__ fb2,
    const float* __restrict__ fw3, const float* __restrict__ fb3,
    const float* __restrict__ fw4, const float* __restrict__ fb4,
    const float* __restrict__ fwo, const float* __restrict__ fbo,
    float* __restrict__ out)
{
    extern __shared__ float sm[];
    const int b    = blockIdx.x;
    const int tid  = threadIdx.x;
    const int w    = tid >> 5;
    const int lane = tid & 31;
    const int g    = lane >> 2;
    const int tg   = lane & 3;

    // ---- preload / zero-fill ----
    for (int i = tid; i < 121; i += NTHREADS) sm[OFF_XS + i] = x[b * 121 + i];
    for (int i = tid; i < 1280; i += NTHREADS) {       // W1 staged [64][20]
        int o = i / 20, k = i % 20;
        sm[OFF_W1S + i] = (k < 9) ? tfr(w1[o * 9 + k]) : 0.f;
    }
    for (int i = tid; i < 1408; i += NTHREADS) sm[OFF_P + i] = 0.f;
    for (int i = tid; i < 7 * 40; i += NTHREADS) sm[OFF_G + 81 * 40 + i] = 0.f;
    __syncthreads();

    // ---- im2col patches P[16][88] ----
    for (int i = tid; i < 729; i += NTHREADS) {
        int tap = i / 81, s = i - tap * 81;
        int iy = s / 9 + tap / 3, ix = s % 9 + tap % 3;
        sm[OFF_P + tap * 88 + s] = tfr(sm[OFF_XS + iy * 11 + ix]);
    }
    __syncthreads();

    // ---- phase 1 (mma): A1[64][81] = W1[64][16] @ P[16][81] ----
    {
        const int m0 = (w >> 1) * 16;
        const int nbeg = (w & 1) ? 6 : 0, nend = (w & 1) ? 11 : 6;
        float D[6][4];
        #pragma unroll
        for (int j = 0; j < 6; j++) { D[j][0]=0.f; D[j][1]=0.f; D[j][2]=0.f; D[j][3]=0.f; }
        #pragma unroll
        for (int kc = 0; kc < 2; kc++) {
            const int k0 = kc * 8;
            uint32_t a0 = ldu(&sm[OFF_W1S + (m0 + g)     * 20 + k0 + tg]);
            uint32_t a1 = ldu(&sm[OFF_W1S + (m0 + g + 8) * 20 + k0 + tg]);
            uint32_t a2 = ldu(&sm[OFF_W1S + (m0 + g)     * 20 + k0 + tg + 4]);
            uint32_t a3 = ldu(&sm[OFF_W1S + (m0 + g + 8) * 20 + k0 + tg + 4]);
            int j = 0;
            for (int nt = nbeg; nt < nend; nt++, j++) {
                uint32_t b0 = ldu(&sm[OFF_P + (k0 + tg)     * 88 + nt * 8 + g]);
                uint32_t b1 = ldu(&sm[OFF_P + (k0 + tg + 4) * 88 + nt * 8 + g]);
                mma_tf32(D[j], a0, a1, a2, a3, b0, b1);
            }
        }
        const int c0 = m0 + g, c1 = m0 + g + 8;
        const float bia0 = b1[c0], bia1 = b1[c1];
        int j = 0;
        for (int nt = nbeg; nt < nend; nt++, j++)
            #pragma unroll
            for (int dd = 0; dd < 2; dd++) {
                int s = nt * 8 + 2 * tg + dd;
                if (s < 81) {
                    sm[OFF_A1 + c0 * 88 + s] = tfr(D[j][dd]     + bia0);
                    sm[OFF_A1 + c1 * 88 + s] = tfr(D[j][2 + dd] + bia1);
                }
            }
    }
    __syncthreads();

    // ---- phase 2 (mma): P96[96][81] = W96 @ A1 ; A-frags from global g_w96f ----
    if (w < 6) {
        float D[11][4];
        #pragma unroll
        for (int nt = 0; nt < 11; nt++) { D[nt][0]=0.f; D[nt][1]=0.f; D[nt][2]=0.f; D[nt][3]=0.f; }
        for (int kc = 0; kc < 8; kc++) {
            const int k0 = kc * 8;
            const float* af = &g_w96f[(w * 8 + kc) * 128];
            uint32_t a0 = __float_as_uint(af[lane]);
            uint32_t a1 = __float_as_uint(af[32 + lane]);
            uint32_t a2 = __float_as_uint(af[64 + lane]);
            uint32_t a3 = __float_as_uint(af[96 + lane]);
            #pragma unroll
            for (int nt = 0; nt < 11; nt++) {
                uint32_t b0 = ldu(&sm[OFF_A1 + (k0 + tg)     * 88 + nt * 8 + g]);
                uint32_t b1 = ldu(&sm[OFF_A1 + (k0 + tg + 4) * 88 + nt * 8 + g]);
                mma_tf32(D[nt], a0, a1, a2, a3, b0, b1);
            }
        }
        const int mat = w >> 1;
        const float* bias = (mat == 0) ? bt : ((mat == 1) ? bp : bg);
        const int ch0 = (w & 1) * 16 + g, ch1 = ch0 + 8;
        const float bv0 = bias[ch0], bv1 = bias[ch1];
        #pragma unroll
        for (int nt = 0; nt < 11; nt++)
            #pragma unroll
            for (int dd = 0; dd < 2; dd++) {
                int s = nt * 8 + 2 * tg + dd;
                if (s < 81) {
                    float v0 = tfr(D[nt][dd] + bv0);
                    float v1 = tfr(D[nt][2 + dd] + bv1);
                    if (mat == 0)      { sm[OFF_TH + s * 36 + ch0] = v0; sm[OFF_TH + s * 36 + ch1] = v1; }
                    else if (mat == 1) { sm[OFF_PH + ch0 * 88 + s] = v0; sm[OFF_PH + ch1 * 88 + s] = v1; }
                    else               { sm[OFF_G  + s * 40 + ch0] = v0; sm[OFF_G  + s * 40 + ch1] = v1; }
                }
            }
    }
    __syncthreads();

    // ---- phase 3a+3b fused: logits -> register softmax -> (shfl) -> Y = attn @ g ----
    if (w < 6) {
        const int m0 = w * 16;
        const int r0 = min(m0 + g, 80), r1 = min(m0 + g + 8, 80);
        float D[11][4];
        #pragma unroll
        for (int nt = 0; nt < 11; nt++) { D[nt][0]=0.f; D[nt][1]=0.f; D[nt][2]=0.f; D[nt][3]=0.f; }
        for (int kc = 0; kc < 4; kc++) {
            const int k0 = kc * 8;
            uint32_t a0 = ldu(&sm[OFF_TH + r0 * 36 + k0 + tg]);
            uint32_t a1 = ldu(&sm[OFF_TH + r1 * 36 + k0 + tg]);
            uint32_t a2 = ldu(&sm[OFF_TH + r0 * 36 + k0 + tg + 4]);
            uint32_t a3 = ldu(&sm[OFF_TH + r1 * 36 + k0 + tg + 4]);
            #pragma unroll
            for (int nt = 0; nt < 11; nt++) {
                uint32_t b0 = ldu(&sm[OFF_PH + (k0 + tg)     * 88 + nt * 8 + g]);
                uint32_t b1 = ldu(&sm[OFF_PH + (k0 + tg + 4) * 88 + nt * 8 + g]);
                mma_tf32(D[nt], a0, a1, a2, a3, b0, b1);
            }
        }
        // register softmax over rows (m0+g), (m0+g+8)
        float mx0 = -1e30f, mx1 = -1e30f;
        #pragma unroll
        for (int nt = 0; nt < 11; nt++)
            #pragma unroll
            for (int dd = 0; dd < 2; dd++) {
                int t = nt * 8 + 2 * tg + dd;
                if (t < 81) { mx0 = fmaxf(mx0, D[nt][dd]); mx1 = fmaxf(mx1, D[nt][2 + dd]); }
            }
        mx0 = fmaxf(mx0, __shfl_xor_sync(0xffffffffu, mx0, 1));
        mx0 = fmaxf(mx0, __shfl_xor_sync(0xffffffffu, mx0, 2));
        mx1 = fmaxf(mx1, __shfl_xor_sync(0xffffffffu, mx1, 1));
        mx1 = fmaxf(mx1, __shfl_xor_sync(0xffffffffu, mx1, 2));
        float s0 = 0.f, s1 = 0.f;
        #pragma unroll
        for (int nt = 0; nt < 11; nt++)
            #pragma unroll
            for (int dd = 0; dd < 2; dd++) {
                int t = nt * 8 + 2 * tg + dd;
                float e0 = (t < 81) ? __expf(D[nt][dd]     - mx0) : 0.f;
                float e1 = (t < 81) ? __expf(D[nt][2 + dd] - mx1) : 0.f;
                D[nt][dd] = e0; D[nt][2 + dd] = e1;
                s0 += e0; s1 += e1;
            }
        s0 += __shfl_xor_sync(0xffffffffu, s0, 1);
        s0 += __shfl_xor_sync(0xffffffffu, s0, 2);
        s1 += __shfl_xor_sync(0xffffffffu, s1, 1);
        s1 += __shfl_xor_sync(0xffffffffu, s1, 2);
        const float inv0 = 1.0f / s0, inv1 = 1.0f / s1;
        #pragma unroll
        for (int nt = 0; nt < 11; nt++)
            #pragma unroll
            for (int dd = 0; dd < 2; dd++) {
                int t = nt * 8 + 2 * tg + dd;
                D[nt][dd]     = (t < 81) ? tfr(D[nt][dd]     * inv0) : 0.f;
                D[nt][2 + dd] = (t < 81) ? tfr(D[nt][2 + dd] * inv1) : 0.f;
            }

        // 3b: Y[16 rows][32] = attn(regs) @ G[88][32]; A-frags via intra-quad shfl
        float Y[4][4];
        #pragma unroll
        for (int nt = 0; nt < 4; nt++) { Y[nt][0]=0.f; Y[nt][1]=0.f; Y[nt][2]=0.f; Y[nt][3]=0.f; }
        const int src0 = (g << 2) + (tg >> 1);
        const int src4 = src0 + 2;
        const bool odd = (tg & 1);
        #pragma unroll
        for (int kc = 0; kc < 11; kc++) {
            float lo, hi;
            lo = __shfl_sync(0xffffffffu, D[kc][0], src0);
            hi = __shfl_sync(0xffffffffu, D[kc][1], src0);
            uint32_t a0 = __float_as_uint(odd ? hi : lo);
            lo = __shfl_sync(0xffffffffu, D[kc][2], src0);
            hi = __shfl_sync(0xffffffffu, D[kc][3], src0);
            uint32_t a1 = __float_as_uint(odd ? hi : lo);
            lo = __shfl_sync(0xffffffffu, D[kc][0], src4);
            hi = __shfl_sync(0xffffffffu, D[kc][1], src4);
            uint32_t a2 = __float_as_uint(odd ? hi : lo);
            lo = __shfl_sync(0xffffffffu, D[kc][2], src4);
            hi = __shfl_sync(0xffffffffu, D[kc][3], src4);
            uint32_t a3 = __float_as_uint(odd ? hi : lo);
            const int k0 = kc * 8;
            #pragma unroll
            for (int nt = 0; nt < 4; nt++) {
                uint32_t b0 = ldu(&sm[OFF_G + (k0 + tg)     * 40 + nt * 8 + g]);
                uint32_t b1 = ldu(&sm[OFF_G + (k0 + tg + 4) * 40 + nt * 8 + g]);
                mma_tf32(Y[nt], a0, a1, a2, a3, b0, b1);
            }
        }
        const int sr0 = m0 + g, sr1 = m0 + g + 8;
        #pragma unroll
        for (int nt = 0; nt < 4; nt++)
            #pragma unroll
            for (int dd = 0; dd < 2; dd++) {
                int i = nt * 8 + 2 * tg + dd;
                if (sr0 < 81) sm[OFF_TH + sr0 * 36 + i] = tfr(Y[nt][dd]);
                if (sr1 < 81) sm[OFF_TH + sr1 * 36 + i] = tfr(Y[nt][2 + dd]);
            }
    }
    __syncthreads();

    // ---- phase 3c (mma): Z[64][81] = wo @ Y^T + bo + residual, lrelu -> A1 ----
    {
        const int mt = w >> 1;
        const int nbeg = (w & 1) ? 6 : 0, nend = (w & 1) ? 11 : 6;
        float D[6][4];
        #pragma unroll
        for (int j = 0; j < 6; j++) { D[j][0]=0.f; D[j][1]=0.f; D[j][2]=0.f; D[j][3]=0.f; }
        for (int kc = 0; kc < 4; kc++) {
            const int k0 = kc * 8;
            const float* af = &g_wof[(mt * 4 + kc) * 128];
            uint32_t a0 = __float_as_uint(af[lane]);
            uint32_t a1 = __float_as_uint(af[32 + lane]);
            uint32_t a2 = __float_as_uint(af[64 + lane]);
            uint32_t a3 = __float_as_uint(af[96 + lane]);
            int j = 0;
            for (int nt = nbeg; nt < nend; nt++, j++) {
                uint32_t b0 = ldu(&sm[OFF_TH + (nt * 8 + g) * 36 + k0 + tg]);
                uint32_t b1 = ldu(&sm[OFF_TH + (nt * 8 + g) * 36 + k0 + tg + 4]);
                mma_tf32(D[j], a0, a1, a2, a3, b0, b1);
            }
        }
        const int c0 = mt * 16 + g, c1 = c0 + 8;
        const float bo0 = bo[c0], bo1 = bo[c1];
        int j = 0;
        for (int nt = nbeg; nt < nend; nt++, j++)
            #pragma unroll
            for (int dd = 0; dd < 2; dd++) {
                int s = nt * 8 + 2 * tg + dd;
                if (s < 81) {
                    sm[OFF_A1 + c0 * 88 + s] = tfr(lrelu(D[j][dd]     + bo0 + sm[OFF_A1 + c0 * 88 + s]));
                    sm[OFF_A1 + c1 * 88 + s] = tfr(lrelu(D[j][2 + dd] + bo1 + sm[OFF_A1 + c1 * 88 + s]));
                }
            }
    }
    __syncthreads();

    // ---- phase 4 (mma): conv2, K split by channel, two nt-passes, two-round reduce ----
    {
        const int c0 = w * 8;
        float* buf = &sm[OFF_RED + (w & 3) * 1824];
        #pragma unroll
        for (int pass = 0; pass < 2; pass++) {
            const int ntb = pass ? 4 : 0;
            const int ntn = pass ? 3 : 4;
            int rmv[4];
            #pragma unroll
            for (int q = 0; q < 4; q++) {
                int qq = (q < ntn) ? q : (ntn - 1);
                int p = (ntb + qq) * 8 + g;
                rmv[q] = (p < 49) ? (p / 7) * 9 + (p % 7) : 0;
            }
            float D[8][4];
            #pragma unroll
            for (int j = 0; j < 8; j++) { D[j][0]=0.f; D[j][1]=0.f; D[j][2]=0.f; D[j][3]=0.f; }
            for (int tap = 0; tap < 9; tap++) {
                const int off = (tap / 3) * 9 + (tap % 3);
                const float* af = &g_w2f[(tap * 8 + w) * 256];
                uint32_t A[8];
                #pragma unroll
                for (int r = 0; r < 8; r++) A[r] = __float_as_uint(af[r * 32 + lane]);
                for (int q = 0; q < ntn; q++) {
                    uint32_t b0 = ldu(&sm[OFF_A1 + (c0 + tg)     * 88 + rmv[q] + off]);
                    uint32_t b1 = ldu(&sm[OFF_A1 + (c0 + tg + 4) * 88 + rmv[q] + off]);
                    mma_tf32(D[q],     A[0], A[1], A[2], A[3], b0, b1);
                    mma_tf32(D[4 + q], A[4], A[5], A[6], A[7], b0, b1);
                }
            }
            if (w < 4) {
                for (int mt = 0; mt < 2; mt++)
                    for (int q = 0; q < ntn; q++)
                        #pragma unroll
                        for (int dd = 0; dd < 2; dd++) {
                            int o0 = mt * 16 + g, p = (ntb + q) * 8 + 2 * tg + dd;
                            buf[o0 * 57 + p]       = D[mt * 4 + q][dd];
                            buf[(o0 + 8) * 57 + p] = D[mt * 4 + q][2 + dd];
                        }
            }
            __syncthreads();
            if (w >= 4) {
                for (int mt = 0; mt < 2; mt++)
                    for (int q = 0; q < ntn; q++)
                        #pragma unroll
                        for (int dd = 0; dd < 2; dd++) {
                            int o0 = mt * 16 + g, p = (ntb + q) * 8 + 2 * tg + dd;
                            buf[o0 * 57 + p]       += D[mt * 4 + q][dd];
                            buf[(o0 + 8) * 57 + p] += D[mt * 4 + q][2 + dd];
                        }
            }
        }
        __syncthreads();
    }
    for (int e = tid; e < 1568; e += NTHREADS) {     // reduce 4 bufs + bias + lrelu -> A3
        int o = e / 49, p = e % 49;
        float s = b2[o];
        #pragma unroll
        for (int k = 0; k < 4; k++) s += sm[OFF_RED + k * 1824 + o * 57 + p];
        sm[OFF_A3 + o * 56 + p] = lrelu(s);
    }
    __syncthreads();

    // ---- phase 5 (mma): conv3, taps split across warps ----
    {
        int rmv[4];
        #pragma unroll
        for (int nt = 0; nt < 4; nt++) {
            int n = nt * 8 + g;
            rmv[nt] = (n < 25) ? (n / 5) * 7 + (n % 5) : 0;
        }
        float D[4][4];
        #pragma unroll
        for (int nt = 0; nt < 4; nt++) { D[nt][0]=0.f; D[nt][1]=0.f; D[nt][2]=0.f; D[nt][3]=0.f; }
        for (int t = w; t < 9; t += 8) {
            const int off = (t / 3) * 7 + (t % 3);
            #pragma unroll
            for (int kc = 0; kc < 4; kc++) {
                uint32_t a0 = __float_as_uint(g_w3f[((t * 4 + kc) * 2 + 0) * 32 + lane]);
                uint32_t a2 = __float_as_uint(g_w3f[((t * 4 + kc) * 2 + 1) * 32 + lane]);
                #pragma unroll
                for (int nt = 0; nt < 4; nt++) {
                    uint32_t b0 = ldu(&sm[OFF_A3 + (kc * 8 + tg)     * 56 + rmv[nt] + off]);
                    uint32_t b1 = ldu(&sm[OFF_A3 + (kc * 8 + tg + 4) * 56 + rmv[nt] + off]);
                    mma_tf32(D[nt], a0, 0u, a2, 0u, b0, b1);
                }
            }
        }
        float* buf3 = &sm[OFF_RED3 + w * 264];
        #pragma unroll
        for (int nt = 0; nt < 4; nt++)
            #pragma unroll
            for (int dd = 0; dd < 2; dd++)
                buf3[g * 33 + nt * 8 + 2 * tg + dd] = D[nt][dd];
    }
    __syncthreads();
    if (tid < 200) {     // reduce 8 tap-partials + bias + lrelu -> flat
        int o = tid / 25, p = tid % 25;
        float s = b3[o];
        #pragma unroll
        for (int ww = 0; ww < 8; ww++) s += sm[OFF_RED3 + ww * 264 + o * 33 + p];
        sm[OFF_FLAT + o * 25 + p] = lrelu(s);
    }
    __syncthreads();

    // ---- phase 6: MLP ----
    float* flat = &sm[OFF_FLAT];
    float* scr  = &sm[OFF_FCS];
    float* sc2  = &sm[OFF_FC2S];
    float* f1 = &sm[OFF_F1];
    float* f2 = &sm[OFF_F2];
    float* f3 = &sm[OFF_F3];
    float* f4 = &sm[OFF_F4];

    {   // fc1: 200 -> 64
        int q = tid >> 6, j = tid & 63;
        float acc = 0.f;
        int k0 = q * 50;
        for (int k = 0; k < 50; k++)
            acc += g_fw1T[(k0 + k) * 64 + j] * flat[k0 + k];
        scr[q * 64 + j] = acc;
    }
    __syncthreads();
    if (tid < 64)
        f1[tid] = lrelu(scr[tid] + scr[64 + tid] + scr[128 + tid] + scr[192 + tid] + fb1[tid]);
    __syncthreads();
    if (tid < 128) {  // fc2: 64 -> 32
        int q = tid >> 5, j = tid & 31;
        float acc = 0.f;
        int k0 = q * 16;
        for (int k = 0; k < 16; k++)
            acc += g_fw2T[(k0 + k) * 32 + j] * f1[k0 + k];
        sc2[q * 32 + j] = acc;
    }
    __syncthreads();
    if (tid < 32)
        f2[tid] = lrelu(sc2[tid] + sc2[32 + tid] + sc2[64 + tid] + sc2[96 + tid] + fb2[tid]);
    __syncthreads();
    if (tid < 64) {   // fc3: 32 -> 16
        int j = tid >> 2, q = tid & 3;
        float acc = 0.f;
        const float* wr = &fw3[j * 32 + q * 8];
        for (int k = 0; k < 8; k++) acc += wr[k] * f2[q * 8 + k];
        acc += __shfl_xor_sync(0xffffffffu, acc, 1);
        acc += __shfl_xor_sync(0xffffffffu, acc, 2);
        if (q == 0) f3[j] = lrelu(acc + fb3[j]);
    }
    __syncthreads();
    if (tid < 32) {   // fc4: 16 -> 8
        int j = tid >> 2, q = tid & 3;
        float acc = 0.f;
        const float* wr = &fw4[j * 16 + q * 4];
        for (int k = 0; k < 4; k++) acc += wr[k] * f3[q * 4 + k];
        acc += __shfl_xor_sync(0xffffffffu, acc, 1);
        acc += __shfl_xor_sync(0xffffffffu, acc, 2);
        if (q == 0) f4[j] = lrelu(acc + fb4[j]);
    }
    __syncthreads();
    if (tid < 2) {    // fco: 8 -> 2
        float acc = fbo[tid];
        const float* wr = &fwo[tid * 8];
        #pragma unroll
        for (int k = 0; k < 8; k++) acc += wr[k] * f4[k];
        out[b * 2 + tid] = acc;
    }
}

extern "C" void kernel_launch(void* const* d_in, const int* in_sizes, int n_in,
                              void* d_out, int out_size) {
    const float* x   = (const float*)d_in[0];
    const float* w1  = (const float*)d_in[1];
    const float* b1  = (const float*)d_in[2];
    const float* wt  = (const float*)d_in[3];
    const float* bt  = (const float*)d_in[4];
    const float* wp  = (const float*)d_in[5];
    const float* bp  = (const float*)d_in[6];
    const float* wg  = (const float*)d_in[7];
    const float* bg  = (const float*)d_in[8];
    const float* wo  = (const float*)d_in[9];
    const float* bo  = (const float*)d_in[10];
    const float* w2  = (const float*)d_in[11];
    const float* b2  = (const float*)d_in[12];
    const float* w3  = (const float*)d_in[13];
    const float* b3  = (const float*)d_in[14];
    const float* fw1 = (const float*)d_in[15];
    const float* fb1 = (const float*)d_in[16];
    const float* fw2 = (const float*)d_in[17];
    const float* fb2 = (const float*)d_in[18];
    const float* fw3 = (const float*)d_in[19];
    const float* fb3 = (const float*)d_in[20];
    const float* fw4 = (const float*)d_in[21];
    const float* fb4 = (const float*)d_in[22];
    const float* fwo = (const float*)d_in[23];
    const float* fbo = (const float*)d_in[24];
    float* out = (float*)d_out;

    int B = in_sizes[0] / 121;

    prep_kernel<<<(PREP_TOTAL + 255) / 256, 256>>>(w2, w3, fw1, fw2, wt, wp, wg, wo);

    cudaFuncSetAttribute(braggnn_kernel,
                         cudaFuncAttributeMaxDynamicSharedMemorySize, SMEM_BYTES);
    braggnn_kernel<<<B, NTHREADS, SMEM_BYTES>>>(
        x, w1, b1, bt, bp, bg, bo, b2, b3,
        fb1, fb2, fw3, fb3, fw4, fb4, fwo, fbo, out);
}

// round 11
// speedup vs baseline: 9.7889x; 1.5477x over previous
#include <cuda_runtime.h>
#include <cstdint>

#define NTHREADS 256

__device__ __forceinline__ float lrelu(float v) { return fmaxf(v, 0.01f * v); }

// pack two floats -> bf16x2 word (lo = first/even-k element, in low 16 bits)
__device__ __forceinline__ uint32_t pk(float lo, float hi) {
    uint32_t r;
    asm("cvt.rn.bf16x2.f32 %0, %1, %2;" : "=r"(r) : "f"(hi), "f"(lo));
    return r;
}
__device__ __forceinline__ float bf_lo(uint32_t wd) { return __uint_as_float(wd << 16); }
__device__ __forceinline__ float bf_hi(uint32_t wd) { return __uint_as_float(wd & 0xffff0000u); }

__device__ __forceinline__ void mma_bf16(float* d,
                                         uint32_t a0, uint32_t a1, uint32_t a2, uint32_t a3,
                                         uint32_t b0, uint32_t b1) {
    asm volatile("mma.sync.aligned.m16n8k16.row.col.f32.bf16.bf16.f32 "
                 "{%0,%1,%2,%3},{%4,%5,%6,%7},{%8,%9},{%0,%1,%2,%3};"
                 : "+f"(d[0]), "+f"(d[1]), "+f"(d[2]), "+f"(d[3])
                 : "r"(a0), "r"(a1), "r"(a2), "r"(a3), "r"(b0), "r"(b1));
}

// ---- shared memory layout (32-bit word offsets) ----
// region0 (reused over time):
#define OFF_XS    0        // 121 fp32 image (phase 1 only)
#define OFF_PP    128      // 8*88 = 704 packed im2col (phase 1 only)
#define OFF_W1S   832      // 64*12 = 768 packed conv1 weights -> 1600
#define OFF_A3    0        // 16*56 = 896 packed conv2 out
#define OFF_FLAT  1792     // 200 fp32
#define OFF_FCS   1992     // 256
#define OFF_F1    2248
#define OFF_F2    2312
#define OFF_F3    2344
#define OFF_F4    2360
#define OFF_FC2S  2368     // -> 2496
// high region (packed bf16x2; strides bank-tiled):
#define OFF_A1    2880     // A1p [32 cp][88]  -> 5696
#define OFF_TH    5696     // THp [81 s][20]   -> 7316  (theta, i-pairs)
#define OFF_PH    7316     // PHp [16 ip][88]  -> 8724  (phi)
#define OFF_G     8724     // Gp  [48 tp][40]  -> 10644 (g, t-pairs; rows 40..47 zeroed)
#define OFF_Y     10644    // Yp  [16 ip][88]  -> 12052
#define OFF_RED   5696     // conv2 partials: 4 bufs x 1824 fp32 -> 12992 (TH..Y dead)
#define OFF_RED3  5696     // conv3 partials: 8 x 264 fp32
#define SMEM_FLOATS 12992
#define SMEM_BYTES  (SMEM_FLOATS * 4)

// ---- prepacked weights (device scratch, filled by prep kernel) ----
__device__ __align__(16) uint32_t g_w2fb[5 * 8 * 8 * 32];   // conv2 tap-pair frags
__device__ __align__(16) uint32_t g_w3fb[9 * 2 * 2 * 32];   // conv3 frags
__device__ __align__(16) float    g_fw1T[200 * 64];
__device__ __align__(16) float    g_fw2T[64 * 32];
__device__ __align__(16) uint32_t g_w96fb[6 * 4 * 4 * 32];  // phase-2 A frags (wt|wp|wg)
__device__ __align__(16) uint32_t g_wofb[4 * 2 * 4 * 32];   // phase-3c A frags (wo)

#define N_W2FB  (5 * 8 * 8 * 32)
#define N_W3FB  (9 * 2 * 2 * 32)
#define N_F1T   (200 * 64)
#define N_F2T   (64 * 32)
#define N_W96FB (6 * 4 * 4 * 32)
#define N_WOFB  (4 * 2 * 4 * 32)
#define PREP_TOTAL (N_W2FB + N_W3FB + N_F1T + N_F2T + N_W96FB + N_WOFB)

__global__ void prep_kernel(const float* __restrict__ w2, const float* __restrict__ w3,
                            const float* __restrict__ fw1, const float* __restrict__ fw2,
                            const float* __restrict__ wt, const float* __restrict__ wp,
                            const float* __restrict__ wg, const float* __restrict__ wo) {
    int i = blockIdx.x * blockDim.x + threadIdx.x;
    if (i < N_W2FB) {
        int lane = i & 31;
        int idx  = (i >> 5) & 7;
        int w    = (i >> 8) & 7;
        int tp   = i >> 11;                 // 0..4
        int g = lane >> 2, tg = lane & 3;
        int mt = idx >> 2, r = idx & 3;
        int o = mt * 16 + g + 8 * (r & 1);
        int tap = 2 * tp + (r >> 1);
        int c = w * 8 + 2 * tg;
        uint32_t v = 0;
        if (tap <= 8) {
            float lo = w2[o * 576 + c * 9 + tap];
            float hi = w2[o * 576 + (c + 1) * 9 + tap];
            v = pk(lo, hi);
        }
        g_w2fb[i] = v;
        return;
    }
    i -= N_W2FB;
    if (i < N_W3FB) {
        int lane = i & 31;
        int ridx = (i >> 5) & 1;
        int kc2  = (i >> 6) & 1;
        int t    = i >> 7;                  // 0..8
        int g = lane >> 2, tg = lane & 3;
        int o = g;                          // output channel 0..7
        int c = kc2 * 16 + 8 * ridx + 2 * tg;
        g_w3fb[i] = pk(w3[o * 288 + c * 9 + t], w3[o * 288 + (c + 1) * 9 + t]);
        return;
    }
    i -= N_W3FB;
    if (i < N_F1T) {
        int kk = i / 64, jj = i % 64;
        g_fw1T[i] = fw1[jj * 200 + kk];
        return;
    }
    i -= N_F1T;
    if (i < N_F2T) {
        int kk = i / 32, jj = i % 32;
        g_fw2T[i] = fw2[jj * 64 + kk];
        return;
    }
    i -= N_F2T;
    if (i < N_W96FB) {
        int lane = i & 31;
        int r    = (i >> 5) & 3;
        int kc   = (i >> 7) & 3;
        int wm   = i >> 9;                  // 0..5
        int g = lane >> 2, tg = lane & 3;
        int row = wm * 16 + g + 8 * (r & 1);    // 0..95
        int k0  = kc * 16 + 8 * (r >> 1) + 2 * tg;
        const float* src = (row < 32) ? wt : ((row < 64) ? wp : wg);
        g_w96fb[i] = pk(src[(row & 31) * 64 + k0], src[(row & 31) * 64 + k0 + 1]);
        return;
    }
    i -= N_W96FB;
    if (i < N_WOFB) {
        int lane = i & 31;
        int r    = (i >> 5) & 3;
        int kc2  = (i >> 7) & 1;
        int mt   = i >> 8;                  // 0..3
        int g = lane >> 2, tg = lane & 3;
        int row = mt * 16 + g + 8 * (r & 1);    // 0..63
        int k0  = kc2 * 16 + 8 * (r >> 1) + 2 * tg;
        g_wofb[i] = pk(wo[row * 32 + k0], wo[row * 32 + k0 + 1]);
    }
}

__global__ void __launch_bounds__(NTHREADS, 3) braggnn_kernel(
    const float* __restrict__ x,
    const float* __restrict__ w1, const float* __restrict__ b1,
    const float* __restrict__ bt, const float* __restrict__ bp,
    const float* __restrict__ bg, const float* __restrict__ bo,
    const float* __restrict__ b2, const float* __restrict__ b3,
    const float* __restrict__ fb1, const float* __restrict__ fb2,
    const float* __restrict__ fw3, const float* __restrict__ fb3,
    const float* __restrict__ fw4, const float* __restrict__ fb4,
    const float* __restrict__ fwo, const float* __restrict__ fbo,
    float* __restrict__ out)
{
    extern __shared__ float sm[];
    uint32_t* smu = (uint32_t*)sm;
    const int b    = blockIdx.x;
    const int tid  = threadIdx.x;
    const int w    = tid >> 5;
    const int lane = tid & 31;
    const int g    = lane >> 2;
    const int tg   = lane & 3;

    // ---- init: image, conv1 weights (packed), Gp pad rows ----
    for (int i = tid; i < 121; i += NTHREADS) sm[OFF_XS + i] = x[b * 121 + i];
    for (int i = tid; i < 512; i += NTHREADS) {        // W1Sp [64][12], 8 words used/row
        int o = i >> 3, ip = i & 7;
        float lo = (2 * ip <= 8) ? w1[o * 9 + 2 * ip] : 0.f;
        float hi = (2 * ip + 1 <= 8) ? w1[o * 9 + 2 * ip + 1] : 0.f;
        smu[OFF_W1S + o * 12 + ip] = pk(lo, hi);
    }
    for (int i = tid; i < 320; i += NTHREADS) smu[OFF_G + 40 * 40 + i] = 0u;  // Gp rows 40..47
    __syncthreads();

    // ---- im2col packed Pp [8 kp][88] ----
    for (int i = tid; i < 704; i += NTHREADS) {
        int kp = i / 88, s = i - kp * 88;
        float lo = 0.f, hi = 0.f;
        if (s < 81) {
            int t0 = 2 * kp, t1 = 2 * kp + 1;
            if (t0 <= 8) lo = sm[OFF_XS + (s / 9 + t0 / 3) * 11 + (s % 9) + t0 % 3];
            if (t1 <= 8) hi = sm[OFF_XS + (s / 9 + t1 / 3) * 11 + (s % 9) + t1 % 3];
        }
        smu[OFF_PP + kp * 88 + s] = pk(lo, hi);
    }
    __syncthreads();

    // ---- phase 1 (mma): A1[64][81] = W1[64][16] @ P[16][81], store packed pairs ----
    {
        const int m0 = (w >> 1) * 16;
        const int nbeg = (w & 1) ? 6 : 0, nend = (w & 1) ? 11 : 6;
        float D[6][4];
        #pragma unroll
        for (int j = 0; j < 6; j++) { D[j][0]=0.f; D[j][1]=0.f; D[j][2]=0.f; D[j][3]=0.f; }
        uint32_t a0 = smu[OFF_W1S + (m0 + g)     * 12 + tg];
        uint32_t a1 = smu[OFF_W1S + (m0 + g + 8) * 12 + tg];
        uint32_t a2 = smu[OFF_W1S + (m0 + g)     * 12 + tg + 4];
        uint32_t a3 = smu[OFF_W1S + (m0 + g + 8) * 12 + tg + 4];
        {
            int j = 0;
            for (int nt = nbeg; nt < nend; nt++, j++) {
                uint32_t b0 = smu[OFF_PP + tg       * 88 + nt * 8 + g];
                uint32_t b1 = smu[OFF_PP + (tg + 4) * 88 + nt * 8 + g];
                mma_bf16(D[j], a0, a1, a2, a3, b0, b1);
            }
        }
        const int c0 = m0 + g, c1 = m0 + g + 8;
        const float bia0 = b1[c0], bia1 = b1[c1];
        int j = 0;
        for (int nt = nbeg; nt < nend; nt++, j++)
            #pragma unroll
            for (int dd = 0; dd < 2; dd++) {
                int s = nt * 8 + 2 * tg + dd;
                float v0 = D[j][dd]     + bia0;
                float v1 = D[j][2 + dd] + bia1;
                float p0 = __shfl_xor_sync(0xffffffffu, v0, 4);
                float p1 = __shfl_xor_sync(0xffffffffu, v1, 4);
                if (!(g & 1) && s < 81) {
                    smu[OFF_A1 + (c0 >> 1) * 88 + s] = pk(v0, p0);
                    smu[OFF_A1 + (c1 >> 1) * 88 + s] = pk(v1, p1);
                }
            }
    }
    __syncthreads();

    // ---- phase 2 (mma): [theta|phi|g][96][81] = W96 @ A1 ----
    if (w < 6) {
        float D[11][4];
        #pragma unroll
        for (int nt = 0; nt < 11; nt++) { D[nt][0]=0.f; D[nt][1]=0.f; D[nt][2]=0.f; D[nt][3]=0.f; }
        for (int kc = 0; kc < 4; kc++) {
            const uint32_t* af = &g_w96fb[(w * 4 + kc) * 128];
            uint32_t a0 = af[lane], a1 = af[32 + lane], a2 = af[64 + lane], a3 = af[96 + lane];
            #pragma unroll
            for (int nt = 0; nt < 11; nt++) {
                uint32_t b0 = smu[OFF_A1 + (kc * 8 + tg)     * 88 + nt * 8 + g];
                uint32_t b1 = smu[OFF_A1 + (kc * 8 + tg + 4) * 88 + nt * 8 + g];
                mma_bf16(D[nt], a0, a1, a2, a3, b0, b1);
            }
        }
        const int mat = w >> 1;                          // 0=theta 1=phi 2=g
        const float* bias = (mat == 0) ? bt : ((mat == 1) ? bp : bg);
        const int ch0 = (w & 1) * 16 + g, ch1 = ch0 + 8;
        const float bv0 = bias[ch0], bv1 = bias[ch1];
        if (mat == 2) {
            // Gp [tp][i]: t-pairs are local (dd)
            #pragma unroll
            for (int nt = 0; nt < 11; nt++) {
                int s0 = nt * 8 + 2 * tg;
                if (s0 < 81) {
                    float v00 = D[nt][0] + bv0, v01 = D[nt][1] + bv0;
                    float v10 = D[nt][2] + bv1, v11 = D[nt][3] + bv1;
                    float h0 = (s0 + 1 < 81) ? v01 : 0.f;
                    float h1 = (s0 + 1 < 81) ? v11 : 0.f;
                    smu[OFF_G + (nt * 4 + tg) * 40 + ch0] = pk(v00, h0);
                    smu[OFF_G + (nt * 4 + tg) * 40 + ch1] = pk(v10, h1);
                }
            }
        } else {
            // THp [s][ip] / PHp [ip][t]: i-pairs via g-parity shfl
            #pragma unroll
            for (int nt = 0; nt < 11; nt++)
                #pragma unroll
                for (int dd = 0; dd < 2; dd++) {
                    int s = nt * 8 + 2 * tg + dd;
                    float v0 = D[nt][dd]     + bv0;
                    float v1 = D[nt][2 + dd] + bv1;
                    float p0 = __shfl_xor_sync(0xffffffffu, v0, 4);
                    float p1 = __shfl_xor_sync(0xffffffffu, v1, 4);
                    if (!(g & 1) && s < 81) {
                        if (mat == 0) {
                            smu[OFF_TH + s * 20 + (ch0 >> 1)] = pk(v0, p0);
                            smu[OFF_TH + s * 20 + (ch1 >> 1)] = pk(v1, p1);
                        } else {
                            smu[OFF_PH + (ch0 >> 1) * 88 + s] = pk(v0, p0);
                            smu[OFF_PH + (ch1 >> 1) * 88 + s] = pk(v1, p1);
                        }
                    }
                }
        }
    }
    __syncthreads();

    // ---- phase 3a+3b fused: logits -> register softmax -> (local repack) -> Y ----
    if (w < 6) {
        const int m0 = w * 16;
        const int r0 = min(m0 + g, 80), r1 = min(m0 + g + 8, 80);
        float D[11][4];
        #pragma unroll
        for (int nt = 0; nt < 11; nt++) { D[nt][0]=0.f; D[nt][1]=0.f; D[nt][2]=0.f; D[nt][3]=0.f; }
        #pragma unroll
        for (int kc2 = 0; kc2 < 2; kc2++) {
            uint32_t a0 = smu[OFF_TH + r0 * 20 + kc2 * 8 + tg];
            uint32_t a1 = smu[OFF_TH + r1 * 20 + kc2 * 8 + tg];
            uint32_t a2 = smu[OFF_TH + r0 * 20 + kc2 * 8 + tg + 4];
            uint32_t a3 = smu[OFF_TH + r1 * 20 + kc2 * 8 + tg + 4];
            #pragma unroll
            for (int nt = 0; nt < 11; nt++) {
                uint32_t b0 = smu[OFF_PH + (kc2 * 8 + tg)     * 88 + nt * 8 + g];
                uint32_t b1 = smu[OFF_PH + (kc2 * 8 + tg + 4) * 88 + nt * 8 + g];
                mma_bf16(D[nt], a0, a1, a2, a3, b0, b1);
            }
        }
        // register softmax (rows m0+g, m0+g+8)
        float mx0 = -1e30f, mx1 = -1e30f;
        #pragma unroll
        for (int nt = 0; nt < 11; nt++)
            #pragma unroll
            for (int dd = 0; dd < 2; dd++) {
                int t = nt * 8 + 2 * tg + dd;
                if (t < 81) { mx0 = fmaxf(mx0, D[nt][dd]); mx1 = fmaxf(mx1, D[nt][2 + dd]); }
            }
        mx0 = fmaxf(mx0, __shfl_xor_sync(0xffffffffu, mx0, 1));
        mx0 = fmaxf(mx0, __shfl_xor_sync(0xffffffffu, mx0, 2));
        mx1 = fmaxf(mx1, __shfl_xor_sync(0xffffffffu, mx1, 1));
        mx1 = fmaxf(mx1, __shfl_xor_sync(0xffffffffu, mx1, 2));
        float s0 = 0.f, s1 = 0.f;
        #pragma unroll
        for (int nt = 0; nt < 11; nt++)
            #pragma unroll
            for (int dd = 0; dd < 2; dd++) {
                int t = nt * 8 + 2 * tg + dd;
                float e0 = (t < 81) ? __expf(D[nt][dd]     - mx0) : 0.f;
                float e1 = (t < 81) ? __expf(D[nt][2 + dd] - mx1) : 0.f;
                D[nt][dd] = e0; D[nt][2 + dd] = e1;
                s0 += e0; s1 += e1;
            }
        s0 += __shfl_xor_sync(0xffffffffu, s0, 1);
        s0 += __shfl_xor_sync(0xffffffffu, s0, 2);
        s1 += __shfl_xor_sync(0xffffffffu, s1, 1);
        s1 += __shfl_xor_sync(0xffffffffu, s1, 2);
        const float inv0 = 1.0f / s0, inv1 = 1.0f / s1;
        #pragma unroll
        for (int nt = 0; nt < 11; nt++)
            #pragma unroll
            for (int dd = 0; dd < 2; dd++) {
                D[nt][dd]     *= inv0;
                D[nt][2 + dd] *= inv1;
            }
        // 3b: Y = attn @ G; A-frags are register-local packs of D
        float Y[4][4];
        #pragma unroll
        for (int nt = 0; nt < 4; nt++) { Y[nt][0]=0.f; Y[nt][1]=0.f; Y[nt][2]=0.f; Y[nt][3]=0.f; }
        #pragma unroll
        for (int kc = 0; kc < 6; kc++) {
            uint32_t a0, a1, a2, a3;
            if (kc < 5) {
                a0 = pk(D[2 * kc][0],     D[2 * kc][1]);
                a1 = pk(D[2 * kc][2],     D[2 * kc][3]);
                a2 = pk(D[2 * kc + 1][0], D[2 * kc + 1][1]);
                a3 = pk(D[2 * kc + 1][2], D[2 * kc + 1][3]);
            } else {
                a0 = pk(D[10][0], D[10][1]);
                a1 = pk(D[10][2], D[10][3]);
                a2 = 0u; a3 = 0u;
            }
            #pragma unroll
            for (int nt = 0; nt < 4; nt++) {
                uint32_t b0 = smu[OFF_G + (kc * 8 + tg)     * 40 + nt * 8 + g];
                uint32_t b1 = smu[OFF_G + (kc * 8 + tg + 4) * 40 + nt * 8 + g];
                mma_bf16(Y[nt], a0, a1, a2, a3, b0, b1);
            }
        }
        const int sr0 = m0 + g, sr1 = m0 + g + 8;
        #pragma unroll
        for (int nt = 0; nt < 4; nt++) {
            if (sr0 < 81) smu[OFF_Y + (nt * 4 + tg) * 88 + sr0] = pk(Y[nt][0], Y[nt][1]);
            if (sr1 < 81) smu[OFF_Y + (nt * 4 + tg) * 88 + sr1] = pk(Y[nt][2], Y[nt][3]);
        }
    }
    __syncthreads();

    // ---- phase 3c (mma): Z[64][81] = wo @ Y^T + bo + residual, lrelu -> A1p ----
    {
        const int mt = w >> 1;
        const int nbeg = (w & 1) ? 6 : 0, nend = (w & 1) ? 11 : 6;
        float D[6][4];
        #pragma unroll
        for (int j = 0; j < 6; j++) { D[j][0]=0.f; D[j][1]=0.f; D[j][2]=0.f; D[j][3]=0.f; }
        #pragma unroll
        for (int kc2 = 0; kc2 < 2; kc2++) {
            const uint32_t* af = &g_wofb[(mt * 2 + kc2) * 128];
            uint32_t a0 = af[lane], a1 = af[32 + lane], a2 = af[64 + lane], a3 = af[96 + lane];
            int j = 0;
            for (int nt = nbeg; nt < nend; nt++, j++) {
                uint32_t b0 = smu[OFF_Y + (kc2 * 8 + tg)     * 88 + nt * 8 + g];
                uint32_t b1 = smu[OFF_Y + (kc2 * 8 + tg + 4) * 88 + nt * 8 + g];
                mma_bf16(D[j], a0, a1, a2, a3, b0, b1);
            }
        }
        const int c0 = mt * 16 + g, c1 = c0 + 8;
        const float bo0 = bo[c0], bo1 = bo[c1];
        int j = 0;
        for (int nt = nbeg; nt < nend; nt++, j++)
            #pragma unroll
            for (int dd = 0; dd < 2; dd++) {
                int s = nt * 8 + 2 * tg + dd;
                uint32_t w0 = smu[OFF_A1 + (c0 >> 1) * 88 + s];
                uint32_t w1v = smu[OFF_A1 + (c1 >> 1) * 88 + s];
                float r0v = (g & 1) ? bf_hi(w0)  : bf_lo(w0);
                float r1v = (g & 1) ? bf_hi(w1v) : bf_lo(w1v);
                float v0 = lrelu(D[j][dd]     + bo0 + r0v);
                float v1 = lrelu(D[j][2 + dd] + bo1 + r1v);
                float p0 = __shfl_xor_sync(0xffffffffu, v0, 4);
                float p1 = __shfl_xor_sync(0xffffffffu, v1, 4);
                if (!(g & 1) && s < 81) {
                    smu[OFF_A1 + (c0 >> 1) * 88 + s] = pk(v0, p0);
                    smu[OFF_A1 + (c1 >> 1) * 88 + s] = pk(v1, p1);
                }
            }
    }
    __syncthreads();

    // ---- phase 4 (mma): conv2 via tap-pair K=16 GEMMs, K-split by channel ----
    {
        const int c0p = w * 4;          // A1p row base (channel pairs)
        float* buf = &sm[OFF_RED + (w & 3) * 1824];
        #pragma unroll
        for (int pass = 0; pass < 2; pass++) {
            const int ntb = pass ? 4 : 0;
            const int ntn = pass ? 3 : 4;
            int rmv[4];
            #pragma unroll
            for (int q = 0; q < 4; q++) {
                int qq = (q < ntn) ? q : (ntn - 1);
                int p = (ntb + qq) * 8 + g;
                rmv[q] = (p < 49) ? (p / 7) * 9 + (p % 7) : 0;
            }
            float D[8][4];
            #pragma unroll
            for (int j = 0; j < 8; j++) { D[j][0]=0.f; D[j][1]=0.f; D[j][2]=0.f; D[j][3]=0.f; }
            for (int tp = 0; tp < 5; tp++) {
                int ta = 2 * tp, tb = (2 * tp + 1 <= 8) ? 2 * tp + 1 : 8;
                int off0 = (ta / 3) * 9 + ta % 3;
                int off1 = (tb / 3) * 9 + tb % 3;
                const uint32_t* af = &g_w2fb[(tp * 8 + w) * 256];
                uint32_t A[8];
                #pragma unroll
                for (int r = 0; r < 8; r++) A[r] = af[r * 32 + lane];
                for (int q = 0; q < ntn; q++) {
                    uint32_t b0 = smu[OFF_A1 + (c0p + tg) * 88 + rmv[q] + off0];
                    uint32_t b1 = smu[OFF_A1 + (c0p + tg) * 88 + rmv[q] + off1];
                    mma_bf16(D[q],     A[0], A[1], A[2], A[3], b0, b1);
                    mma_bf16(D[4 + q], A[4], A[5], A[6], A[7], b0, b1);
                }
            }
            if (w < 4) {
                for (int mt = 0; mt < 2; mt++)
                    for (int q = 0; q < ntn; q++)
                        #pragma unroll
                        for (int dd = 0; dd < 2; dd++) {
                            int o0 = mt * 16 + g, p = (ntb + q) * 8 + 2 * tg + dd;
                            buf[o0 * 57 + p]       = D[mt * 4 + q][dd];
                            buf[(o0 + 8) * 57 + p] = D[mt * 4 + q][2 + dd];
                        }
            }
            __syncthreads();
            if (w >= 4) {
                for (int mt = 0; mt < 2; mt++)
                    for (int q = 0; q < ntn; q++)
                        #pragma unroll
                        for (int dd = 0; dd < 2; dd++) {
                            int o0 = mt * 16 + g, p = (ntb + q) * 8 + 2 * tg + dd;
                            buf[o0 * 57 + p]       += D[mt * 4 + q][dd];
                            buf[(o0 + 8) * 57 + p] += D[mt * 4 + q][2 + dd];
                        }
            }
        }
        __syncthreads();
    }
    for (int e = tid; e < 784; e += NTHREADS) {     // reduce + bias + lrelu -> A3p packed
        int op = e / 49, p = e - op * 49;
        float s0 = b2[2 * op], s1 = b2[2 * op + 1];
        #pragma unroll
        for (int k = 0; k < 4; k++) {
            s0 += sm[OFF_RED + k * 1824 + (2 * op)     * 57 + p];
            s1 += sm[OFF_RED + k * 1824 + (2 * op + 1) * 57 + p];
        }
        smu[OFF_A3 + op * 56 + p] = pk(lrelu(s0), lrelu(s1));
    }
    __syncthreads();

    // ---- phase 5 (mma): conv3, taps split across warps ----
    {
        int rmv[4];
        #pragma unroll
        for (int nt = 0; nt < 4; nt++) {
            int n = nt * 8 + g;
            rmv[nt] = (n < 25) ? (n / 5) * 7 + (n % 5) : 0;
        }
        float D[4][4];
        #pragma unroll
        for (int nt = 0; nt < 4; nt++) { D[nt][0]=0.f; D[nt][1]=0.f; D[nt][2]=0.f; D[nt][3]=0.f; }
        for (int t = w; t < 9; t += 8) {
            const int off = (t / 3) * 7 + (t % 3);
            #pragma unroll
            for (int kc2 = 0; kc2 < 2; kc2++) {
                uint32_t a0 = g_w3fb[((t * 2 + kc2) * 2 + 0) * 32 + lane];
                uint32_t a2 = g_w3fb[((t * 2 + kc2) * 2 + 1) * 32 + lane];
                #pragma unroll
                for (int nt = 0; nt < 4; nt++) {
                    uint32_t b0 = smu[OFF_A3 + (kc2 * 8 + tg)     * 56 + rmv[nt] + off];
                    uint32_t b1 = smu[OFF_A3 + (kc2 * 8 + tg + 4) * 56 + rmv[nt] + off];
                    mma_bf16(D[nt], a0, 0u, a2, 0u, b0, b1);
                }
            }
        }
        float* buf3 = &sm[OFF_RED3 + w * 264];
        #pragma unroll
        for (int nt = 0; nt < 4; nt++)
            #pragma unroll
            for (int dd = 0; dd < 2; dd++)
                buf3[g * 33 + nt * 8 + 2 * tg + dd] = D[nt][dd];
    }
    __syncthreads();
    if (tid < 200) {
        int o = tid / 25, p = tid % 25;
        float s = b3[o];
        #pragma unroll
        for (int ww = 0; ww < 8; ww++) s += sm[OFF_RED3 + ww * 264 + o * 33 + p];
        sm[OFF_FLAT + o * 25 + p] = lrelu(s);
    }
    __syncthreads();

    // ---- phase 6: MLP (fp32) ----
    float* flat = &sm[OFF_FLAT];
    float* scr  = &sm[OFF_FCS];
    float* sc2  = &sm[OFF_FC2S];
    float* f1 = &sm[OFF_F1];
    float* f2 = &sm[OFF_F2];
    float* f3 = &sm[OFF_F3];
    float* f4 = &sm[OFF_F4];

    {   // fc1: 200 -> 64
        int q = tid >> 6, j = tid & 63;
        float acc = 0.f;
        int k0 = q * 50;
        for (int k = 0; k < 50; k++)
            acc += g_fw1T[(k0 + k) * 64 + j] * flat[k0 + k];
        scr[q * 64 + j] = acc;
    }
    __syncthreads();
    if (tid < 64)
        f1[tid] = lrelu(scr[tid] + scr[64 + tid] + scr[128 + tid] + scr[192 + tid] + fb1[tid]);
    __syncthreads();
    if (tid < 128) {  // fc2: 64 -> 32
        int q = tid >> 5, j = tid & 31;
        float acc = 0.f;
        int k0 = q * 16;
        for (int k = 0; k < 16; k++)
            acc += g_fw2T[(k0 + k) * 32 + j] * f1[k0 + k];
        sc2[q * 32 + j] = acc;
    }
    __syncthreads();
    if (tid < 32)
        f2[tid] = lrelu(sc2[tid] + sc2[32 + tid] + sc2[64 + tid] + sc2[96 + tid] + fb2[tid]);
    __syncthreads();
    if (tid < 64) {   // fc3: 32 -> 16
        int j = tid >> 2, q = tid & 3;
        float acc = 0.f;
        const float* wr = &fw3[j * 32 + q * 8];
        for (int k = 0; k < 8; k++) acc += wr[k] * f2[q * 8 + k];
        acc += __shfl_xor_sync(0xffffffffu, acc, 1);
        acc += __shfl_xor_sync(0xffffffffu, acc, 2);
        if (q == 0) f3[j] = lrelu(acc + fb3[j]);
    }
    __syncthreads();
    if (tid < 32) {   // fc4: 16 -> 8
        int j = tid >> 2, q = tid & 3;
        float acc = 0.f;
        const float* wr = &fw4[j * 16 + q * 4];
        for (int k = 0; k < 4; k++) acc += wr[k] * f3[q * 4 + k];
        acc += __shfl_xor_sync(0xffffffffu, acc, 1);
        acc += __shfl_xor_sync(0xffffffffu, acc, 2);
        if (q == 0) f4[j] = lrelu(acc + fb4[j]);
    }
    __syncthreads();
    if (tid < 2) {    // fco: 8 -> 2
        float acc = fbo[tid];
        const float* wr = &fwo[tid * 8];
        #pragma unroll
        for (int k = 0; k < 8; k++) acc += wr[k] * f4[k];
        out[b * 2 + tid] = acc;
    }
}

extern "C" void kernel_launch(void* const* d_in, const int* in_sizes, int n_in,
                              void* d_out, int out_size) {
    const float* x   = (const float*)d_in[0];
    const float* w1  = (const float*)d_in[1];
    const float* b1  = (const float*)d_in[2];
    const float* wt  = (const float*)d_in[3];
    const float* bt  = (const float*)d_in[4];
    const float* wp  = (const float*)d_in[5];
    const float* bp  = (const float*)d_in[6];
    const float* wg  = (const float*)d_in[7];
    const float* bg  = (const float*)d_in[8];
    const float* wo  = (const float*)d_in[9];
    const float* bo  = (const float*)d_in[10];
    const float* w2  = (const float*)d_in[11];
    const float* b2  = (const float*)d_in[12];
    const float* w3  = (const float*)d_in[13];
    const float* b3  = (const float*)d_in[14];
    const float* fw1 = (const float*)d_in[15];
    const float* fb1 = (const float*)d_in[16];
    const float* fw2 = (const float*)d_in[17];
    const float* fb2 = (const float*)d_in[18];
    const float* fw3 = (const float*)d_in[19];
    const float* fb3 = (const float*)d_in[20];
    const float* fw4 = (const float*)d_in[21];
    const float* fb4 = (const float*)d_in[22];
    const float* fwo = (const float*)d_in[23];
    const float* fbo = (const float*)d_in[24];
    float* out = (float*)d_out;

    int B = in_sizes[0] / 121;

    prep_kernel<<<(PREP_TOTAL + 255) / 256, 256>>>(w2, w3, fw1, fw2, wt, wp, wg, wo);

    cudaFuncSetAttribute(braggnn_kernel,
                         cudaFuncAttributeMaxDynamicSharedMemorySize, SMEM_BYTES);
    braggnn_kernel<<<B, NTHREADS, SMEM_BYTES>>>(
        x, w1, b1, bt, bp, bg, bo, b2, b3,
        fb1, fb2, fw3, fb3, fw4, fb4, fwo, fbo, out);
}